// round 1
// baseline (speedup 1.0000x reference)
#include <cuda_runtime.h>
#include <math.h>

#define BB 4
#define NTOK 16384
#define C 128
#define NT (BB*NTOK)      /* 65536 token rows */
#define M 256             /* sr tokens per image */
#define BM (BB*M)         /* 1024 */
#define HEADS 2
#define DH 64
#define XH 8
#define KCONV 8192
#define KSPLIT 8

#define F_ACCUM 1
#define F_GELU  2

// ------------------------- scratch (static device globals; no allocs) -----
__device__ __align__(256) float g_xa0[NT*C];
__device__ __align__(256) float g_xa1[NT*C];
__device__ __align__(256) float g_q  [NT*C];
__device__ __align__(256) float g_h  [NT*C];
__device__ __align__(256) float g_s  [NT*C];
__device__ __align__(256) float g_qkv[(size_t)NT*3*C];
__device__ __align__(256) float g_kp1[NT*C];
__device__ __align__(256) float g_vp1[NT*C];
__device__ __align__(256) float g_o  [NT*C];
__device__ __align__(256) float g_n  [NT*C];
__device__ __align__(256) float g_cpart[KSPLIT*BM*C];
__device__ __align__(256) float g_xi [BM*C];
__device__ __align__(256) float g_kv [BM*2*C];
__device__ __align__(256) float g_ck [C];
__device__ __align__(256) float g_cv [C];

// ------------------------- helpers ---------------------------------------
__device__ __forceinline__ float gelu_exact(float v){
    return 0.5f * v * (1.0f + erff(v * 0.70710678118654752f));
}
__device__ __forceinline__ float warp_sum(float v){
    #pragma unroll
    for (int o = 16; o > 0; o >>= 1) v += __shfl_xor_sync(0xffffffffu, v, o);
    return v;
}

// ------------------------- generic GEMM: D = A @ W^T (+epilogues) --------
// A: (R,K) row-major, lda=K.  W: rows of length K at stride ldw.
// D: (R,Ncols) row-major.  All dims multiples of 64/4.
__global__ void __launch_bounds__(256) gemm_kernel(
    const float* __restrict__ A, const float* __restrict__ Am,
    const float* __restrict__ W, int ldw,
    const float* __restrict__ bias, const float* __restrict__ resid,
    float* __restrict__ D, int Ncols, int K, int flags)
{
    __shared__ float As[16][64];
    __shared__ float Ws[16][64];
    const int tid = threadIdx.x;
    const int tx = tid & 15, ty = tid >> 4;
    const long row0 = (long)blockIdx.x * 64;
    const int  col0 = blockIdx.y * 64;
    const int lr = tid >> 2;            // 0..63
    const int lk = (tid & 3) << 2;      // 0,4,8,12

    const float* Arow  = A + (row0 + lr) * (long)K + lk;
    const float* Amrow = Am ? (Am + (row0 + lr) * (long)K + lk) : Am;
    const float* Wrow  = W + (long)(col0 + lr) * ldw + lk;

    float acc[4][4] = {};
    for (int kk = 0; kk < K; kk += 16) {
        float4 av = *(const float4*)(Arow + kk);
        if (Am) {
            float4 mv = *(const float4*)(Amrow + kk);
            av.x *= mv.x; av.y *= mv.y; av.z *= mv.z; av.w *= mv.w;
        }
        float4 wv = *(const float4*)(Wrow + kk);
        As[lk+0][lr]=av.x; As[lk+1][lr]=av.y; As[lk+2][lr]=av.z; As[lk+3][lr]=av.w;
        Ws[lk+0][lr]=wv.x; Ws[lk+1][lr]=wv.y; Ws[lk+2][lr]=wv.z; Ws[lk+3][lr]=wv.w;
        __syncthreads();
        #pragma unroll
        for (int k = 0; k < 16; k++) {
            float ar[4], br[4];
            *(float4*)ar = *(const float4*)&As[k][ty<<2];
            *(float4*)br = *(const float4*)&Ws[k][tx<<2];
            #pragma unroll
            for (int i = 0; i < 4; i++)
                #pragma unroll
                for (int j = 0; j < 4; j++)
                    acc[i][j] += ar[i] * br[j];
        }
        __syncthreads();
    }
    #pragma unroll
    for (int i = 0; i < 4; i++) {
        long r = row0 + (ty<<2) + i;
        int  c = col0 + (tx<<2);
        float4 v = make_float4(acc[i][0],acc[i][1],acc[i][2],acc[i][3]);
        if (bias){ v.x+=bias[c]; v.y+=bias[c+1]; v.z+=bias[c+2]; v.w+=bias[c+3]; }
        float* dp = D + r * (long)Ncols + c;
        if (flags & F_ACCUM){ float4 o = *(const float4*)dp; v.x+=o.x; v.y+=o.y; v.z+=o.z; v.w+=o.w; }
        if (flags & F_GELU){ v.x=gelu_exact(v.x); v.y=gelu_exact(v.y); v.z=gelu_exact(v.z); v.w=gelu_exact(v.w); }
        if (resid){ float4 rv = *(const float4*)(resid + r*(long)Ncols + c);
                    v.x+=rv.x; v.y+=rv.y; v.z+=rv.z; v.w+=rv.w; }
        *(float4*)dp = v;
    }
}

// ------------------------- patch conv as split-K implicit GEMM -----------
// rows r = (b,patch), cols o = out channel, K = i*64 + kh*8 + kw  (8192)
__global__ void __launch_bounds__(256) conv_kernel(
    const float* __restrict__ x, const float* __restrict__ srw,
    float* __restrict__ part)
{
    __shared__ float As[16][64];
    __shared__ float Ws[16][64];
    const int tid = threadIdx.x;
    const int tx = tid & 15, ty = tid >> 4;
    const int row0 = blockIdx.x * 64;
    const int col0 = blockIdx.y * 64;
    const int kz   = blockIdx.z;
    const int lr = tid >> 2;
    const int lk = (tid & 3) << 2;

    const int r  = row0 + lr;
    const int b_ = r >> 8, p = r & 255, ph = p >> 4, pw = p & 15;
    const float* Wrow = srw + (long)(col0 + lr) * KCONV + kz * 1024 + lk;

    float acc[4][4] = {};
    for (int kk = 0; kk < 1024; kk += 16) {
        const int kg  = kz*1024 + kk + lk;
        const int i   = kg >> 6;
        const int rem = kg & 63;
        const int kh  = rem >> 3, kw = rem & 7;
        const float* xp = x + ((long)b_*NTOK + (ph*8+kh)*128 + (pw*8+kw)) * C + i;
        As[lk+0][lr]=xp[0]; As[lk+1][lr]=xp[C]; As[lk+2][lr]=xp[2*C]; As[lk+3][lr]=xp[3*C];
        float4 wv = *(const float4*)(Wrow + kk);
        Ws[lk+0][lr]=wv.x; Ws[lk+1][lr]=wv.y; Ws[lk+2][lr]=wv.z; Ws[lk+3][lr]=wv.w;
        __syncthreads();
        #pragma unroll
        for (int k = 0; k < 16; k++) {
            float ar[4], br[4];
            *(float4*)ar = *(const float4*)&As[k][ty<<2];
            *(float4*)br = *(const float4*)&Ws[k][tx<<2];
            #pragma unroll
            for (int i2 = 0; i2 < 4; i2++)
                #pragma unroll
                for (int j = 0; j < 4; j++)
                    acc[i2][j] += ar[i2] * br[j];
        }
        __syncthreads();
    }
    #pragma unroll
    for (int i2 = 0; i2 < 4; i2++) {
        int rr = row0 + (ty<<2) + i2;
        float4 v = make_float4(acc[i2][0],acc[i2][1],acc[i2][2],acc[i2][3]);
        *(float4*)(part + ((long)kz*BM + rr)*C + col0 + (tx<<2)) = v;
    }
}

__global__ void conv_reduce_kernel(const float* __restrict__ part,
                                   const float* __restrict__ srb,
                                   float* __restrict__ xi)
{
    int idx = blockIdx.x * 256 + threadIdx.x;   // BM*C = 131072
    if (idx < BM*C) {
        float s = srb[idx & (C-1)];
        #pragma unroll
        for (int z = 0; z < KSPLIT; z++) s += part[(long)z*BM*C + idx];
        xi[idx] = s;
    }
}

// ------------------------- layernorm over C (in place) --------------------
__global__ void ln_kernel(float* __restrict__ xi, const float* __restrict__ g,
                          const float* __restrict__ b)
{
    const int row = blockIdx.x, t = threadIdx.x;
    __shared__ float red[4];
    __shared__ float mv[2];
    float v = xi[(long)row*C + t];
    float s = warp_sum(v);
    if ((t & 31) == 0) red[t >> 5] = s;
    __syncthreads();
    if (t == 0) mv[0] = (red[0]+red[1]+red[2]+red[3]) * (1.0f/C);
    __syncthreads();
    float d = v - mv[0];
    float s2 = warp_sum(d*d);
    if ((t & 31) == 0) red[t >> 5] = s2;
    __syncthreads();
    if (t == 0) mv[1] = (red[0]+red[1]+red[2]+red[3]) * (1.0f/C);
    __syncthreads();
    xi[(long)row*C + t] = d * rsqrtf(mv[1] + 1e-5f) * g[t] + b[t];
}

// ------------------------- SR attention (K,V,scores all in smem) ----------
// block: (qtile of 64, head, batch). 256 threads.
#define ATTN_SMEM_FLOATS (64*68 + 256*64 + 256*64 + 64*257 + 256 + 64)
__global__ void __launch_bounds__(256) attn_kernel(
    const float* __restrict__ Q, const float* __restrict__ KV,
    float* __restrict__ O)
{
    extern __shared__ float sm[];
    float* Qs   = sm;                  // [64][68] (68: keeps rows 16B aligned)
    float* Ks   = Qs + 64*68;          // [256][64]
    float* Vs   = Ks + 256*64;         // [256][64]
    float* S    = Vs + 256*64;         // [64][257] (pad -> conflict free)
    float* red  = S  + 64*257;         // [64][4]
    float* rowv = red + 256;           // [64]

    const int tid = threadIdx.x;
    const int h  = blockIdx.y, b_ = blockIdx.z;
    const int q0 = blockIdx.x * 64;

    for (int e = tid; e < 64*16; e += 256) {
        int qq = e >> 4, d4 = (e & 15) << 2;
        float4 v = *(const float4*)(Q + ((long)b_*NTOK + q0 + qq)*C + h*DH + d4);
        *(float4*)&Qs[qq*68 + d4] = v;
    }
    for (int e = tid; e < 256*16; e += 256) {
        int m = e >> 4, d4 = (e & 15) << 2;
        const float* base = KV + ((long)b_*M + m)*(2*C) + h*DH + d4;
        *(float4*)&Ks[m*64 + d4] = *(const float4*)base;
        *(float4*)&Vs[m*64 + d4] = *(const float4*)(base + C);
    }
    __syncthreads();

    const int q  = tid & 63;
    const int mg = tid >> 6;    // 0..3

    float qr[64];
    #pragma unroll
    for (int d = 0; d < 64; d += 4) {
        float4 v = *(const float4*)&Qs[q*68 + d];
        qr[d]=v.x; qr[d+1]=v.y; qr[d+2]=v.z; qr[d+3]=v.w;
    }
    // scores: warp reads of Ks are broadcast (same m,d across lanes)
    for (int mi = 0; mi < 64; mi++) {
        int m = mg*64 + mi;
        const float* kr = &Ks[m*64];
        float s = 0.f;
        #pragma unroll
        for (int d = 0; d < 64; d += 4) {
            float4 kv4 = *(const float4*)(kr + d);
            s += qr[d]*kv4.x + qr[d+1]*kv4.y + qr[d+2]*kv4.z + qr[d+3]*kv4.w;
        }
        S[q*257 + m] = s * 0.125f;
    }
    __syncthreads();

    // softmax over 256, 4 threads/row
    float lmax = -1e30f;
    for (int mi = 0; mi < 64; mi++) lmax = fmaxf(lmax, S[q*257 + mg*64 + mi]);
    red[q*4 + mg] = lmax;
    __syncthreads();
    if (tid < 64)
        rowv[tid] = fmaxf(fmaxf(red[tid*4],red[tid*4+1]), fmaxf(red[tid*4+2],red[tid*4+3]));
    __syncthreads();
    float rm = rowv[q];
    float lsum = 0.f;
    for (int mi = 0; mi < 64; mi++) {
        int m = mg*64 + mi;
        float e = expf(S[q*257 + m] - rm);
        S[q*257 + m] = e;
        lsum += e;
    }
    red[q*4 + mg] = lsum;
    __syncthreads();
    if (tid < 64)
        rowv[tid] = 1.0f / (red[tid*4]+red[tid*4+1]+red[tid*4+2]+red[tid*4+3]);
    __syncthreads();

    // output: thread handles (q, 16 dims); Vs reads broadcast across warp
    const int dg = mg;
    float o[16] = {};
    for (int m = 0; m < 256; m++) {
        float p = S[q*257 + m];
        const float* vr = &Vs[m*64 + dg*16];
        #pragma unroll
        for (int dd = 0; dd < 16; dd += 4) {
            float4 v4 = *(const float4*)(vr + dd);
            o[dd]+=p*v4.x; o[dd+1]+=p*v4.y; o[dd+2]+=p*v4.z; o[dd+3]+=p*v4.w;
        }
    }
    float inv = rowv[q];
    float* op = O + ((long)b_*NTOK + q0 + q)*C + h*DH + dg*16;
    #pragma unroll
    for (int dd = 0; dd < 16; dd += 4)
        *(float4*)(op + dd) = make_float4(o[dd]*inv, o[dd+1]*inv, o[dd+2]*inv, o[dd+3]*inv);
}

// ------------------------- judger row softmax (C=128), warp/row ----------
__global__ void rowsoftmax_kernel(float* __restrict__ S)
{
    const int row  = blockIdx.x * 8 + (threadIdx.x >> 5);
    const int lane = threadIdx.x & 31;
    float* p = S + (long)row*C + lane*4;
    float4 v = *(const float4*)p;
    float m = fmaxf(fmaxf(v.x,v.y), fmaxf(v.z,v.w));
    #pragma unroll
    for (int o = 16; o > 0; o >>= 1) m = fmaxf(m, __shfl_xor_sync(0xffffffffu, m, o));
    float4 e = make_float4(expf(v.x-m), expf(v.y-m), expf(v.z-m), expf(v.w-m));
    float s = e.x+e.y+e.z+e.w;
    s = warp_sum(s);
    float inv = 1.0f/s;
    e.x*=inv; e.y*=inv; e.z*=inv; e.w*=inv;
    *(float4*)p = e;
}

// ------------------------- constant noise projections ---------------------
// ck = k_noise[d] @ Wk^T    cv = v_noise[d] @ Wv^T   (biases already in qkv)
__global__ void cknoise_kernel(const float* __restrict__ inw,
                               const float* __restrict__ kn,
                               const float* __restrict__ vn,
                               float* __restrict__ ck, float* __restrict__ cv)
{
    int t = threadIdx.x;
    if (t < 128) {
        const float* w = inw + (long)(C + t)*C;
        float s = 0.f;
        #pragma unroll 4
        for (int j = 0; j < C; j++) s += kn[j]*w[j];
        ck[t] = s;
    } else {
        int c = t - 128;
        const float* w = inw + (long)(2*C + c)*C;
        float s = 0.f;
        #pragma unroll 4
        for (int j = 0; j < C; j++) s += vn[j]*w[j];
        cv[c] = s;
    }
}

// ------------------------- per-token 2-key attention combine --------------
__global__ void combine_kernel(const float* __restrict__ qkv,
                               const float* __restrict__ kp1,
                               const float* __restrict__ vp1,
                               const float* __restrict__ ck,
                               const float* __restrict__ cv,
                               float* __restrict__ O)
{
    long idx = (long)blockIdx.x * 256 + threadIdx.x;  // NT*XH threads
    long r = idx >> 3;
    int  h = (int)(idx & 7);
    const float* qp = qkv + r*384 + h*16;
    const float* k0 = qkv + r*384 + 128 + h*16;
    const float* v0 = qkv + r*384 + 256 + h*16;
    const float* k1 = kp1 + r*128 + h*16;
    const float* v1 = vp1 + r*128 + h*16;
    const float* ckh = ck + h*16;
    const float* cvh = cv + h*16;
    float s0 = 0.f, s1 = 0.f;
    #pragma unroll
    for (int i = 0; i < 16; i++) {
        float qv = qp[i];
        s0 += qv * (k0[i] + ckh[i]);
        s1 += qv * k1[i];
    }
    s0 *= 0.25f; s1 *= 0.25f;
    float mx = fmaxf(s0, s1);
    float e0 = expf(s0-mx), e1 = expf(s1-mx);
    float inv = 1.0f/(e0+e1);
    float a0 = e0*inv, a1 = e1*inv;
    float* op = O + r*128 + h*16;
    #pragma unroll
    for (int i = 0; i < 16; i++)
        op[i] = a0*(v0[i] + cvh[i]) + a1*v1[i];
}

// ------------------------- host driver ------------------------------------
static void run_gemm(const float* A, const float* Am, const float* W, int ldw,
                     const float* bias, const float* resid, float* D,
                     int R, int Ncols, int K, int flags)
{
    dim3 g(R/64, Ncols/64);
    gemm_kernel<<<g, 256>>>(A, Am, W, ldw, bias, resid, D, Ncols, K, flags);
}

extern "C" void kernel_launch(void* const* d_in, const int* in_sizes, int n_in,
                              void* d_out, int out_size)
{
    const float* x0       = (const float*)d_in[0];
    const float* x1       = (const float*)d_in[1];
    const float* Wq       = (const float*)d_in[2];
    const float* bq       = (const float*)d_in[3];
    const float* Wkv      = (const float*)d_in[4];
    const float* bkv      = (const float*)d_in[5];
    const float* sr_w     = (const float*)d_in[6];
    const float* sr_b     = (const float*)d_in[7];
    const float* ln_g[2]  = {(const float*)d_in[8],  (const float*)d_in[10]};
    const float* ln_b[2]  = {(const float*)d_in[9],  (const float*)d_in[11]};
    const float* in_w[2]  = {(const float*)d_in[12], (const float*)d_in[16]};
    const float* in_b[2]  = {(const float*)d_in[13], (const float*)d_in[17]};
    const float* out_w[2] = {(const float*)d_in[14], (const float*)d_in[18]};
    const float* out_b[2] = {(const float*)d_in[15], (const float*)d_in[19]};
    const float* rj_w1    = (const float*)d_in[20];
    const float* rj_b1    = (const float*)d_in[21];
    const float* rj_w2    = (const float*)d_in[22];
    const float* rj_b2    = (const float*)d_in[23];
    const float* k_noise  = (const float*)d_in[24];
    const float* v_noise  = (const float*)d_in[25];
    const float* proj_w   = (const float*)d_in[26];
    const float* proj_b   = (const float*)d_in[27];

    float *xa0, *xa1, *q, *h, *s, *qkv, *kp1, *vp1, *o, *nbuf, *cpart, *xi, *kv, *ck, *cv;
    cudaGetSymbolAddress((void**)&xa0,   g_xa0);
    cudaGetSymbolAddress((void**)&xa1,   g_xa1);
    cudaGetSymbolAddress((void**)&q,     g_q);
    cudaGetSymbolAddress((void**)&h,     g_h);
    cudaGetSymbolAddress((void**)&s,     g_s);
    cudaGetSymbolAddress((void**)&qkv,   g_qkv);
    cudaGetSymbolAddress((void**)&kp1,   g_kp1);
    cudaGetSymbolAddress((void**)&vp1,   g_vp1);
    cudaGetSymbolAddress((void**)&o,     g_o);
    cudaGetSymbolAddress((void**)&nbuf,  g_n);
    cudaGetSymbolAddress((void**)&cpart, g_cpart);
    cudaGetSymbolAddress((void**)&xi,    g_xi);
    cudaGetSymbolAddress((void**)&kv,    g_kv);
    cudaGetSymbolAddress((void**)&ck,    g_ck);
    cudaGetSymbolAddress((void**)&cv,    g_cv);

    const int attn_smem = ATTN_SMEM_FLOATS * 4;
    cudaFuncSetAttribute(attn_kernel, cudaFuncAttributeMaxDynamicSharedMemorySize, attn_smem);

    float* xa[2] = {xa0, xa1};
    const float* xin[2] = {x0, x1};

    // ---- stage A: SR attention per image ----
    for (int im = 0; im < 2; im++) {
        run_gemm(xin[im], nullptr, Wq, C, bq, nullptr, q, NT, C, C, 0);
        conv_kernel<<<dim3(16, 2, KSPLIT), 256>>>(xin[im], sr_w, cpart);
        conv_reduce_kernel<<<(BM*C + 255)/256, 256>>>(cpart, sr_b, xi);
        ln_kernel<<<BM, 128>>>(xi, ln_g[im], ln_b[im]);
        run_gemm(xi, nullptr, Wkv, C, bkv, nullptr, kv, BM, 2*C, C, 0);
        attn_kernel<<<dim3(NTOK/64, HEADS, BB), 256, attn_smem>>>(q, kv, xa[im]);
    }

    // ---- stage B: per direction ----
    for (int d = 0; d < 2; d++) {
        const float* a  = xa[d];
        const float* bb = xa[1-d];
        float* dst = (float*)d_out + (size_t)d * NT * C;

        // judger: h = gelu(a@W1a^T + bb@W1b^T + b1); s = softmax(h@W2^T + b2)
        run_gemm(a,  nullptr, rj_w1,     2*C, rj_b1,  nullptr, h, NT, C, C, 0);
        run_gemm(bb, nullptr, rj_w1 + C, 2*C, nullptr,nullptr, h, NT, C, C, F_ACCUM | F_GELU);
        run_gemm(h,  nullptr, rj_w2,     C,   rj_b2,  nullptr, s, NT, C, C, 0);
        rowsoftmax_kernel<<<NT/8, 256>>>(s);

        cknoise_kernel<<<1, 256>>>(in_w[d], k_noise + d*C, v_noise + d*C, ck, cv);

        // fused qp|kp-raw|vp-raw, plus the two data-dependent projections
        run_gemm(a,  nullptr, in_w[d],           C, in_b[d],       nullptr, qkv, NT, 3*C, C, 0);
        run_gemm(a,  s,       in_w[d] + C*C,     C, in_b[d] + C,   nullptr, kp1, NT, C,   C, 0);
        run_gemm(bb, nullptr, in_w[d] + 2*C*C,   C, in_b[d] + 2*C, nullptr, vp1, NT, C,   C, 0);

        combine_kernel<<<(long)NT*XH/256, 256>>>(qkv, kp1, vp1, ck, cv, o);

        // n = a + o@out_w^T + out_b ;  out = n@proj_w^T + proj_b
        run_gemm(o,    nullptr, out_w[d], C, out_b[d], a,       nbuf, NT, C, C, 0);
        run_gemm(nbuf, nullptr, proj_w,   C, proj_b,   nullptr, dst,  NT, C, C, 0);
    }
}

// round 4
// speedup vs baseline: 1.7133x; 1.7133x over previous
#include <cuda_runtime.h>
#include <math.h>

#define BB 4
#define NTOK 16384
#define C 128
#define NT (BB*NTOK)      /* 65536 token rows */
#define M 256             /* sr tokens per image */
#define BM (BB*M)         /* 1024 */
#define HEADS 2
#define DH 64
#define XH 8
#define KCONV 8192
#define KSPLIT 8

#define F_ACCUM 1
#define F_GELU  2

// ------------------------- scratch (static device globals; no allocs) -----
__device__ __align__(256) float g_xa0[NT*C];
__device__ __align__(256) float g_xa1[NT*C];
__device__ __align__(256) float g_q  [NT*C];
__device__ __align__(256) float g_h  [NT*C];
__device__ __align__(256) float g_s  [NT*C];
__device__ __align__(256) float g_qkv[(size_t)NT*3*C];
__device__ __align__(256) float g_kp1[NT*C];
__device__ __align__(256) float g_vp1[NT*C];
__device__ __align__(256) float g_o  [NT*C];
__device__ __align__(256) float g_n  [NT*C];
__device__ __align__(256) float g_cpart[KSPLIT*BM*C];
__device__ __align__(256) float g_xi [BM*C];
__device__ __align__(256) float g_kv [BM*2*C];
__device__ __align__(256) float g_ck [C];
__device__ __align__(256) float g_cv [C];

// ------------------------- helpers ---------------------------------------
__device__ __forceinline__ float gelu_exact(float v){
    return 0.5f * v * (1.0f + erff(v * 0.70710678118654752f));
}
__device__ __forceinline__ float warp_sum(float v){
    #pragma unroll
    for (int o = 16; o > 0; o >>= 1) v += __shfl_xor_sync(0xffffffffu, v, o);
    return v;
}
__device__ __forceinline__ unsigned f2tf(float x){
    unsigned r; asm("cvt.rna.tf32.f32 %0, %1;" : "=r"(r) : "f"(x)); return r;
}
__device__ __forceinline__ void mma8(float* c, const unsigned* a, const unsigned* b){
    asm("mma.sync.aligned.m16n8k8.row.col.f32.tf32.tf32.f32 "
        "{%0,%1,%2,%3}, {%4,%5,%6,%7}, {%8,%9}, {%0,%1,%2,%3};"
        : "+f"(c[0]),"+f"(c[1]),"+f"(c[2]),"+f"(c[3])
        : "r"(a[0]),"r"(a[1]),"r"(a[2]),"r"(a[3]), "r"(b[0]),"r"(b[1]));
}
__device__ __forceinline__ unsigned long long pk2(float lo, float hi){
    unsigned long long r;
    asm("mov.b64 %0, {%1,%2};" : "=l"(r) : "f"(lo), "f"(hi));
    return r;
}
__device__ __forceinline__ void upk2(unsigned long long v, float& lo, float& hi){
    asm("mov.b64 {%0,%1}, %2;" : "=f"(lo), "=f"(hi) : "l"(v));
}
__device__ __forceinline__ unsigned long long ffma2(unsigned long long a,
        unsigned long long b, unsigned long long c){
    unsigned long long r;
    asm("fma.rn.f32x2 %0, %1, %2, %3;" : "=l"(r) : "l"(a), "l"(b), "l"(c));
    return r;
}

// ===================== tf32 tensor-core GEMM ==============================
// D[R x N] = concat(A, A2)[R x Ktot] @ W^T (+bias/gelu/resid), lda fixed 128.
// Block 256x128, 8 warps of 64x64, K-chunks of 32, double buffered.
#define AST 36
#define BST 36
#define MMA_SMEM_BYTES ((2*256*AST + 2*128*BST)*4)

__global__ void __launch_bounds__(256, 1) mma_gemm(
    const float* __restrict__ A, const float* __restrict__ A2,
    const float* __restrict__ Am,
    const float* __restrict__ W, int ldw,
    const float* __restrict__ bias, const float* __restrict__ resid,
    float* __restrict__ D, int Ncols, int Ktot, int flags)
{
    extern __shared__ unsigned smu[];
    unsigned* AsB = smu;                 // [2][256][AST]
    unsigned* BsB = smu + 2*256*AST;     // [2][128][BST]

    const int tid  = threadIdx.x;
    const int lane = tid & 31, wid = tid >> 5;
    const int wm = wid >> 1, wn = wid & 1;
    const long row0 = (long)blockIdx.x * 256;
    const int  col0 = blockIdx.y * 128;
    const int lrow = tid >> 3;           // 0..31
    const int lcol = (tid & 7) << 2;     // 0,4,...,28

    float acc[4][8][4];
    #pragma unroll
    for (int i=0;i<4;i++)
        #pragma unroll
        for (int j=0;j<8;j++)
            #pragma unroll
            for (int t=0;t<4;t++) acc[i][j][t]=0.f;

    const int nch = Ktot >> 5;
    float4 areg[8], breg[4];

    // ---- load chunk 0 ----
    #pragma unroll
    for (int i=0;i<8;i++){
        long r = row0 + lrow + i*32;
        float4 v = *(const float4*)(A + r*128 + lcol);
        if (Am){ float4 m = *(const float4*)(Am + r*128 + lcol);
                 v.x*=m.x; v.y*=m.y; v.z*=m.z; v.w*=m.w; }
        areg[i] = v;
    }
    #pragma unroll
    for (int i=0;i<4;i++)
        breg[i] = *(const float4*)(W + (long)(col0 + lrow + i*32)*ldw + lcol);
    // ---- store chunk 0 ----
    {
        unsigned* Ab = AsB;
        unsigned* Bb = BsB;
        #pragma unroll
        for (int i=0;i<8;i++){
            uint4 u = make_uint4(f2tf(areg[i].x),f2tf(areg[i].y),f2tf(areg[i].z),f2tf(areg[i].w));
            *(uint4*)(Ab + (lrow + i*32)*AST + lcol) = u;
        }
        #pragma unroll
        for (int i=0;i<4;i++){
            uint4 u = make_uint4(f2tf(breg[i].x),f2tf(breg[i].y),f2tf(breg[i].z),f2tf(breg[i].w));
            *(uint4*)(Bb + (lrow + i*32)*BST + lcol) = u;
        }
    }
    __syncthreads();

    for (int ch = 0; ch < nch; ch++){
        // prefetch next chunk into registers
        if (ch+1 < nch){
            int kk = (ch+1)*32;
            const float* Asrc = (kk < 128) ? A : A2;
            int kc = kk & 127;
            #pragma unroll
            for (int i=0;i<8;i++){
                long r = row0 + lrow + i*32;
                float4 v = *(const float4*)(Asrc + r*128 + kc + lcol);
                if (Am && kk < 128){
                    float4 m = *(const float4*)(Am + r*128 + kc + lcol);
                    v.x*=m.x; v.y*=m.y; v.z*=m.z; v.w*=m.w;
                }
                areg[i] = v;
            }
            #pragma unroll
            for (int i=0;i<4;i++)
                breg[i] = *(const float4*)(W + (long)(col0 + lrow + i*32)*ldw + kk + lcol);
        }
        // compute current
        const unsigned* Ab = AsB + (ch&1)*(256*AST);
        const unsigned* Bb = BsB + (ch&1)*(128*BST);
        #pragma unroll
        for (int kb=0;kb<4;kb++){
            const int k0 = kb*8;
            unsigned af[4][4], bf[8][2];
            #pragma unroll
            for (int i=0;i<4;i++){
                const unsigned* p = Ab + (wm*64 + i*16 + (lane>>2))*AST + k0 + (lane&3);
                af[i][0]=p[0]; af[i][1]=p[8*AST]; af[i][2]=p[4]; af[i][3]=p[8*AST+4];
            }
            #pragma unroll
            for (int j=0;j<8;j++){
                const unsigned* p = Bb + (wn*64 + j*8 + (lane>>2))*BST + k0 + (lane&3);
                bf[j][0]=p[0]; bf[j][1]=p[4];
            }
            #pragma unroll
            for (int i=0;i<4;i++)
                #pragma unroll
                for (int j=0;j<8;j++)
                    mma8(acc[i][j], af[i], bf[j]);
        }
        __syncthreads();
        if (ch+1 < nch){
            unsigned* Ab2 = AsB + ((ch+1)&1)*(256*AST);
            unsigned* Bb2 = BsB + ((ch+1)&1)*(128*BST);
            #pragma unroll
            for (int i=0;i<8;i++){
                uint4 u = make_uint4(f2tf(areg[i].x),f2tf(areg[i].y),f2tf(areg[i].z),f2tf(areg[i].w));
                *(uint4*)(Ab2 + (lrow + i*32)*AST + lcol) = u;
            }
            #pragma unroll
            for (int i=0;i<4;i++){
                uint4 u = make_uint4(f2tf(breg[i].x),f2tf(breg[i].y),f2tf(breg[i].z),f2tf(breg[i].w));
                *(uint4*)(Bb2 + (lrow + i*32)*BST + lcol) = u;
            }
            __syncthreads();
        }
    }

    // ---- epilogue ----
    #pragma unroll
    for (int i=0;i<4;i++){
        long r = row0 + wm*64 + i*16 + (lane>>2);
        #pragma unroll
        for (int j=0;j<8;j++){
            int cc = col0 + wn*64 + j*8 + ((lane&3)<<1);
            float2 v0 = make_float2(acc[i][j][0], acc[i][j][1]);
            float2 v1 = make_float2(acc[i][j][2], acc[i][j][3]);
            if (bias){
                float2 b2 = *(const float2*)(bias + cc);
                v0.x+=b2.x; v0.y+=b2.y; v1.x+=b2.x; v1.y+=b2.y;
            }
            if (flags & F_GELU){
                v0.x=gelu_exact(v0.x); v0.y=gelu_exact(v0.y);
                v1.x=gelu_exact(v1.x); v1.y=gelu_exact(v1.y);
            }
            if (resid){
                float2 r0 = *(const float2*)(resid + r*(long)Ncols + cc);
                float2 r1 = *(const float2*)(resid + (r+8)*(long)Ncols + cc);
                v0.x+=r0.x; v0.y+=r0.y; v1.x+=r1.x; v1.y+=r1.y;
            }
            *(float2*)(D + r*(long)Ncols + cc) = v0;
            *(float2*)(D + (r+8)*(long)Ncols + cc) = v1;
        }
    }
}

// ------------------------- scalar GEMM (kept for tiny kv proj) ------------
__global__ void __launch_bounds__(256) gemm_kernel(
    const float* __restrict__ A, const float* __restrict__ Am,
    const float* __restrict__ W, int ldw,
    const float* __restrict__ bias, const float* __restrict__ resid,
    float* __restrict__ D, int Ncols, int K, int flags)
{
    __shared__ float As[16][64];
    __shared__ float Ws[16][64];
    const int tid = threadIdx.x;
    const int tx = tid & 15, ty = tid >> 4;
    const long row0 = (long)blockIdx.x * 64;
    const int  col0 = blockIdx.y * 64;
    const int lr = tid >> 2;
    const int lk = (tid & 3) << 2;

    const float* Arow  = A + (row0 + lr) * (long)K + lk;
    const float* Wrow  = W + (long)(col0 + lr) * ldw + lk;

    float acc[4][4] = {};
    for (int kk = 0; kk < K; kk += 16) {
        float4 av = *(const float4*)(Arow + kk);
        float4 wv = *(const float4*)(Wrow + kk);
        As[lk+0][lr]=av.x; As[lk+1][lr]=av.y; As[lk+2][lr]=av.z; As[lk+3][lr]=av.w;
        Ws[lk+0][lr]=wv.x; Ws[lk+1][lr]=wv.y; Ws[lk+2][lr]=wv.z; Ws[lk+3][lr]=wv.w;
        __syncthreads();
        #pragma unroll
        for (int k = 0; k < 16; k++) {
            float ar[4], br[4];
            *(float4*)ar = *(const float4*)&As[k][ty<<2];
            *(float4*)br = *(const float4*)&Ws[k][tx<<2];
            #pragma unroll
            for (int i = 0; i < 4; i++)
                #pragma unroll
                for (int j = 0; j < 4; j++)
                    acc[i][j] += ar[i] * br[j];
        }
        __syncthreads();
    }
    #pragma unroll
    for (int i = 0; i < 4; i++) {
        long r = row0 + (ty<<2) + i;
        int  c = col0 + (tx<<2);
        float4 v = make_float4(acc[i][0],acc[i][1],acc[i][2],acc[i][3]);
        if (bias){ v.x+=bias[c]; v.y+=bias[c+1]; v.z+=bias[c+2]; v.w+=bias[c+3]; }
        *(float4*)(D + r * (long)Ncols + c) = v;
    }
}

// ------------------------- patch conv as split-K implicit GEMM -----------
__global__ void __launch_bounds__(256) conv_kernel(
    const float* __restrict__ x, const float* __restrict__ srw,
    float* __restrict__ part)
{
    __shared__ float As[16][64];
    __shared__ float Ws[16][64];
    const int tid = threadIdx.x;
    const int tx = tid & 15, ty = tid >> 4;
    const int row0 = blockIdx.x * 64;
    const int col0 = blockIdx.y * 64;
    const int kz   = blockIdx.z;
    const int lr = tid >> 2;
    const int lk = (tid & 3) << 2;

    const int r  = row0 + lr;
    const int b_ = r >> 8, p = r & 255, ph = p >> 4, pw = p & 15;
    const float* Wrow = srw + (long)(col0 + lr) * KCONV + kz * 1024 + lk;

    float acc[4][4] = {};
    for (int kk = 0; kk < 1024; kk += 16) {
        const int kg  = kz*1024 + kk + lk;
        const int i   = kg >> 6;
        const int rem = kg & 63;
        const int kh  = rem >> 3, kw = rem & 7;
        const float* xp = x + ((long)b_*NTOK + (ph*8+kh)*128 + (pw*8+kw)) * C + i;
        As[lk+0][lr]=xp[0]; As[lk+1][lr]=xp[C]; As[lk+2][lr]=xp[2*C]; As[lk+3][lr]=xp[3*C];
        float4 wv = *(const float4*)(Wrow + kk);
        Ws[lk+0][lr]=wv.x; Ws[lk+1][lr]=wv.y; Ws[lk+2][lr]=wv.z; Ws[lk+3][lr]=wv.w;
        __syncthreads();
        #pragma unroll
        for (int k = 0; k < 16; k++) {
            float ar[4], br[4];
            *(float4*)ar = *(const float4*)&As[k][ty<<2];
            *(float4*)br = *(const float4*)&Ws[k][tx<<2];
            #pragma unroll
            for (int i2 = 0; i2 < 4; i2++)
                #pragma unroll
                for (int j = 0; j < 4; j++)
                    acc[i2][j] += ar[i2] * br[j];
        }
        __syncthreads();
    }
    #pragma unroll
    for (int i2 = 0; i2 < 4; i2++) {
        int rr = row0 + (ty<<2) + i2;
        float4 v = make_float4(acc[i2][0],acc[i2][1],acc[i2][2],acc[i2][3]);
        *(float4*)(part + ((long)kz*BM + rr)*C + col0 + (tx<<2)) = v;
    }
}

__global__ void conv_reduce_kernel(const float* __restrict__ part,
                                   const float* __restrict__ srb,
                                   float* __restrict__ xi)
{
    int idx = blockIdx.x * 256 + threadIdx.x;
    if (idx < BM*C) {
        float s = srb[idx & (C-1)];
        #pragma unroll
        for (int z = 0; z < KSPLIT; z++) s += part[(long)z*BM*C + idx];
        xi[idx] = s;
    }
}

// ------------------------- layernorm over C (in place) --------------------
__global__ void ln_kernel(float* __restrict__ xi, const float* __restrict__ g,
                          const float* __restrict__ b)
{
    const int row = blockIdx.x, t = threadIdx.x;
    __shared__ float red[4];
    __shared__ float mv[2];
    float v = xi[(long)row*C + t];
    float s = warp_sum(v);
    if ((t & 31) == 0) red[t >> 5] = s;
    __syncthreads();
    if (t == 0) mv[0] = (red[0]+red[1]+red[2]+red[3]) * (1.0f/C);
    __syncthreads();
    float d = v - mv[0];
    float s2 = warp_sum(d*d);
    if ((t & 31) == 0) red[t >> 5] = s2;
    __syncthreads();
    if (t == 0) mv[1] = (red[0]+red[1]+red[2]+red[3]) * (1.0f/C);
    __syncthreads();
    xi[(long)row*C + t] = d * rsqrtf(mv[1] + 1e-5f) * g[t] + b[t];
}

// ------------------------- SR attention (K,V,scores all in smem) ----------
#define ATTN_SMEM_FLOATS (64*68 + 256*64 + 256*64 + 64*257 + 256 + 64)
__global__ void __launch_bounds__(256) attn_kernel(
    const float* __restrict__ Q, const float* __restrict__ KV,
    float* __restrict__ O)
{
    extern __shared__ float sm[];
    float* Qs   = sm;                  // [64][68]
    float* Ks   = Qs + 64*68;          // [256][64]
    float* Vs   = Ks + 256*64;         // [256][64]
    float* S    = Vs + 256*64;         // [64][257]
    float* red  = S  + 64*257;         // [64][4]
    float* rowv = red + 256;           // [64]

    const int tid = threadIdx.x;
    const int h  = blockIdx.y, b_ = blockIdx.z;
    const int q0 = blockIdx.x * 64;

    for (int e = tid; e < 64*16; e += 256) {
        int qq = e >> 4, d4 = (e & 15) << 2;
        float4 v = *(const float4*)(Q + ((long)b_*NTOK + q0 + qq)*C + h*DH + d4);
        *(float4*)&Qs[qq*68 + d4] = v;
    }
    for (int e = tid; e < 256*16; e += 256) {
        int m = e >> 4, d4 = (e & 15) << 2;
        const float* base = KV + ((long)b_*M + m)*(2*C) + h*DH + d4;
        *(float4*)&Ks[m*64 + d4] = *(const float4*)base;
        *(float4*)&Vs[m*64 + d4] = *(const float4*)(base + C);
    }
    __syncthreads();

    const int q  = tid & 63;
    const int mg = tid >> 6;    // 0..3

    unsigned long long q2[32];
    #pragma unroll
    for (int d = 0; d < 16; d++) {
        float4 v = *(const float4*)&Qs[q*68 + d*4];
        q2[2*d]   = pk2(v.x, v.y);
        q2[2*d+1] = pk2(v.z, v.w);
    }
    for (int mi = 0; mi < 64; mi++) {
        int m = mg*64 + mi;
        const float4* kr = (const float4*)&Ks[m*64];
        unsigned long long a0 = 0ull, a1 = 0ull;
        #pragma unroll
        for (int dd = 0; dd < 16; dd++) {
            float4 kv4 = kr[dd];
            a0 = ffma2(pk2(kv4.x,kv4.y), q2[2*dd],   a0);
            a1 = ffma2(pk2(kv4.z,kv4.w), q2[2*dd+1], a1);
        }
        float x0,x1,y0,y1; upk2(a0,x0,x1); upk2(a1,y0,y1);
        S[q*257 + m] = (x0+x1+y0+y1) * 0.125f;
    }
    __syncthreads();

    float lmax = -1e30f;
    for (int mi = 0; mi < 64; mi++) lmax = fmaxf(lmax, S[q*257 + mg*64 + mi]);
    red[q*4 + mg] = lmax;
    __syncthreads();
    if (tid < 64)
        rowv[tid] = fmaxf(fmaxf(red[tid*4],red[tid*4+1]), fmaxf(red[tid*4+2],red[tid*4+3]));
    __syncthreads();
    float rm = rowv[q];
    float lsum = 0.f;
    for (int mi = 0; mi < 64; mi++) {
        int m = mg*64 + mi;
        float e = expf(S[q*257 + m] - rm);
        S[q*257 + m] = e;
        lsum += e;
    }
    red[q*4 + mg] = lsum;
    __syncthreads();
    if (tid < 64)
        rowv[tid] = 1.0f / (red[tid*4]+red[tid*4+1]+red[tid*4+2]+red[tid*4+3]);
    __syncthreads();

    const int dg = mg;
    unsigned long long o2[8];
    #pragma unroll
    for (int t = 0; t < 8; t++) o2[t] = 0ull;
    for (int m = 0; m < 256; m++) {
        float p = S[q*257 + m];
        unsigned long long pd = pk2(p, p);
        const float4* vr = (const float4*)&Vs[m*64 + dg*16];
        #pragma unroll
        for (int t = 0; t < 4; t++) {
            float4 v4 = vr[t];
            o2[2*t]   = ffma2(pk2(v4.x,v4.y), pd, o2[2*t]);
            o2[2*t+1] = ffma2(pk2(v4.z,v4.w), pd, o2[2*t+1]);
        }
    }
    float inv = rowv[q];
    float ov[16];
    #pragma unroll
    for (int t = 0; t < 8; t++) upk2(o2[t], ov[2*t], ov[2*t+1]);
    float* op = O + ((long)b_*NTOK + q0 + q)*C + h*DH + dg*16;
    #pragma unroll
    for (int dd = 0; dd < 16; dd += 4)
        *(float4*)(op + dd) = make_float4(ov[dd]*inv, ov[dd+1]*inv, ov[dd+2]*inv, ov[dd+3]*inv);
}

// ------------------------- judger row softmax -----------------------------
__global__ void rowsoftmax_kernel(float* __restrict__ S)
{
    const int row  = blockIdx.x * 8 + (threadIdx.x >> 5);
    const int lane = threadIdx.x & 31;
    float* p = S + (long)row*C + lane*4;
    float4 v = *(const float4*)p;
    float m = fmaxf(fmaxf(v.x,v.y), fmaxf(v.z,v.w));
    #pragma unroll
    for (int o = 16; o > 0; o >>= 1) m = fmaxf(m, __shfl_xor_sync(0xffffffffu, m, o));
    float4 e = make_float4(expf(v.x-m), expf(v.y-m), expf(v.z-m), expf(v.w-m));
    float s = e.x+e.y+e.z+e.w;
    s = warp_sum(s);
    float inv = 1.0f/s;
    e.x*=inv; e.y*=inv; e.z*=inv; e.w*=inv;
    *(float4*)p = e;
}

// ------------------------- constant noise projections ---------------------
__global__ void cknoise_kernel(const float* __restrict__ inw,
                               const float* __restrict__ kn,
                               const float* __restrict__ vn,
                               float* __restrict__ ck, float* __restrict__ cv)
{
    int t = threadIdx.x;
    if (t < 128) {
        const float* w = inw + (long)(C + t)*C;
        float s = 0.f;
        #pragma unroll 4
        for (int j = 0; j < C; j++) s += kn[j]*w[j];
        ck[t] = s;
    } else {
        int c = t - 128;
        const float* w = inw + (long)(2*C + c)*C;
        float s = 0.f;
        #pragma unroll 4
        for (int j = 0; j < C; j++) s += vn[j]*w[j];
        cv[c] = s;
    }
}

// ------------------------- per-token 2-key attention combine --------------
__global__ void combine_kernel(const float* __restrict__ qkv,
                               const float* __restrict__ kp1,
                               const float* __restrict__ vp1,
                               const float* __restrict__ ck,
                               const float* __restrict__ cv,
                               float* __restrict__ O)
{
    long idx = (long)blockIdx.x * 256 + threadIdx.x;
    long r = idx >> 3;
    int  h = (int)(idx & 7);
    const float* qp = qkv + r*384 + h*16;
    const float* k0 = qkv + r*384 + 128 + h*16;
    const float* v0 = qkv + r*384 + 256 + h*16;
    const float* k1 = kp1 + r*128 + h*16;
    const float* v1 = vp1 + r*128 + h*16;
    const float* ckh = ck + h*16;
    const float* cvh = cv + h*16;
    float s0 = 0.f, s1 = 0.f;
    #pragma unroll
    for (int i = 0; i < 16; i++) {
        float qv = qp[i];
        s0 += qv * (k0[i] + ckh[i]);
        s1 += qv * k1[i];
    }
    s0 *= 0.25f; s1 *= 0.25f;
    float mx = fmaxf(s0, s1);
    float e0 = expf(s0-mx), e1 = expf(s1-mx);
    float inv = 1.0f/(e0+e1);
    float a0 = e0*inv, a1 = e1*inv;
    float* op = O + r*128 + h*16;
    #pragma unroll
    for (int i = 0; i < 16; i++)
        op[i] = a0*(v0[i] + cvh[i]) + a1*v1[i];
}

// ------------------------- host driver ------------------------------------
static void run_mma(const float* A, const float* A2, const float* Am,
                    const float* W, int ldw,
                    const float* bias, const float* resid, float* D,
                    int Ncols, int Ktot, int flags)
{
    dim3 g(NT/256, Ncols/128);
    mma_gemm<<<g, 256, MMA_SMEM_BYTES>>>(A, A2, Am, W, ldw, bias, resid, D, Ncols, Ktot, flags);
}

extern "C" void kernel_launch(void* const* d_in, const int* in_sizes, int n_in,
                              void* d_out, int out_size)
{
    const float* x0       = (const float*)d_in[0];
    const float* x1       = (const float*)d_in[1];
    const float* Wq       = (const float*)d_in[2];
    const float* bq       = (const float*)d_in[3];
    const float* Wkv      = (const float*)d_in[4];
    const float* bkv      = (const float*)d_in[5];
    const float* sr_w     = (const float*)d_in[6];
    const float* sr_b     = (const float*)d_in[7];
    const float* ln_g[2]  = {(const float*)d_in[8],  (const float*)d_in[10]};
    const float* ln_b[2]  = {(const float*)d_in[9],  (const float*)d_in[11]};
    const float* in_w[2]  = {(const float*)d_in[12], (const float*)d_in[16]};
    const float* in_b[2]  = {(const float*)d_in[13], (const float*)d_in[17]};
    const float* out_w[2] = {(const float*)d_in[14], (const float*)d_in[18]};
    const float* out_b[2] = {(const float*)d_in[15], (const float*)d_in[19]};
    const float* rj_w1    = (const float*)d_in[20];
    const float* rj_b1    = (const float*)d_in[21];
    const float* rj_w2    = (const float*)d_in[22];
    const float* rj_b2    = (const float*)d_in[23];
    const float* k_noise  = (const float*)d_in[24];
    const float* v_noise  = (const float*)d_in[25];
    const float* proj_w   = (const float*)d_in[26];
    const float* proj_b   = (const float*)d_in[27];

    float *xa0, *xa1, *q, *h, *s, *qkv, *kp1, *vp1, *o, *nbuf, *cpart, *xi, *kv, *ck, *cv;
    cudaGetSymbolAddress((void**)&xa0,   g_xa0);
    cudaGetSymbolAddress((void**)&xa1,   g_xa1);
    cudaGetSymbolAddress((void**)&q,     g_q);
    cudaGetSymbolAddress((void**)&h,     g_h);
    cudaGetSymbolAddress((void**)&s,     g_s);
    cudaGetSymbolAddress((void**)&qkv,   g_qkv);
    cudaGetSymbolAddress((void**)&kp1,   g_kp1);
    cudaGetSymbolAddress((void**)&vp1,   g_vp1);
    cudaGetSymbolAddress((void**)&o,     g_o);
    cudaGetSymbolAddress((void**)&nbuf,  g_n);
    cudaGetSymbolAddress((void**)&cpart, g_cpart);
    cudaGetSymbolAddress((void**)&xi,    g_xi);
    cudaGetSymbolAddress((void**)&kv,    g_kv);
    cudaGetSymbolAddress((void**)&ck,    g_ck);
    cudaGetSymbolAddress((void**)&cv,    g_cv);

    const int attn_smem = ATTN_SMEM_FLOATS * 4;
    cudaFuncSetAttribute(attn_kernel, cudaFuncAttributeMaxDynamicSharedMemorySize, attn_smem);
    cudaFuncSetAttribute(mma_gemm, cudaFuncAttributeMaxDynamicSharedMemorySize, MMA_SMEM_BYTES);

    float* xa[2] = {xa0, xa1};
    const float* xin[2] = {x0, x1};

    // ---- stage A: SR attention per image ----
    for (int im = 0; im < 2; im++) {
        run_mma(xin[im], nullptr, nullptr, Wq, C, bq, nullptr, q, C, C, 0);
        conv_kernel<<<dim3(16, 2, KSPLIT), 256>>>(xin[im], sr_w, cpart);
        conv_reduce_kernel<<<(BM*C + 255)/256, 256>>>(cpart, sr_b, xi);
        ln_kernel<<<BM, 128>>>(xi, ln_g[im], ln_b[im]);
        gemm_kernel<<<dim3(BM/64, (2*C)/64), 256>>>(xi, nullptr, Wkv, C, bkv, nullptr, kv, 2*C, C, 0);
        attn_kernel<<<dim3(NTOK/64, HEADS, BB), 256, attn_smem>>>(q, kv, xa[im]);
    }

    // ---- stage B: per direction ----
    for (int d = 0; d < 2; d++) {
        const float* a  = xa[d];
        const float* bb = xa[1-d];
        float* dst = (float*)d_out + (size_t)d * NT * C;

        // judger fused K=256: h = gelu(concat(a,bb) @ rj_w1^T + rj_b1)
        run_mma(a, bb, nullptr, rj_w1, 2*C, rj_b1, nullptr, h, C, 2*C, F_GELU);
        run_mma(h, nullptr, nullptr, rj_w2, C, rj_b2, nullptr, s, C, C, 0);
        rowsoftmax_kernel<<<NT/8, 256>>>(s);

        cknoise_kernel<<<1, 256>>>(in_w[d], k_noise + d*C, v_noise + d*C, ck, cv);

        run_mma(a,  nullptr, nullptr, in_w[d],         C, in_b[d],       nullptr, qkv, 3*C, C, 0);
        run_mma(a,  nullptr, s,       in_w[d] + C*C,   C, in_b[d] + C,   nullptr, kp1, C,   C, 0);
        run_mma(bb, nullptr, nullptr, in_w[d] + 2*C*C, C, in_b[d] + 2*C, nullptr, vp1, C,   C, 0);

        combine_kernel<<<(long)NT*XH/256, 256>>>(qkv, kp1, vp1, ck, cv, o);

        run_mma(o,    nullptr, nullptr, out_w[d], C, out_b[d], a,       nbuf, C, C, 0);
        run_mma(nbuf, nullptr, nullptr, proj_w,   C, proj_b,   nullptr, dst,  C, C, 0);
    }
}

// round 5
// speedup vs baseline: 1.7346x; 1.0124x over previous
#include <cuda_runtime.h>
#include <math.h>

#define BB 4
#define NTOK 16384
#define C 128
#define NT (BB*NTOK)      /* 65536 token rows */
#define M 256             /* sr tokens per image */
#define BM (BB*M)         /* 1024 */
#define HEADS 2
#define DH 64
#define XH 8
#define KCONV 8192
#define KSPLIT 8

#define F_GELU  2

// ------------------------- scratch (static device globals; no allocs) -----
__device__ __align__(256) float g_xa0[NT*C];
__device__ __align__(256) float g_xa1[NT*C];
__device__ __align__(256) float g_q  [NT*C];
__device__ __align__(256) float g_h  [NT*C];
__device__ __align__(256) float g_s  [NT*C];
__device__ __align__(256) float g_qkv[(size_t)NT*3*C];
__device__ __align__(256) float g_kp1[NT*C];
__device__ __align__(256) float g_vp1[NT*C];
__device__ __align__(256) float g_o  [NT*C];
__device__ __align__(256) float g_cpart[KSPLIT*BM*C];
__device__ __align__(256) float g_xi [BM*C];
__device__ __align__(256) float g_kv [BM*2*C];
__device__ __align__(256) float g_ck [C];
__device__ __align__(256) float g_cv [C];
__device__ __align__(256) float g_wf [C*2*C];
__device__ __align__(256) float g_bc [C];

// ------------------------- helpers ---------------------------------------
__device__ __forceinline__ float gelu_exact(float v){
    return 0.5f * v * (1.0f + erff(v * 0.70710678118654752f));
}
__device__ __forceinline__ float warp_sum(float v){
    #pragma unroll
    for (int o = 16; o > 0; o >>= 1) v += __shfl_xor_sync(0xffffffffu, v, o);
    return v;
}
__device__ __forceinline__ unsigned f2tf(float x){
    unsigned r; asm("cvt.rna.tf32.f32 %0, %1;" : "=r"(r) : "f"(x)); return r;
}
__device__ __forceinline__ void mma8(float* c, const unsigned* a, const unsigned* b){
    asm("mma.sync.aligned.m16n8k8.row.col.f32.tf32.tf32.f32 "
        "{%0,%1,%2,%3}, {%4,%5,%6,%7}, {%8,%9}, {%0,%1,%2,%3};"
        : "+f"(c[0]),"+f"(c[1]),"+f"(c[2]),"+f"(c[3])
        : "r"(a[0]),"r"(a[1]),"r"(a[2]),"r"(a[3]), "r"(b[0]),"r"(b[1]));
}
__device__ __forceinline__ unsigned long long pk2(float lo, float hi){
    unsigned long long r;
    asm("mov.b64 %0, {%1,%2};" : "=l"(r) : "f"(lo), "f"(hi));
    return r;
}
__device__ __forceinline__ void upk2(unsigned long long v, float& lo, float& hi){
    asm("mov.b64 {%0,%1}, %2;" : "=f"(lo), "=f"(hi) : "l"(v));
}
__device__ __forceinline__ unsigned long long ffma2(unsigned long long a,
        unsigned long long b, unsigned long long c){
    unsigned long long r;
    asm("fma.rn.f32x2 %0, %1, %2, %3;" : "=l"(r) : "l"(a), "l"(b), "l"(c));
    return r;
}

// ===================== tf32 tensor-core GEMM v2 ===========================
// D[NT x Ncols] = concat(A,A2)[NT x Ktot] @ W^T (+bias, +gelu). lda fixed 128.
// 512 threads, CTA tile 256x128, 16 warps of 64x32, cp.async double buffer.
#define AST 36
#define BST 36
#define MMA_SMEM_BYTES ((2*256*AST + 2*128*BST)*4)

__global__ void __launch_bounds__(512, 1) mma_gemm(
    const float* __restrict__ A, const float* __restrict__ A2,
    const float* __restrict__ W, int ldw,
    const float* __restrict__ bias,
    float* __restrict__ D, int Ncols, int Ktot, int flags)
{
    extern __shared__ float smf[];
    float* Asm = smf;               // [2][256*AST]
    float* Bsm = smf + 2*256*AST;   // [2][128*BST]

    const int tid = threadIdx.x;
    const int lane = tid & 31, wid = tid >> 5;
    const int wm = wid >> 2, wn = wid & 3;
    const long row0 = (long)blockIdx.x * 256;
    const int  col0 = blockIdx.y * 128;

    float acc[4][4][4];
    #pragma unroll
    for (int i=0;i<4;i++)
        #pragma unroll
        for (int j=0;j<4;j++)
            #pragma unroll
            for (int t=0;t<4;t++) acc[i][j][t]=0.f;

    const int nch = Ktot >> 5;

    auto issue = [&](int ch){
        const int kk = ch*32;
        const float* Asrc = (kk < 128) ? A : A2;
        const int kc = kk & 127;
        float* Ab = Asm + (ch&1)*(256*AST);
        float* Bb = Bsm + (ch&1)*(128*BST);
        #pragma unroll
        for (int t=0;t<4;t++){
            int s = tid + t*512;
            int row = s >> 3, kq = (s & 7) << 2;
            unsigned sa = (unsigned)__cvta_generic_to_shared(Ab + row*AST + kq);
            const float* ga = Asrc + (row0+row)*128 + kc + kq;
            asm volatile("cp.async.cg.shared.global [%0],[%1],16;\n"::"r"(sa),"l"(ga));
        }
        #pragma unroll
        for (int t=0;t<2;t++){
            int s = tid + t*512;
            int row = s >> 3, kq = (s & 7) << 2;
            unsigned sb = (unsigned)__cvta_generic_to_shared(Bb + row*BST + kq);
            const float* gb = W + (long)(col0+row)*ldw + kk + kq;
            asm volatile("cp.async.cg.shared.global [%0],[%1],16;\n"::"r"(sb),"l"(gb));
        }
        asm volatile("cp.async.commit_group;\n");
    };

    issue(0);
    if (nch > 1) issue(1);

    for (int ch = 0; ch < nch; ch++){
        if (ch+1 < nch) asm volatile("cp.async.wait_group 1;\n" ::: "memory");
        else            asm volatile("cp.async.wait_group 0;\n" ::: "memory");
        __syncthreads();
        const float* Ab = Asm + (ch&1)*(256*AST);
        const float* Bb = Bsm + (ch&1)*(128*BST);
        #pragma unroll
        for (int kb=0;kb<4;kb++){
            unsigned af[4][4], bf[4][2];
            #pragma unroll
            for (int i=0;i<4;i++){
                const float* p = Ab + (wm*64 + i*16 + (lane>>2))*AST + kb*8 + (lane&3);
                af[i][0]=f2tf(p[0]);  af[i][1]=f2tf(p[8*AST]);
                af[i][2]=f2tf(p[4]);  af[i][3]=f2tf(p[8*AST+4]);
            }
            #pragma unroll
            for (int j=0;j<4;j++){
                const float* p = Bb + (wn*32 + j*8 + (lane>>2))*BST + kb*8 + (lane&3);
                bf[j][0]=f2tf(p[0]); bf[j][1]=f2tf(p[4]);
            }
            #pragma unroll
            for (int i=0;i<4;i++)
                #pragma unroll
                for (int j=0;j<4;j++)
                    mma8(acc[i][j], af[i], bf[j]);
        }
        __syncthreads();
        if (ch+2 < nch) issue(ch+2);
    }

    // ---- epilogue ----
    #pragma unroll
    for (int i=0;i<4;i++){
        long r = row0 + wm*64 + i*16 + (lane>>2);
        #pragma unroll
        for (int j=0;j<4;j++){
            int cc = col0 + wn*32 + j*8 + ((lane&3)<<1);
            float2 v0 = make_float2(acc[i][j][0], acc[i][j][1]);
            float2 v1 = make_float2(acc[i][j][2], acc[i][j][3]);
            if (bias){
                float2 b2 = *(const float2*)(bias + cc);
                v0.x+=b2.x; v0.y+=b2.y; v1.x+=b2.x; v1.y+=b2.y;
            }
            if (flags & F_GELU){
                v0.x=gelu_exact(v0.x); v0.y=gelu_exact(v0.y);
                v1.x=gelu_exact(v1.x); v1.y=gelu_exact(v1.y);
            }
            *(float2*)(D + r*(long)Ncols + cc) = v0;
            *(float2*)(D + (r+8)*(long)Ncols + cc) = v1;
        }
    }
}

// ------------------------- scalar GEMM (tiny kv proj only) ----------------
__global__ void __launch_bounds__(256) gemm_kernel(
    const float* __restrict__ A,
    const float* __restrict__ W, int ldw,
    const float* __restrict__ bias,
    float* __restrict__ D, int Ncols, int K)
{
    __shared__ float As[16][64];
    __shared__ float Ws[16][64];
    const int tid = threadIdx.x;
    const int tx = tid & 15, ty = tid >> 4;
    const long row0 = (long)blockIdx.x * 64;
    const int  col0 = blockIdx.y * 64;
    const int lr = tid >> 2;
    const int lk = (tid & 3) << 2;

    const float* Arow  = A + (row0 + lr) * (long)K + lk;
    const float* Wrow  = W + (long)(col0 + lr) * ldw + lk;

    float acc[4][4] = {};
    for (int kk = 0; kk < K; kk += 16) {
        float4 av = *(const float4*)(Arow + kk);
        float4 wv = *(const float4*)(Wrow + kk);
        As[lk+0][lr]=av.x; As[lk+1][lr]=av.y; As[lk+2][lr]=av.z; As[lk+3][lr]=av.w;
        Ws[lk+0][lr]=wv.x; Ws[lk+1][lr]=wv.y; Ws[lk+2][lr]=wv.z; Ws[lk+3][lr]=wv.w;
        __syncthreads();
        #pragma unroll
        for (int k = 0; k < 16; k++) {
            float ar[4], br[4];
            *(float4*)ar = *(const float4*)&As[k][ty<<2];
            *(float4*)br = *(const float4*)&Ws[k][tx<<2];
            #pragma unroll
            for (int i = 0; i < 4; i++)
                #pragma unroll
                for (int j = 0; j < 4; j++)
                    acc[i][j] += ar[i] * br[j];
        }
        __syncthreads();
    }
    #pragma unroll
    for (int i = 0; i < 4; i++) {
        long r = row0 + (ty<<2) + i;
        int  c = col0 + (tx<<2);
        float4 v = make_float4(acc[i][0],acc[i][1],acc[i][2],acc[i][3]);
        v.x+=bias[c]; v.y+=bias[c+1]; v.z+=bias[c+2]; v.w+=bias[c+3];
        *(float4*)(D + r * (long)Ncols + c) = v;
    }
}

// ------------------------- patch conv as split-K implicit GEMM -----------
__global__ void __launch_bounds__(256) conv_kernel(
    const float* __restrict__ x, const float* __restrict__ srw,
    float* __restrict__ part)
{
    __shared__ float As[16][64];
    __shared__ float Ws[16][64];
    const int tid = threadIdx.x;
    const int tx = tid & 15, ty = tid >> 4;
    const int row0 = blockIdx.x * 64;
    const int col0 = blockIdx.y * 64;
    const int kz   = blockIdx.z;
    const int lr = tid >> 2;
    const int lk = (tid & 3) << 2;

    const int r  = row0 + lr;
    const int b_ = r >> 8, p = r & 255, ph = p >> 4, pw = p & 15;
    const float* Wrow = srw + (long)(col0 + lr) * KCONV + kz * 1024 + lk;

    float acc[4][4] = {};
    for (int kk = 0; kk < 1024; kk += 16) {
        const int kg  = kz*1024 + kk + lk;
        const int i   = kg >> 6;
        const int rem = kg & 63;
        const int kh  = rem >> 3, kw = rem & 7;
        const float* xp = x + ((long)b_*NTOK + (ph*8+kh)*128 + (pw*8+kw)) * C + i;
        As[lk+0][lr]=xp[0]; As[lk+1][lr]=xp[C]; As[lk+2][lr]=xp[2*C]; As[lk+3][lr]=xp[3*C];
        float4 wv = *(const float4*)(Wrow + kk);
        Ws[lk+0][lr]=wv.x; Ws[lk+1][lr]=wv.y; Ws[lk+2][lr]=wv.z; Ws[lk+3][lr]=wv.w;
        __syncthreads();
        #pragma unroll
        for (int k = 0; k < 16; k++) {
            float ar[4], br[4];
            *(float4*)ar = *(const float4*)&As[k][ty<<2];
            *(float4*)br = *(const float4*)&Ws[k][tx<<2];
            #pragma unroll
            for (int i2 = 0; i2 < 4; i2++)
                #pragma unroll
                for (int j = 0; j < 4; j++)
                    acc[i2][j] += ar[i2] * br[j];
        }
        __syncthreads();
    }
    #pragma unroll
    for (int i2 = 0; i2 < 4; i2++) {
        int rr = row0 + (ty<<2) + i2;
        float4 v = make_float4(acc[i2][0],acc[i2][1],acc[i2][2],acc[i2][3]);
        *(float4*)(part + ((long)kz*BM + rr)*C + col0 + (tx<<2)) = v;
    }
}

__global__ void conv_reduce_kernel(const float* __restrict__ part,
                                   const float* __restrict__ srb,
                                   float* __restrict__ xi)
{
    int idx = blockIdx.x * 256 + threadIdx.x;
    if (idx < BM*C) {
        float s = srb[idx & (C-1)];
        #pragma unroll
        for (int z = 0; z < KSPLIT; z++) s += part[(long)z*BM*C + idx];
        xi[idx] = s;
    }
}

// ------------------------- layernorm over C (in place) --------------------
__global__ void ln_kernel(float* __restrict__ xi, const float* __restrict__ g,
                          const float* __restrict__ b)
{
    const int row = blockIdx.x, t = threadIdx.x;
    __shared__ float red[4];
    __shared__ float mv[2];
    float v = xi[(long)row*C + t];
    float s = warp_sum(v);
    if ((t & 31) == 0) red[t >> 5] = s;
    __syncthreads();
    if (t == 0) mv[0] = (red[0]+red[1]+red[2]+red[3]) * (1.0f/C);
    __syncthreads();
    float d = v - mv[0];
    float s2 = warp_sum(d*d);
    if ((t & 31) == 0) red[t >> 5] = s2;
    __syncthreads();
    if (t == 0) mv[1] = (red[0]+red[1]+red[2]+red[3]) * (1.0f/C);
    __syncthreads();
    xi[(long)row*C + t] = d * rsqrtf(mv[1] + 1e-5f) * g[t] + b[t];
}

// ------------------------- SR attention (K,V,scores all in smem) ----------
#define ATTN_SMEM_FLOATS (64*68 + 256*64 + 256*64 + 64*257 + 256 + 64)
__global__ void __launch_bounds__(256) attn_kernel(
    const float* __restrict__ Q, const float* __restrict__ KV,
    float* __restrict__ O)
{
    extern __shared__ float sm[];
    float* Qs   = sm;                  // [64][68]
    float* Ks   = Qs + 64*68;          // [256][64]
    float* Vs   = Ks + 256*64;         // [256][64]
    float* S    = Vs + 256*64;         // [64][257]
    float* red  = S  + 64*257;         // [64][4]
    float* rowv = red + 256;           // [64]

    const int tid = threadIdx.x;
    const int h  = blockIdx.y, b_ = blockIdx.z;
    const int q0 = blockIdx.x * 64;

    for (int e = tid; e < 64*16; e += 256) {
        int qq = e >> 4, d4 = (e & 15) << 2;
        float4 v = *(const float4*)(Q + ((long)b_*NTOK + q0 + qq)*C + h*DH + d4);
        *(float4*)&Qs[qq*68 + d4] = v;
    }
    for (int e = tid; e < 256*16; e += 256) {
        int m = e >> 4, d4 = (e & 15) << 2;
        const float* base = KV + ((long)b_*M + m)*(2*C) + h*DH + d4;
        *(float4*)&Ks[m*64 + d4] = *(const float4*)base;
        *(float4*)&Vs[m*64 + d4] = *(const float4*)(base + C);
    }
    __syncthreads();

    const int q  = tid & 63;
    const int mg = tid >> 6;    // 0..3

    unsigned long long q2[32];
    #pragma unroll
    for (int d = 0; d < 16; d++) {
        float4 v = *(const float4*)&Qs[q*68 + d*4];
        q2[2*d]   = pk2(v.x, v.y);
        q2[2*d+1] = pk2(v.z, v.w);
    }
    for (int mi = 0; mi < 64; mi++) {
        int m = mg*64 + mi;
        const float4* kr = (const float4*)&Ks[m*64];
        unsigned long long a0 = 0ull, a1 = 0ull;
        #pragma unroll
        for (int dd = 0; dd < 16; dd++) {
            float4 kv4 = kr[dd];
            a0 = ffma2(pk2(kv4.x,kv4.y), q2[2*dd],   a0);
            a1 = ffma2(pk2(kv4.z,kv4.w), q2[2*dd+1], a1);
        }
        float x0,x1,y0,y1; upk2(a0,x0,x1); upk2(a1,y0,y1);
        S[q*257 + m] = (x0+x1+y0+y1) * 0.125f;
    }
    __syncthreads();

    float lmax = -1e30f;
    for (int mi = 0; mi < 64; mi++) lmax = fmaxf(lmax, S[q*257 + mg*64 + mi]);
    red[q*4 + mg] = lmax;
    __syncthreads();
    if (tid < 64)
        rowv[tid] = fmaxf(fmaxf(red[tid*4],red[tid*4+1]), fmaxf(red[tid*4+2],red[tid*4+3]));
    __syncthreads();
    float rm = rowv[q];
    float lsum = 0.f;
    for (int mi = 0; mi < 64; mi++) {
        int m = mg*64 + mi;
        float e = expf(S[q*257 + m] - rm);
        S[q*257 + m] = e;
        lsum += e;
    }
    red[q*4 + mg] = lsum;
    __syncthreads();
    if (tid < 64)
        rowv[tid] = 1.0f / (red[tid*4]+red[tid*4+1]+red[tid*4+2]+red[tid*4+3]);
    __syncthreads();

    const int dg = mg;
    unsigned long long o2[8];
    #pragma unroll
    for (int t = 0; t < 8; t++) o2[t] = 0ull;
    for (int m = 0; m < 256; m++) {
        float p = S[q*257 + m];
        unsigned long long pd = pk2(p, p);
        const float4* vr = (const float4*)&Vs[m*64 + dg*16];
        #pragma unroll
        for (int t = 0; t < 4; t++) {
            float4 v4 = vr[t];
            o2[2*t]   = ffma2(pk2(v4.x,v4.y), pd, o2[2*t]);
            o2[2*t+1] = ffma2(pk2(v4.z,v4.w), pd, o2[2*t+1]);
        }
    }
    float inv = rowv[q];
    float ov[16];
    #pragma unroll
    for (int t = 0; t < 8; t++) upk2(o2[t], ov[2*t], ov[2*t+1]);
    float* op = O + ((long)b_*NTOK + q0 + q)*C + h*DH + dg*16;
    #pragma unroll
    for (int dd = 0; dd < 16; dd += 4)
        *(float4*)(op + dd) = make_float4(ov[dd]*inv, ov[dd+1]*inv, ov[dd+2]*inv, ov[dd+3]*inv);
}

// ------------------------- judger row softmax -----------------------------
__global__ void rowsoftmax_kernel(float* __restrict__ S)
{
    const int row  = blockIdx.x * 8 + (threadIdx.x >> 5);
    const int lane = threadIdx.x & 31;
    float* p = S + (long)row*C + lane*4;
    float4 v = *(const float4*)p;
    float m = fmaxf(fmaxf(v.x,v.y), fmaxf(v.z,v.w));
    #pragma unroll
    for (int o = 16; o > 0; o >>= 1) m = fmaxf(m, __shfl_xor_sync(0xffffffffu, m, o));
    float4 e = make_float4(expf(v.x-m), expf(v.y-m), expf(v.z-m), expf(v.w-m));
    float s = e.x+e.y+e.z+e.w;
    s = warp_sum(s);
    float inv = 1.0f/s;
    e.x*=inv; e.y*=inv; e.z*=inv; e.w*=inv;
    *(float4*)p = e;
}

// ------------------------- elementwise a*s --------------------------------
__global__ void amul_kernel(const float* __restrict__ a,
                            const float* __restrict__ s,
                            float* __restrict__ d)
{
    long i = (long)blockIdx.x * 256 + threadIdx.x;
    float4 va = ((const float4*)a)[i];
    float4 vs = ((const float4*)s)[i];
    va.x*=vs.x; va.y*=vs.y; va.z*=vs.z; va.w*=vs.w;
    ((float4*)d)[i] = va;
}

// ------------------------- fused proj weight build ------------------------
// wf[o][0:128] = (proj_w @ out_w)[o], wf[o][128:256] = proj_w[o]
// bc[o] = proj_b[o] + dot(proj_w[o], out_b)
__global__ void wfuse_kernel(const float* __restrict__ projw,
                             const float* __restrict__ outw,
                             const float* __restrict__ outb,
                             const float* __restrict__ projb,
                             float* __restrict__ wf, float* __restrict__ bc)
{
    const int o = blockIdx.x, t = threadIdx.x;
    float s = 0.f;
    #pragma unroll 4
    for (int j = 0; j < C; j++) s += projw[o*C + j] * outw[j*C + t];
    wf[o*2*C + t]       = s;
    wf[o*2*C + C + t]   = projw[o*C + t];
    __shared__ float red[C];
    red[t] = projw[o*C + t] * outb[t];
    __syncthreads();
    for (int st = 64; st > 0; st >>= 1){
        if (t < st) red[t] += red[t + st];
        __syncthreads();
    }
    if (t == 0) bc[o] = projb[o] + red[0];
}

// ------------------------- constant noise projections ---------------------
__global__ void cknoise_kernel(const float* __restrict__ inw,
                               const float* __restrict__ kn,
                               const float* __restrict__ vn,
                               float* __restrict__ ck, float* __restrict__ cv)
{
    int t = threadIdx.x;
    if (t < 128) {
        const float* w = inw + (long)(C + t)*C;
        float s = 0.f;
        #pragma unroll 4
        for (int j = 0; j < C; j++) s += kn[j]*w[j];
        ck[t] = s;
    } else {
        int c = t - 128;
        const float* w = inw + (long)(2*C + c)*C;
        float s = 0.f;
        #pragma unroll 4
        for (int j = 0; j < C; j++) s += vn[j]*w[j];
        cv[c] = s;
    }
}

// ------------------------- per-token 2-key attention combine --------------
__global__ void combine_kernel(const float* __restrict__ qkv,
                               const float* __restrict__ kp1,
                               const float* __restrict__ vp1,
                               const float* __restrict__ ck,
                               const float* __restrict__ cv,
                               float* __restrict__ O)
{
    long idx = (long)blockIdx.x * 256 + threadIdx.x;
    long r = idx >> 3;
    int  h = (int)(idx & 7);
    const float* qp = qkv + r*384 + h*16;
    const float* k0 = qkv + r*384 + 128 + h*16;
    const float* v0 = qkv + r*384 + 256 + h*16;
    const float* k1 = kp1 + r*128 + h*16;
    const float* v1 = vp1 + r*128 + h*16;
    const float* ckh = ck + h*16;
    const float* cvh = cv + h*16;
    float s0 = 0.f, s1 = 0.f;
    #pragma unroll
    for (int i = 0; i < 16; i++) {
        float qv = qp[i];
        s0 += qv * (k0[i] + ckh[i]);
        s1 += qv * k1[i];
    }
    s0 *= 0.25f; s1 *= 0.25f;
    float mx = fmaxf(s0, s1);
    float e0 = expf(s0-mx), e1 = expf(s1-mx);
    float inv = 1.0f/(e0+e1);
    float a0 = e0*inv, a1 = e1*inv;
    float* op = O + r*128 + h*16;
    #pragma unroll
    for (int i = 0; i < 16; i++)
        op[i] = a0*(v0[i] + cvh[i]) + a1*v1[i];
}

// ------------------------- host driver ------------------------------------
static void run_mma(const float* A, const float* A2,
                    const float* W, int ldw,
                    const float* bias, float* D,
                    int Ncols, int Ktot, int flags)
{
    dim3 g(NT/256, Ncols/128);
    mma_gemm<<<g, 512, MMA_SMEM_BYTES>>>(A, A2, W, ldw, bias, D, Ncols, Ktot, flags);
}

extern "C" void kernel_launch(void* const* d_in, const int* in_sizes, int n_in,
                              void* d_out, int out_size)
{
    const float* x0       = (const float*)d_in[0];
    const float* x1       = (const float*)d_in[1];
    const float* Wq       = (const float*)d_in[2];
    const float* bq       = (const float*)d_in[3];
    const float* Wkv      = (const float*)d_in[4];
    const float* bkv      = (const float*)d_in[5];
    const float* sr_w     = (const float*)d_in[6];
    const float* sr_b     = (const float*)d_in[7];
    const float* ln_g[2]  = {(const float*)d_in[8],  (const float*)d_in[10]};
    const float* ln_b[2]  = {(const float*)d_in[9],  (const float*)d_in[11]};
    const float* in_w[2]  = {(const float*)d_in[12], (const float*)d_in[16]};
    const float* in_b[2]  = {(const float*)d_in[13], (const float*)d_in[17]};
    const float* out_w[2] = {(const float*)d_in[14], (const float*)d_in[18]};
    const float* out_b[2] = {(const float*)d_in[15], (const float*)d_in[19]};
    const float* rj_w1    = (const float*)d_in[20];
    const float* rj_b1    = (const float*)d_in[21];
    const float* rj_w2    = (const float*)d_in[22];
    const float* rj_b2    = (const float*)d_in[23];
    const float* k_noise  = (const float*)d_in[24];
    const float* v_noise  = (const float*)d_in[25];
    const float* proj_w   = (const float*)d_in[26];
    const float* proj_b   = (const float*)d_in[27];

    float *xa0, *xa1, *q, *h, *s, *qkv, *kp1, *vp1, *o, *cpart, *xi, *kv, *ck, *cv, *wf, *bc;
    cudaGetSymbolAddress((void**)&xa0,   g_xa0);
    cudaGetSymbolAddress((void**)&xa1,   g_xa1);
    cudaGetSymbolAddress((void**)&q,     g_q);
    cudaGetSymbolAddress((void**)&h,     g_h);
    cudaGetSymbolAddress((void**)&s,     g_s);
    cudaGetSymbolAddress((void**)&qkv,   g_qkv);
    cudaGetSymbolAddress((void**)&kp1,   g_kp1);
    cudaGetSymbolAddress((void**)&vp1,   g_vp1);
    cudaGetSymbolAddress((void**)&o,     g_o);
    cudaGetSymbolAddress((void**)&cpart, g_cpart);
    cudaGetSymbolAddress((void**)&xi,    g_xi);
    cudaGetSymbolAddress((void**)&kv,    g_kv);
    cudaGetSymbolAddress((void**)&ck,    g_ck);
    cudaGetSymbolAddress((void**)&cv,    g_cv);
    cudaGetSymbolAddress((void**)&wf,    g_wf);
    cudaGetSymbolAddress((void**)&bc,    g_bc);

    const int attn_smem = ATTN_SMEM_FLOATS * 4;
    cudaFuncSetAttribute(attn_kernel, cudaFuncAttributeMaxDynamicSharedMemorySize, attn_smem);
    cudaFuncSetAttribute(mma_gemm, cudaFuncAttributeMaxDynamicSharedMemorySize, MMA_SMEM_BYTES);

    float* xa[2] = {xa0, xa1};
    const float* xin[2] = {x0, x1};

    // ---- stage A: SR attention per image ----
    for (int im = 0; im < 2; im++) {
        run_mma(xin[im], nullptr, Wq, C, bq, q, C, C, 0);
        conv_kernel<<<dim3(16, 2, KSPLIT), 256>>>(xin[im], sr_w, cpart);
        conv_reduce_kernel<<<(BM*C + 255)/256, 256>>>(cpart, sr_b, xi);
        ln_kernel<<<BM, 128>>>(xi, ln_g[im], ln_b[im]);
        gemm_kernel<<<dim3(BM/64, (2*C)/64), 256>>>(xi, Wkv, C, bkv, kv, 2*C, C);
        attn_kernel<<<dim3(NTOK/64, HEADS, BB), 256, attn_smem>>>(q, kv, xa[im]);
    }

    // ---- stage B: per direction ----
    for (int d = 0; d < 2; d++) {
        const float* a  = xa[d];
        const float* bb = xa[1-d];
        float* dst = (float*)d_out + (size_t)d * NT * C;

        // judger fused K=256: h = gelu(concat(a,bb) @ rj_w1^T + rj_b1)
        run_mma(a, bb, rj_w1, 2*C, rj_b1, h, C, 2*C, F_GELU);
        run_mma(h, nullptr, rj_w2, C, rj_b2, s, C, C, 0);
        rowsoftmax_kernel<<<NT/8, 256>>>(s);

        cknoise_kernel<<<1, 256>>>(in_w[d], k_noise + d*C, v_noise + d*C, ck, cv);
        amul_kernel<<<NT*C/4/256, 256>>>(a, s, h);   // h := a*s (h free now)

        run_mma(a,  nullptr, in_w[d],         C, in_b[d],       qkv, 3*C, C, 0);
        run_mma(h,  nullptr, in_w[d] + C*C,   C, in_b[d] + C,   kp1, C,   C, 0);
        run_mma(bb, nullptr, in_w[d] + 2*C*C, C, in_b[d] + 2*C, vp1, C,   C, 0);

        combine_kernel<<<(long)NT*XH/256, 256>>>(qkv, kp1, vp1, ck, cv, o);

        // fused: dst = [o | a] @ [proj_w@out_w | proj_w]^T + (proj_b + proj_w@out_b)
        wfuse_kernel<<<C, C>>>(proj_w, out_w[d], out_b[d], proj_b, wf, bc);
        run_mma(o, a, wf, 2*C, bc, dst, C, 2*C, 0);
    }
}

// round 7
// speedup vs baseline: 1.8958x; 1.0929x over previous
#include <cuda_runtime.h>
#include <cuda_fp16.h>
#include <math.h>
#include <cstdint>

#define BB 4
#define NTOK 16384
#define C 128
#define NT (BB*NTOK)
#define M 256
#define BM (BB*M)
#define HEADS 2
#define DH 64
#define XH 8
#define KCONV 8192
#define KSPLIT 8

#define F_GELU  2

// ------------------------- scratch ---------------------------------------
__device__ __align__(256) float g_xa0[NT*C];
__device__ __align__(256) float g_xa1[NT*C];
__device__ __align__(256) float g_q  [NT*C];
__device__ __align__(256) float g_h  [NT*C];
__device__ __align__(256) float g_s  [NT*C];
__device__ __align__(256) float g_qkv[(size_t)NT*3*C];
__device__ __align__(256) float g_kp1[NT*C];
__device__ __align__(256) float g_vp1[NT*C];
__device__ __align__(256) float g_o  [NT*C];
__device__ __align__(256) float g_cpart[KSPLIT*BM*C];
__device__ __align__(256) float g_xi [BM*C];
__device__ __align__(256) float g_kv [BM*2*C];
__device__ __align__(256) float g_ck [C];
__device__ __align__(256) float g_cv [C];
__device__ __align__(256) float g_wf [C*2*C];
__device__ __align__(256) float g_bc [C];

// ------------------------- helpers ---------------------------------------
__device__ __forceinline__ float gelu_exact(float v){
    return 0.5f * v * (1.0f + erff(v * 0.70710678118654752f));
}
__device__ __forceinline__ float warp_sum(float v){
    #pragma unroll
    for (int o = 16; o > 0; o >>= 1) v += __shfl_xor_sync(0xffffffffu, v, o);
    return v;
}
__device__ __forceinline__ unsigned long long pk2(float lo, float hi){
    unsigned long long r;
    asm("mov.b64 %0, {%1,%2};" : "=l"(r) : "f"(lo), "f"(hi));
    return r;
}
__device__ __forceinline__ void upk2(unsigned long long v, float& lo, float& hi){
    asm("mov.b64 {%0,%1}, %2;" : "=f"(lo), "=f"(hi) : "l"(v));
}
__device__ __forceinline__ unsigned long long ffma2(unsigned long long a,
        unsigned long long b, unsigned long long c){
    unsigned long long r;
    asm("fma.rn.f32x2 %0, %1, %2, %3;" : "=l"(r) : "l"(a), "l"(b), "l"(c));
    return r;
}
__device__ __forceinline__ void mma16(float* c, const unsigned* a, const unsigned* b){
    asm("mma.sync.aligned.m16n8k16.row.col.f32.f16.f16.f32 "
        "{%0,%1,%2,%3}, {%4,%5,%6,%7}, {%8,%9}, {%0,%1,%2,%3};"
        : "+f"(c[0]),"+f"(c[1]),"+f"(c[2]),"+f"(c[3])
        : "r"(a[0]),"r"(a[1]),"r"(a[2]),"r"(a[3]), "r"(b[0]),"r"(b[1]));
}
__device__ __forceinline__ unsigned h2pack(float lo, float hi){
    __half2 h = __floats2half2_rn(lo, hi);
    return *(unsigned*)&h;
}

// ===================== fp16 tensor-core GEMM ==============================
#define AST 40
#define BST 40
#define MMA_SMEM_BYTES ((2*256*AST + 2*128*BST)*2)

__global__ void __launch_bounds__(512, 1) mma_gemm(
    const float* __restrict__ A, const float* __restrict__ A2,
    const float* __restrict__ W, int ldw,
    const float* __restrict__ bias,
    float* __restrict__ D, int Ncols, int Ktot, int flags)
{
    extern __shared__ __half smh[];
    __half* smA = smh;
    __half* smB = smh + 2*256*AST;

    const int tid = threadIdx.x;
    const int lane = tid & 31, wid = tid >> 5;
    const int wm = wid >> 2, wn = wid & 3;
    const long row0 = (long)blockIdx.x * 256;
    const int  col0 = blockIdx.y * 128;
    const int lrow = tid >> 3;
    const int lcol = (tid & 7) << 2;

    float acc[4][4][4];
    #pragma unroll
    for (int i=0;i<4;i++)
        #pragma unroll
        for (int j=0;j<4;j++)
            #pragma unroll
            for (int t=0;t<4;t++) acc[i][j][t]=0.f;

    const int nch = Ktot >> 5;
    float4 areg[4], breg[2];

    auto gload = [&](int ch){
        const int kk = ch*32;
        const float* Asrc = (kk < 128) ? A : A2;
        const int kc = kk & 127;
        #pragma unroll
        for (int t=0;t<4;t++){
            int row = lrow + t*64;
            areg[t] = *(const float4*)(Asrc + (row0+row)*128 + kc + lcol);
        }
        #pragma unroll
        for (int t=0;t<2;t++){
            int row = lrow + t*64;
            breg[t] = *(const float4*)(W + (long)(col0+row)*ldw + kk + lcol);
        }
    };
    auto sstore = [&](int ch){
        __half* Ab = smA + (ch&1)*(256*AST);
        __half* Bb = smB + (ch&1)*(128*BST);
        #pragma unroll
        for (int t=0;t<4;t++){
            int row = lrow + t*64;
            uint2 u = make_uint2(h2pack(areg[t].x, areg[t].y),
                                 h2pack(areg[t].z, areg[t].w));
            *(uint2*)(Ab + row*AST + lcol) = u;
        }
        #pragma unroll
        for (int t=0;t<2;t++){
            int row = lrow + t*64;
            uint2 u = make_uint2(h2pack(breg[t].x, breg[t].y),
                                 h2pack(breg[t].z, breg[t].w));
            *(uint2*)(Bb + row*BST + lcol) = u;
        }
    };

    gload(0); sstore(0);
    __syncthreads();

    for (int ch = 0; ch < nch; ch++){
        if (ch+1 < nch) gload(ch+1);

        const __half* Ab = smA + (ch&1)*(256*AST);
        const __half* Bb = smB + (ch&1)*(128*BST);
        #pragma unroll
        for (int kb=0;kb<2;kb++){
            unsigned af[4][4], bf[4][2];
            #pragma unroll
            for (int i=0;i<4;i++){
                const __half* p = Ab + (wm*64 + i*16 + (lane>>2))*AST
                                + kb*16 + ((lane&3)<<1);
                af[i][0] = *(const unsigned*)p;
                af[i][1] = *(const unsigned*)(p + 8*AST);
                af[i][2] = *(const unsigned*)(p + 8);
                af[i][3] = *(const unsigned*)(p + 8*AST + 8);
            }
            #pragma unroll
            for (int j=0;j<4;j++){
                const __half* p = Bb + (wn*32 + j*8 + (lane>>2))*BST
                                + kb*16 + ((lane&3)<<1);
                bf[j][0] = *(const unsigned*)p;
                bf[j][1] = *(const unsigned*)(p + 8);
            }
            #pragma unroll
            for (int i=0;i<4;i++)
                #pragma unroll
                for (int j=0;j<4;j++)
                    mma16(acc[i][j], af[i], bf[j]);
        }
        __syncthreads();
        if (ch+1 < nch){
            sstore(ch+1);
            __syncthreads();
        }
    }

    #pragma unroll
    for (int i=0;i<4;i++){
        long r = row0 + wm*64 + i*16 + (lane>>2);
        #pragma unroll
        for (int j=0;j<4;j++){
            int cc = col0 + wn*32 + j*8 + ((lane&3)<<1);
            float2 v0 = make_float2(acc[i][j][0], acc[i][j][1]);
            float2 v1 = make_float2(acc[i][j][2], acc[i][j][3]);
            if (bias){
                float2 b2 = *(const float2*)(bias + cc);
                v0.x+=b2.x; v0.y+=b2.y; v1.x+=b2.x; v1.y+=b2.y;
            }
            if (flags & F_GELU){
                v0.x=gelu_exact(v0.x); v0.y=gelu_exact(v0.y);
                v1.x=gelu_exact(v1.x); v1.y=gelu_exact(v1.y);
            }
            *(float2*)(D + r*(long)Ncols + cc) = v0;
            *(float2*)(D + (r+8)*(long)Ncols + cc) = v1;
        }
    }
}

// ------------------------- scalar GEMM (tiny kv proj only) ----------------
__global__ void __launch_bounds__(256) gemm_kernel(
    const float* __restrict__ A,
    const float* __restrict__ W, int ldw,
    const float* __restrict__ bias,
    float* __restrict__ D, int Ncols, int K)
{
    __shared__ float As[16][64];
    __shared__ float Ws[16][64];
    const int tid = threadIdx.x;
    const int tx = tid & 15, ty = tid >> 4;
    const long row0 = (long)blockIdx.x * 64;
    const int  col0 = blockIdx.y * 64;
    const int lr = tid >> 2;
    const int lk = (tid & 3) << 2;

    const float* Arow  = A + (row0 + lr) * (long)K + lk;
    const float* Wrow  = W + (long)(col0 + lr) * ldw + lk;

    float acc[4][4] = {};
    for (int kk = 0; kk < K; kk += 16) {
        float4 av = *(const float4*)(Arow + kk);
        float4 wv = *(const float4*)(Wrow + kk);
        As[lk+0][lr]=av.x; As[lk+1][lr]=av.y; As[lk+2][lr]=av.z; As[lk+3][lr]=av.w;
        Ws[lk+0][lr]=wv.x; Ws[lk+1][lr]=wv.y; Ws[lk+2][lr]=wv.z; Ws[lk+3][lr]=wv.w;
        __syncthreads();
        #pragma unroll
        for (int k = 0; k < 16; k++) {
            float ar[4], br[4];
            *(float4*)ar = *(const float4*)&As[k][ty<<2];
            *(float4*)br = *(const float4*)&Ws[k][tx<<2];
            #pragma unroll
            for (int i = 0; i < 4; i++)
                #pragma unroll
                for (int j = 0; j < 4; j++)
                    acc[i][j] += ar[i] * br[j];
        }
        __syncthreads();
    }
    #pragma unroll
    for (int i = 0; i < 4; i++) {
        long r = row0 + (ty<<2) + i;
        int  c = col0 + (tx<<2);
        float4 v = make_float4(acc[i][0],acc[i][1],acc[i][2],acc[i][3]);
        v.x+=bias[c]; v.y+=bias[c+1]; v.z+=bias[c+2]; v.w+=bias[c+3];
        *(float4*)(D + r * (long)Ncols + c) = v;
    }
}

// ------------------------- patch conv as split-K implicit GEMM -----------
__global__ void __launch_bounds__(256) conv_kernel(
    const float* __restrict__ x, const float* __restrict__ srw,
    float* __restrict__ part)
{
    __shared__ float As[16][64];
    __shared__ float Ws[16][64];
    const int tid = threadIdx.x;
    const int tx = tid & 15, ty = tid >> 4;
    const int row0 = blockIdx.x * 64;
    const int col0 = blockIdx.y * 64;
    const int kz   = blockIdx.z;
    const int lr = tid >> 2;
    const int lk = (tid & 3) << 2;

    const int r  = row0 + lr;
    const int b_ = r >> 8, p = r & 255, ph = p >> 4, pw = p & 15;
    const float* Wrow = srw + (long)(col0 + lr) * KCONV + kz * 1024 + lk;

    float acc[4][4] = {};
    for (int kk = 0; kk < 1024; kk += 16) {
        const int kg  = kz*1024 + kk + lk;
        const int i   = kg >> 6;
        const int rem = kg & 63;
        const int kh  = rem >> 3, kw = rem & 7;
        const float* xp = x + ((long)b_*NTOK + (ph*8+kh)*128 + (pw*8+kw)) * C + i;
        As[lk+0][lr]=xp[0]; As[lk+1][lr]=xp[C]; As[lk+2][lr]=xp[2*C]; As[lk+3][lr]=xp[3*C];
        float4 wv = *(const float4*)(Wrow + kk);
        Ws[lk+0][lr]=wv.x; Ws[lk+1][lr]=wv.y; Ws[lk+2][lr]=wv.z; Ws[lk+3][lr]=wv.w;
        __syncthreads();
        #pragma unroll
        for (int k = 0; k < 16; k++) {
            float ar[4], br[4];
            *(float4*)ar = *(const float4*)&As[k][ty<<2];
            *(float4*)br = *(const float4*)&Ws[k][tx<<2];
            #pragma unroll
            for (int i2 = 0; i2 < 4; i2++)
                #pragma unroll
                for (int j = 0; j < 4; j++)
                    acc[i2][j] += ar[i2] * br[j];
        }
        __syncthreads();
    }
    #pragma unroll
    for (int i2 = 0; i2 < 4; i2++) {
        int rr = row0 + (ty<<2) + i2;
        float4 v = make_float4(acc[i2][0],acc[i2][1],acc[i2][2],acc[i2][3]);
        *(float4*)(part + ((long)kz*BM + rr)*C + col0 + (tx<<2)) = v;
    }
}

__global__ void conv_reduce_kernel(const float* __restrict__ part,
                                   const float* __restrict__ srb,
                                   float* __restrict__ xi)
{
    int idx = blockIdx.x * 256 + threadIdx.x;
    if (idx < BM*C) {
        float s = srb[idx & (C-1)];
        #pragma unroll
        for (int z = 0; z < KSPLIT; z++) s += part[(long)z*BM*C + idx];
        xi[idx] = s;
    }
}

// ------------------------- layernorm --------------------------------------
__global__ void ln_kernel(float* __restrict__ xi, const float* __restrict__ g,
                          const float* __restrict__ b)
{
    const int row = blockIdx.x, t = threadIdx.x;
    __shared__ float red[4];
    __shared__ float mv[2];
    float v = xi[(long)row*C + t];
    float s = warp_sum(v);
    if ((t & 31) == 0) red[t >> 5] = s;
    __syncthreads();
    if (t == 0) mv[0] = (red[0]+red[1]+red[2]+red[3]) * (1.0f/C);
    __syncthreads();
    float d = v - mv[0];
    float s2 = warp_sum(d*d);
    if ((t & 31) == 0) red[t >> 5] = s2;
    __syncthreads();
    if (t == 0) mv[1] = (red[0]+red[1]+red[2]+red[3]) * (1.0f/C);
    __syncthreads();
    xi[(long)row*C + t] = d * rsqrtf(mv[1] + 1e-5f) * g[t] + b[t];
}

// ------------------------- SR attention -----------------------------------
#define ATTN_SMEM_FLOATS (64*68 + 256*64 + 256*64 + 64*257 + 256 + 64)
__global__ void __launch_bounds__(256) attn_kernel(
    const float* __restrict__ Q, const float* __restrict__ KV,
    float* __restrict__ O)
{
    extern __shared__ float sm[];
    float* Qs   = sm;
    float* Ks   = Qs + 64*68;
    float* Vs   = Ks + 256*64;
    float* S    = Vs + 256*64;
    float* red  = S  + 64*257;
    float* rowv = red + 256;

    const int tid = threadIdx.x;
    const int h  = blockIdx.y, b_ = blockIdx.z;
    const int q0 = blockIdx.x * 64;

    for (int e = tid; e < 64*16; e += 256) {
        int qq = e >> 4, d4 = (e & 15) << 2;
        float4 v = *(const float4*)(Q + ((long)b_*NTOK + q0 + qq)*C + h*DH + d4);
        *(float4*)&Qs[qq*68 + d4] = v;
    }
    for (int e = tid; e < 256*16; e += 256) {
        int m = e >> 4, d4 = (e & 15) << 2;
        const float* base = KV + ((long)b_*M + m)*(2*C) + h*DH + d4;
        *(float4*)&Ks[m*64 + d4] = *(const float4*)base;
        *(float4*)&Vs[m*64 + d4] = *(const float4*)(base + C);
    }
    __syncthreads();

    const int q  = tid & 63;
    const int mg = tid >> 6;

    unsigned long long q2[32];
    #pragma unroll
    for (int d = 0; d < 16; d++) {
        float4 v = *(const float4*)&Qs[q*68 + d*4];
        q2[2*d]   = pk2(v.x, v.y);
        q2[2*d+1] = pk2(v.z, v.w);
    }
    for (int mi = 0; mi < 64; mi++) {
        int m = mg*64 + mi;
        const float4* kr = (const float4*)&Ks[m*64];
        unsigned long long a0 = 0ull, a1 = 0ull;
        #pragma unroll
        for (int dd = 0; dd < 16; dd++) {
            float4 kv4 = kr[dd];
            a0 = ffma2(pk2(kv4.x,kv4.y), q2[2*dd],   a0);
            a1 = ffma2(pk2(kv4.z,kv4.w), q2[2*dd+1], a1);
        }
        float x0,x1,y0,y1; upk2(a0,x0,x1); upk2(a1,y0,y1);
        S[q*257 + m] = (x0+x1+y0+y1) * 0.125f;
    }
    __syncthreads();

    float lmax = -1e30f;
    for (int mi = 0; mi < 64; mi++) lmax = fmaxf(lmax, S[q*257 + mg*64 + mi]);
    red[q*4 + mg] = lmax;
    __syncthreads();
    if (tid < 64)
        rowv[tid] = fmaxf(fmaxf(red[tid*4],red[tid*4+1]), fmaxf(red[tid*4+2],red[tid*4+3]));
    __syncthreads();
    float rm = rowv[q];
    float lsum = 0.f;
    for (int mi = 0; mi < 64; mi++) {
        int m = mg*64 + mi;
        float e = expf(S[q*257 + m] - rm);
        S[q*257 + m] = e;
        lsum += e;
    }
    red[q*4 + mg] = lsum;
    __syncthreads();
    if (tid < 64)
        rowv[tid] = 1.0f / (red[tid*4]+red[tid*4+1]+red[tid*4+2]+red[tid*4+3]);
    __syncthreads();

    const int dg = mg;
    unsigned long long o2[8];
    #pragma unroll
    for (int t = 0; t < 8; t++) o2[t] = 0ull;
    for (int m = 0; m < 256; m++) {
        float p = S[q*257 + m];
        unsigned long long pd = pk2(p, p);
        const float4* vr = (const float4*)&Vs[m*64 + dg*16];
        #pragma unroll
        for (int t = 0; t < 4; t++) {
            float4 v4 = vr[t];
            o2[2*t]   = ffma2(pk2(v4.x,v4.y), pd, o2[2*t]);
            o2[2*t+1] = ffma2(pk2(v4.z,v4.w), pd, o2[2*t+1]);
        }
    }
    float inv = rowv[q];
    float ov[16];
    #pragma unroll
    for (int t = 0; t < 8; t++) upk2(o2[t], ov[2*t], ov[2*t+1]);
    float* op = O + ((long)b_*NTOK + q0 + q)*C + h*DH + dg*16;
    #pragma unroll
    for (int dd = 0; dd < 16; dd += 4)
        *(float4*)(op + dd) = make_float4(ov[dd]*inv, ov[dd+1]*inv, ov[dd+2]*inv, ov[dd+3]*inv);
}

// ------------------------- judger row softmax -----------------------------
__global__ void rowsoftmax_kernel(float* __restrict__ S)
{
    const int row  = blockIdx.x * 8 + (threadIdx.x >> 5);
    const int lane = threadIdx.x & 31;
    float* p = S + (long)row*C + lane*4;
    float4 v = *(const float4*)p;
    float m = fmaxf(fmaxf(v.x,v.y), fmaxf(v.z,v.w));
    #pragma unroll
    for (int o = 16; o > 0; o >>= 1) m = fmaxf(m, __shfl_xor_sync(0xffffffffu, m, o));
    float4 e = make_float4(expf(v.x-m), expf(v.y-m), expf(v.z-m), expf(v.w-m));
    float s = e.x+e.y+e.z+e.w;
    s = warp_sum(s);
    float inv = 1.0f/s;
    e.x*=inv; e.y*=inv; e.z*=inv; e.w*=inv;
    *(float4*)p = e;
}

// ------------------------- elementwise a*s --------------------------------
__global__ void amul_kernel(const float* __restrict__ a,
                            const float* __restrict__ s,
                            float* __restrict__ d)
{
    long i = (long)blockIdx.x * 256 + threadIdx.x;
    float4 va = ((const float4*)a)[i];
    float4 vs = ((const float4*)s)[i];
    va.x*=vs.x; va.y*=vs.y; va.z*=vs.z; va.w*=vs.w;
    ((float4*)d)[i] = va;
}

// ------------------------- fused proj weight build ------------------------
__global__ void wfuse_kernel(const float* __restrict__ projw,
                             const float* __restrict__ outw,
                             const float* __restrict__ outb,
                             const float* __restrict__ projb,
                             float* __restrict__ wf, float* __restrict__ bc)
{
    const int o = blockIdx.x, t = threadIdx.x;
    float s = 0.f;
    #pragma unroll 4
    for (int j = 0; j < C; j++) s += projw[o*C + j] * outw[j*C + t];
    wf[o*2*C + t]       = s;
    wf[o*2*C + C + t]   = projw[o*C + t];
    __shared__ float red[C];
    red[t] = projw[o*C + t] * outb[t];
    __syncthreads();
    for (int st = 64; st > 0; st >>= 1){
        if (t < st) red[t] += red[t + st];
        __syncthreads();
    }
    if (t == 0) bc[o] = projb[o] + red[0];
}

// ------------------------- constant noise projections ---------------------
__global__ void cknoise_kernel(const float* __restrict__ inw,
                               const float* __restrict__ kn,
                               const float* __restrict__ vn,
                               float* __restrict__ ck, float* __restrict__ cv)
{
    int t = threadIdx.x;
    if (t < 128) {
        const float* w = inw + (long)(C + t)*C;
        float s = 0.f;
        #pragma unroll 4
        for (int j = 0; j < C; j++) s += kn[j]*w[j];
        ck[t] = s;
    } else {
        int c = t - 128;
        const float* w = inw + (long)(2*C + c)*C;
        float s = 0.f;
        #pragma unroll 4
        for (int j = 0; j < C; j++) s += vn[j]*w[j];
        cv[c] = s;
    }
}

// ------------------------- 2-key attention combine ------------------------
__global__ void combine_kernel(const float* __restrict__ qkv,
                               const float* __restrict__ kp1,
                               const float* __restrict__ vp1,
                               const float* __restrict__ ck,
                               const float* __restrict__ cv,
                               float* __restrict__ O)
{
    long idx = (long)blockIdx.x * 256 + threadIdx.x;
    long r = idx >> 3;
    int  h = (int)(idx & 7);
    const float* qp = qkv + r*384 + h*16;
    const float* k0 = qkv + r*384 + 128 + h*16;
    const float* v0 = qkv + r*384 + 256 + h*16;
    const float* k1 = kp1 + r*128 + h*16;
    const float* v1 = vp1 + r*128 + h*16;
    const float* ckh = ck + h*16;
    const float* cvh = cv + h*16;
    float s0 = 0.f, s1 = 0.f;
    #pragma unroll
    for (int i = 0; i < 16; i++) {
        float qv = qp[i];
        s0 += qv * (k0[i] + ckh[i]);
        s1 += qv * k1[i];
    }
    s0 *= 0.25f; s1 *= 0.25f;
    float mx = fmaxf(s0, s1);
    float e0 = expf(s0-mx), e1 = expf(s1-mx);
    float inv = 1.0f/(e0+e1);
    float a0 = e0*inv, a1 = e1*inv;
    float* op = O + r*128 + h*16;
    #pragma unroll
    for (int i = 0; i < 16; i++)
        op[i] = a0*(v0[i] + cvh[i]) + a1*v1[i];
}

// ------------------------- host driver ------------------------------------
static void run_mma(const float* A, const float* A2,
                    const float* W, int ldw,
                    const float* bias, float* D,
                    int Ncols, int Ktot, int flags)
{
    dim3 g(NT/256, Ncols/128);
    mma_gemm<<<g, 512, MMA_SMEM_BYTES>>>(A, A2, W, ldw, bias, D, Ncols, Ktot, flags);
}

extern "C" void kernel_launch(void* const* d_in, const int* in_sizes, int n_in,
                              void* d_out, int out_size)
{
    const float* x0       = (const float*)d_in[0];
    const float* x1       = (const float*)d_in[1];
    const float* Wq       = (const float*)d_in[2];
    const float* bq       = (const float*)d_in[3];
    const float* Wkv      = (const float*)d_in[4];
    const float* bkv      = (const float*)d_in[5];
    const float* sr_w     = (const float*)d_in[6];
    const float* sr_b     = (const float*)d_in[7];
    const float* ln_g[2]  = {(const float*)d_in[8],  (const float*)d_in[10]};
    const float* ln_b[2]  = {(const float*)d_in[9],  (const float*)d_in[11]};
    const float* in_w[2]  = {(const float*)d_in[12], (const float*)d_in[16]};
    const float* in_b[2]  = {(const float*)d_in[13], (const float*)d_in[17]};
    const float* out_w[2] = {(const float*)d_in[14], (const float*)d_in[18]};
    const float* out_b[2] = {(const float*)d_in[15], (const float*)d_in[19]};
    const float* rj_w1    = (const float*)d_in[20];
    const float* rj_b1    = (const float*)d_in[21];
    const float* rj_w2    = (const float*)d_in[22];
    const float* rj_b2    = (const float*)d_in[23];
    const float* k_noise  = (const float*)d_in[24];
    const float* v_noise  = (const float*)d_in[25];
    const float* proj_w   = (const float*)d_in[26];
    const float* proj_b   = (const float*)d_in[27];

    float *xa0, *xa1, *q, *h, *s, *qkv, *kp1, *vp1, *o, *cpart, *xi, *kv, *ck, *cv, *wf, *bc;
    cudaGetSymbolAddress((void**)&xa0,   g_xa0);
    cudaGetSymbolAddress((void**)&xa1,   g_xa1);
    cudaGetSymbolAddress((void**)&q,     g_q);
    cudaGetSymbolAddress((void**)&h,     g_h);
    cudaGetSymbolAddress((void**)&s,     g_s);
    cudaGetSymbolAddress((void**)&qkv,   g_qkv);
    cudaGetSymbolAddress((void**)&kp1,   g_kp1);
    cudaGetSymbolAddress((void**)&vp1,   g_vp1);
    cudaGetSymbolAddress((void**)&o,     g_o);
    cudaGetSymbolAddress((void**)&cpart, g_cpart);
    cudaGetSymbolAddress((void**)&xi,    g_xi);
    cudaGetSymbolAddress((void**)&kv,    g_kv);
    cudaGetSymbolAddress((void**)&ck,    g_ck);
    cudaGetSymbolAddress((void**)&cv,    g_cv);
    cudaGetSymbolAddress((void**)&wf,    g_wf);
    cudaGetSymbolAddress((void**)&bc,    g_bc);

    const int attn_smem = ATTN_SMEM_FLOATS * 4;
    cudaFuncSetAttribute(attn_kernel, cudaFuncAttributeMaxDynamicSharedMemorySize, attn_smem);
    cudaFuncSetAttribute(mma_gemm, cudaFuncAttributeMaxDynamicSharedMemorySize, MMA_SMEM_BYTES);

    float* xa[2] = {xa0, xa1};
    const float* xin[2] = {x0, x1};

    // ---- stage A ----
    for (int im = 0; im < 2; im++) {
        run_mma(xin[im], nullptr, Wq, C, bq, q, C, C, 0);
        conv_kernel<<<dim3(16, 2, KSPLIT), 256>>>(xin[im], sr_w, cpart);
        conv_reduce_kernel<<<(BM*C + 255)/256, 256>>>(cpart, sr_b, xi);
        ln_kernel<<<BM, 128>>>(xi, ln_g[im], ln_b[im]);
        gemm_kernel<<<dim3(BM/64, (2*C)/64), 256>>>(xi, Wkv, C, bkv, kv, 2*C, C);
        attn_kernel<<<dim3(NTOK/64, HEADS, BB), 256, attn_smem>>>(q, kv, xa[im]);
    }

    // ---- stage B ----
    for (int d = 0; d < 2; d++) {
        const float* a  = xa[d];
        const float* bb = xa[1-d];
        float* dst = (float*)d_out + (size_t)d * NT * C;

        run_mma(a, bb, rj_w1, 2*C, rj_b1, h, C, 2*C, F_GELU);
        run_mma(h, nullptr, rj_w2, C, rj_b2, s, C, C, 0);
        rowsoftmax_kernel<<<NT/8, 256>>>(s);

        cknoise_kernel<<<1, 256>>>(in_w[d], k_noise + d*C, v_noise + d*C, ck, cv);
        amul_kernel<<<NT*C/4/256, 256>>>(a, s, h);   // h := a*s

        run_mma(a,  nullptr, in_w[d],         C, in_b[d],       qkv, 3*C, C, 0);
        run_mma(h,  nullptr, in_w[d] + C*C,   C, in_b[d] + C,   kp1, C,   C, 0);
        run_mma(bb, nullptr, in_w[d] + 2*C*C, C, in_b[d] + 2*C, vp1, C,   C, 0);

        combine_kernel<<<(long)NT*XH/256, 256>>>(qkv, kp1, vp1, ck, cv, o);

        wfuse_kernel<<<C, C>>>(proj_w, out_w[d], out_b[d], proj_b, wf, bc);
        run_mma(o, a, wf, 2*C, bc, dst, C, 2*C, 0);
    }
}

// round 8
// speedup vs baseline: 2.2344x; 1.1786x over previous
#include <cuda_runtime.h>
#include <cuda_fp16.h>
#include <math.h>
#include <cstdint>

#define BB 4
#define NTOK 16384
#define C 128
#define NT (BB*NTOK)
#define M 256
#define BM (BB*M)
#define HEADS 2
#define DH 64
#define XH 8
#define KCONV 8192
#define KSPLIT 8

#define F_GELU  2

// ------------------------- scratch ---------------------------------------
__device__ __align__(256) __half g_xh  [NT*C];
__device__ __align__(256) __half g_xim [(size_t)BM*KCONV];
__device__ __align__(256) __half g_xah0[NT*C];
__device__ __align__(256) __half g_xah1[NT*C];
__device__ __align__(256) __half g_hh  [NT*C];
__device__ __align__(256) __half g_oh  [NT*C];
__device__ __align__(256) __half g_wqh [C*C];
__device__ __align__(256) __half g_rj1h[2*C*C];
__device__ __align__(256) __half g_rj2h[C*C];
__device__ __align__(256) __half g_inwh0[3*C*C];
__device__ __align__(256) __half g_inwh1[3*C*C];
__device__ __align__(256) __half g_wfh [2*C*C];
__device__ __align__(256) __half g_wim [(size_t)C*KCONV];

__device__ __align__(256) float g_q  [NT*C];
__device__ __align__(256) float g_s  [NT*C];
__device__ __align__(256) float g_qkv[(size_t)NT*3*C];
__device__ __align__(256) float g_kp1[NT*C];
__device__ __align__(256) float g_vp1[NT*C];
__device__ __align__(256) float g_cpart[KSPLIT*BM*C];
__device__ __align__(256) float g_xi [BM*C];
__device__ __align__(256) float g_kv [BM*2*C];
__device__ __align__(256) float g_ck [C];
__device__ __align__(256) float g_cv [C];
__device__ __align__(256) float g_bc [C];

// ------------------------- helpers ---------------------------------------
__device__ __forceinline__ float gelu_exact(float v){
    return 0.5f * v * (1.0f + erff(v * 0.70710678118654752f));
}
__device__ __forceinline__ float warp_sum(float v){
    #pragma unroll
    for (int o = 16; o > 0; o >>= 1) v += __shfl_xor_sync(0xffffffffu, v, o);
    return v;
}
__device__ __forceinline__ unsigned long long pk2(float lo, float hi){
    unsigned long long r;
    asm("mov.b64 %0, {%1,%2};" : "=l"(r) : "f"(lo), "f"(hi));
    return r;
}
__device__ __forceinline__ void upk2(unsigned long long v, float& lo, float& hi){
    asm("mov.b64 {%0,%1}, %2;" : "=f"(lo), "=f"(hi) : "l"(v));
}
__device__ __forceinline__ unsigned long long ffma2(unsigned long long a,
        unsigned long long b, unsigned long long c){
    unsigned long long r;
    asm("fma.rn.f32x2 %0, %1, %2, %3;" : "=l"(r) : "l"(a), "l"(b), "l"(c));
    return r;
}
__device__ __forceinline__ void mma16(float* c, const unsigned* a, const unsigned* b){
    asm("mma.sync.aligned.m16n8k16.row.col.f32.f16.f16.f32 "
        "{%0,%1,%2,%3}, {%4,%5,%6,%7}, {%8,%9}, {%0,%1,%2,%3};"
        : "+f"(c[0]),"+f"(c[1]),"+f"(c[2]),"+f"(c[3])
        : "r"(a[0]),"r"(a[1]),"r"(a[2]),"r"(a[3]), "r"(b[0]),"r"(b[1]));
}
__device__ __forceinline__ unsigned h2pack(float lo, float hi){
    __half2 h = __floats2half2_rn(lo, hi);
    return *(unsigned*)&h;
}
__device__ __forceinline__ void cpa16(const __half* g, __half* s){
    unsigned sa = (unsigned)__cvta_generic_to_shared(s);
    asm volatile("cp.async.ca.shared.global [%0],[%1],16;\n" :: "r"(sa), "l"(g));
}

// ===================== fp16 cp.async tensor-core GEMM =====================
// D[NT x Ncols] = concat(A,A2)[NT x Ktot] @ W^T (+bias, +gelu).
// A,A2,W half (lda=128, W stride ldw halfs). 512 thr, CTA 256x128.
#define AST 40
#define BST 40
#define MMA_SMEM_BYTES ((2*256*AST + 2*128*BST)*2)

__global__ void __launch_bounds__(512, 1) mma_gemm(
    const __half* __restrict__ A, const __half* __restrict__ A2,
    const __half* __restrict__ W, int ldw,
    const float* __restrict__ bias,
    float* __restrict__ D, __half* __restrict__ Dh,
    int Ncols, int Ktot, int flags)
{
    extern __shared__ __half smh[];
    __half* smA = smh;
    __half* smB = smh + 2*256*AST;

    const int tid = threadIdx.x;
    const int lane = tid & 31, wid = tid >> 5;
    const int wm = wid >> 2, wn = wid & 3;
    const long row0 = (long)blockIdx.x * 256;
    const int  col0 = blockIdx.y * 128;

    float acc[4][4][4];
    #pragma unroll
    for (int i=0;i<4;i++)
        #pragma unroll
        for (int j=0;j<4;j++)
            #pragma unroll
            for (int t=0;t<4;t++) acc[i][j][t]=0.f;

    const int nch = Ktot >> 5;

    auto issue = [&](int ch){
        const int kk = ch*32;
        const __half* Asrc = (kk < 128) ? A : A2;
        const int kc = kk & 127;
        __half* Ab = smA + (ch&1)*(256*AST);
        __half* Bb = smB + (ch&1)*(128*BST);
        #pragma unroll
        for (int t=0;t<2;t++){
            int s = tid + t*512;
            int row = s >> 2, q8 = (s & 3) << 3;
            cpa16(Asrc + (row0+row)*128 + kc + q8, Ab + row*AST + q8);
        }
        {
            int row = tid >> 2, q8 = (tid & 3) << 3;
            cpa16(W + (long)(col0+row)*ldw + kk + q8, Bb + row*BST + q8);
        }
        asm volatile("cp.async.commit_group;\n");
    };

    issue(0);
    if (nch > 1) issue(1);

    for (int ch = 0; ch < nch; ch++){
        if (ch+1 < nch) asm volatile("cp.async.wait_group 1;\n" ::: "memory");
        else            asm volatile("cp.async.wait_group 0;\n" ::: "memory");
        __syncthreads();
        const __half* Ab = smA + (ch&1)*(256*AST);
        const __half* Bb = smB + (ch&1)*(128*BST);
        #pragma unroll
        for (int kb=0;kb<2;kb++){
            unsigned af[4][4], bf[4][2];
            #pragma unroll
            for (int i=0;i<4;i++){
                const __half* p = Ab + (wm*64 + i*16 + (lane>>2))*AST
                                + kb*16 + ((lane&3)<<1);
                af[i][0] = *(const unsigned*)p;
                af[i][1] = *(const unsigned*)(p + 8*AST);
                af[i][2] = *(const unsigned*)(p + 8);
                af[i][3] = *(const unsigned*)(p + 8*AST + 8);
            }
            #pragma unroll
            for (int j=0;j<4;j++){
                const __half* p = Bb + (wn*32 + j*8 + (lane>>2))*BST
                                + kb*16 + ((lane&3)<<1);
                bf[j][0] = *(const unsigned*)p;
                bf[j][1] = *(const unsigned*)(p + 8);
            }
            #pragma unroll
            for (int i=0;i<4;i++)
                #pragma unroll
                for (int j=0;j<4;j++)
                    mma16(acc[i][j], af[i], bf[j]);
        }
        __syncthreads();
        if (ch+2 < nch) issue(ch+2);
    }

    #pragma unroll
    for (int i=0;i<4;i++){
        long r = row0 + wm*64 + i*16 + (lane>>2);
        #pragma unroll
        for (int j=0;j<4;j++){
            int cc = col0 + wn*32 + j*8 + ((lane&3)<<1);
            float2 v0 = make_float2(acc[i][j][0], acc[i][j][1]);
            float2 v1 = make_float2(acc[i][j][2], acc[i][j][3]);
            if (bias){
                float2 b2 = *(const float2*)(bias + cc);
                v0.x+=b2.x; v0.y+=b2.y; v1.x+=b2.x; v1.y+=b2.y;
            }
            if (flags & F_GELU){
                v0.x=gelu_exact(v0.x); v0.y=gelu_exact(v0.y);
                v1.x=gelu_exact(v1.x); v1.y=gelu_exact(v1.y);
            }
            if (D){
                *(float2*)(D + r*(long)Ncols + cc) = v0;
                *(float2*)(D + (r+8)*(long)Ncols + cc) = v1;
            }
            if (Dh){
                *(__half2*)(Dh + r*(long)Ncols + cc) = __floats2half2_rn(v0.x, v0.y);
                *(__half2*)(Dh + (r+8)*(long)Ncols + cc) = __floats2half2_rn(v1.x, v1.y);
            }
        }
    }
}

// ===================== conv as split-K fp16 MMA ===========================
// part[kz][1024 x 128] = xim[1024 x 8192] @ wim[128 x 8192]^T (k slice kz)
__global__ void __launch_bounds__(256) conv_mma(
    const __half* __restrict__ Aim, const __half* __restrict__ Wim,
    float* __restrict__ part)
{
    __shared__ __half sA[2][64*AST];
    __shared__ __half sB[2][128*BST];
    const int tid = threadIdx.x, lane = tid & 31, wid = tid >> 5;
    const int wm = wid >> 2, wn = wid & 3;     // 2 row groups x 4 col groups
    const int row0 = blockIdx.x * 64;
    const int kz = blockIdx.z;
    const long Kb = (long)kz * 1024;

    float acc[2][4][4];
    #pragma unroll
    for (int i=0;i<2;i++)
        #pragma unroll
        for (int j=0;j<4;j++)
            #pragma unroll
            for (int t=0;t<4;t++) acc[i][j][t]=0.f;

    auto issue = [&](int ch){
        int kk = ch*32;
        {
            int row = tid >> 2, q8 = (tid & 3) << 3;   // 256 segs: rows 0..63
            if (row < 64)
                cpa16(Aim + (long)(row0+row)*KCONV + Kb + kk + q8,
                      &sA[ch&1][row*AST + q8]);
        }
        #pragma unroll
        for (int t=0;t<2;t++){
            int s = tid + t*256;
            int row = s >> 2, q8 = (s & 3) << 3;       // 512 segs: rows 0..127
            cpa16(Wim + (long)row*KCONV + Kb + kk + q8,
                  &sB[ch&1][row*BST + q8]);
        }
        asm volatile("cp.async.commit_group;\n");
    };

    issue(0); issue(1);
    for (int ch = 0; ch < 32; ch++){
        if (ch < 31) asm volatile("cp.async.wait_group 1;\n" ::: "memory");
        else         asm volatile("cp.async.wait_group 0;\n" ::: "memory");
        __syncthreads();
        const __half* Ab = sA[ch&1];
        const __half* Bb = sB[ch&1];
        #pragma unroll
        for (int kb=0;kb<2;kb++){
            unsigned af[2][4], bf[4][2];
            #pragma unroll
            for (int i=0;i<2;i++){
                const __half* p = Ab + (wm*32 + i*16 + (lane>>2))*AST
                                + kb*16 + ((lane&3)<<1);
                af[i][0] = *(const unsigned*)p;
                af[i][1] = *(const unsigned*)(p + 8*AST);
                af[i][2] = *(const unsigned*)(p + 8);
                af[i][3] = *(const unsigned*)(p + 8*AST + 8);
            }
            #pragma unroll
            for (int j=0;j<4;j++){
                const __half* p = Bb + (wn*32 + j*8 + (lane>>2))*BST
                                + kb*16 + ((lane&3)<<1);
                bf[j][0] = *(const unsigned*)p;
                bf[j][1] = *(const unsigned*)(p + 8);
            }
            #pragma unroll
            for (int i=0;i<2;i++)
                #pragma unroll
                for (int j=0;j<4;j++)
                    mma16(acc[i][j], af[i], bf[j]);
        }
        __syncthreads();
        if (ch+2 < 32) issue(ch+2);
    }

    #pragma unroll
    for (int i=0;i<2;i++){
        int r = row0 + wm*32 + i*16 + (lane>>2);
        #pragma unroll
        for (int j=0;j<4;j++){
            int cc = wn*32 + j*8 + ((lane&3)<<1);
            *(float2*)(part + ((long)kz*BM + r)*C + cc)
                = make_float2(acc[i][j][0], acc[i][j][1]);
            *(float2*)(part + ((long)kz*BM + r + 8)*C + cc)
                = make_float2(acc[i][j][2], acc[i][j][3]);
        }
    }
}

// ------------------------- conversions / gathers --------------------------
__global__ void convh_kernel(const float* __restrict__ s,
                             __half* __restrict__ d, int n4)
{
    int i = blockIdx.x * 256 + threadIdx.x;
    if (i < n4){
        float4 v = ((const float4*)s)[i];
        ((uint2*)d)[i] = make_uint2(h2pack(v.x,v.y), h2pack(v.z,v.w));
    }
}

// xim[r][ (kh*8+kw)*128 + i ] = x[b][(ph*8+kh)*128 + pw*8+kw][i]  (fp16)
__global__ void im2col_kernel(const float* __restrict__ x,
                              __half* __restrict__ xim)
{
    int idx = blockIdx.x * 256 + threadIdx.x;      // 2,097,152 total
    int r = idx >> 11, rem = idx & 2047;
    int k4 = rem << 2;
    int khkw = k4 >> 7, i = k4 & 127;
    int b = r >> 8, p = r & 255, ph = p >> 4, pw = p & 15;
    int kh = khkw >> 3, kw = khkw & 7;
    const float* src = x + ((long)(b*NTOK + (ph*8+kh)*128 + pw*8+kw))*C + i;
    float4 v = *(const float4*)src;
    ((uint2*)(xim + (long)r*KCONV + k4))[0] =
        make_uint2(h2pack(v.x,v.y), h2pack(v.z,v.w));
}

// wim[o][(kh*8+kw)*128 + i] = sr_w[o][i][kh][kw]
__global__ void wim_kernel(const float* __restrict__ srw,
                           __half* __restrict__ wim)
{
    int idx = blockIdx.x * 256 + threadIdx.x;      // 1,048,576 total
    int o = idx >> 13, k = idx & 8191;
    int khkw = k >> 7, i = k & 127;
    int kh = khkw >> 3, kw = khkw & 7;
    wim[idx] = __float2half(srw[(long)o*KCONV + i*64 + kh*8 + kw]);
}

__global__ void conv_reduce_kernel(const float* __restrict__ part,
                                   const float* __restrict__ srb,
                                   float* __restrict__ xi)
{
    int idx = blockIdx.x * 256 + threadIdx.x;
    if (idx < BM*C) {
        float s = srb[idx & (C-1)];
        #pragma unroll
        for (int z = 0; z < KSPLIT; z++) s += part[(long)z*BM*C + idx];
        xi[idx] = s;
    }
}

// ------------------------- scalar GEMM (tiny kv proj only) ----------------
__global__ void __launch_bounds__(256) gemm_kernel(
    const float* __restrict__ A,
    const float* __restrict__ W, int ldw,
    const float* __restrict__ bias,
    float* __restrict__ D, int Ncols, int K)
{
    __shared__ float As[16][64];
    __shared__ float Ws[16][64];
    const int tid = threadIdx.x;
    const int tx = tid & 15, ty = tid >> 4;
    const long row0 = (long)blockIdx.x * 64;
    const int  col0 = blockIdx.y * 64;
    const int lr = tid >> 2;
    const int lk = (tid & 3) << 2;

    const float* Arow  = A + (row0 + lr) * (long)K + lk;
    const float* Wrow  = W + (long)(col0 + lr) * ldw + lk;

    float acc[4][4] = {};
    for (int kk = 0; kk < K; kk += 16) {
        float4 av = *(const float4*)(Arow + kk);
        float4 wv = *(const float4*)(Wrow + kk);
        As[lk+0][lr]=av.x; As[lk+1][lr]=av.y; As[lk+2][lr]=av.z; As[lk+3][lr]=av.w;
        Ws[lk+0][lr]=wv.x; Ws[lk+1][lr]=wv.y; Ws[lk+2][lr]=wv.z; Ws[lk+3][lr]=wv.w;
        __syncthreads();
        #pragma unroll
        for (int k = 0; k < 16; k++) {
            float ar[4], br[4];
            *(float4*)ar = *(const float4*)&As[k][ty<<2];
            *(float4*)br = *(const float4*)&Ws[k][tx<<2];
            #pragma unroll
            for (int i = 0; i < 4; i++)
                #pragma unroll
                for (int j = 0; j < 4; j++)
                    acc[i][j] += ar[i] * br[j];
        }
        __syncthreads();
    }
    #pragma unroll
    for (int i = 0; i < 4; i++) {
        long r = row0 + (ty<<2) + i;
        int  c = col0 + (tx<<2);
        float4 v = make_float4(acc[i][0],acc[i][1],acc[i][2],acc[i][3]);
        v.x+=bias[c]; v.y+=bias[c+1]; v.z+=bias[c+2]; v.w+=bias[c+3];
        *(float4*)(D + r * (long)Ncols + c) = v;
    }
}

// ------------------------- layernorm --------------------------------------
__global__ void ln_kernel(float* __restrict__ xi, const float* __restrict__ g,
                          const float* __restrict__ b)
{
    const int row = blockIdx.x, t = threadIdx.x;
    __shared__ float red[4];
    __shared__ float mv[2];
    float v = xi[(long)row*C + t];
    float s = warp_sum(v);
    if ((t & 31) == 0) red[t >> 5] = s;
    __syncthreads();
    if (t == 0) mv[0] = (red[0]+red[1]+red[2]+red[3]) * (1.0f/C);
    __syncthreads();
    float d = v - mv[0];
    float s2 = warp_sum(d*d);
    if ((t & 31) == 0) red[t >> 5] = s2;
    __syncthreads();
    if (t == 0) mv[1] = (red[0]+red[1]+red[2]+red[3]) * (1.0f/C);
    __syncthreads();
    xi[(long)row*C + t] = d * rsqrtf(mv[1] + 1e-5f) * g[t] + b[t];
}

// ------------------------- SR attention (fp16 output) ---------------------
#define ATTN_SMEM_FLOATS (64*68 + 256*64 + 256*64 + 64*257 + 256 + 64)
__global__ void __launch_bounds__(256) attn_kernel(
    const float* __restrict__ Q, const float* __restrict__ KV,
    __half* __restrict__ O)
{
    extern __shared__ float sm[];
    float* Qs   = sm;
    float* Ks   = Qs + 64*68;
    float* Vs   = Ks + 256*64;
    float* S    = Vs + 256*64;
    float* red  = S  + 64*257;
    float* rowv = red + 256;

    const int tid = threadIdx.x;
    const int h  = blockIdx.y, b_ = blockIdx.z;
    const int q0 = blockIdx.x * 64;

    for (int e = tid; e < 64*16; e += 256) {
        int qq = e >> 4, d4 = (e & 15) << 2;
        float4 v = *(const float4*)(Q + ((long)b_*NTOK + q0 + qq)*C + h*DH + d4);
        *(float4*)&Qs[qq*68 + d4] = v;
    }
    for (int e = tid; e < 256*16; e += 256) {
        int m = e >> 4, d4 = (e & 15) << 2;
        const float* base = KV + ((long)b_*M + m)*(2*C) + h*DH + d4;
        *(float4*)&Ks[m*64 + d4] = *(const float4*)base;
        *(float4*)&Vs[m*64 + d4] = *(const float4*)(base + C);
    }
    __syncthreads();

    const int q  = tid & 63;
    const int mg = tid >> 6;

    unsigned long long q2[32];
    #pragma unroll
    for (int d = 0; d < 16; d++) {
        float4 v = *(const float4*)&Qs[q*68 + d*4];
        q2[2*d]   = pk2(v.x, v.y);
        q2[2*d+1] = pk2(v.z, v.w);
    }
    for (int mi = 0; mi < 64; mi++) {
        int m = mg*64 + mi;
        const float4* kr = (const float4*)&Ks[m*64];
        unsigned long long a0 = 0ull, a1 = 0ull;
        #pragma unroll
        for (int dd = 0; dd < 16; dd++) {
            float4 kv4 = kr[dd];
            a0 = ffma2(pk2(kv4.x,kv4.y), q2[2*dd],   a0);
            a1 = ffma2(pk2(kv4.z,kv4.w), q2[2*dd+1], a1);
        }
        float x0,x1,y0,y1; upk2(a0,x0,x1); upk2(a1,y0,y1);
        S[q*257 + m] = (x0+x1+y0+y1) * 0.125f;
    }
    __syncthreads();

    float lmax = -1e30f;
    for (int mi = 0; mi < 64; mi++) lmax = fmaxf(lmax, S[q*257 + mg*64 + mi]);
    red[q*4 + mg] = lmax;
    __syncthreads();
    if (tid < 64)
        rowv[tid] = fmaxf(fmaxf(red[tid*4],red[tid*4+1]), fmaxf(red[tid*4+2],red[tid*4+3]));
    __syncthreads();
    float rm = rowv[q];
    float lsum = 0.f;
    for (int mi = 0; mi < 64; mi++) {
        int m = mg*64 + mi;
        float e = expf(S[q*257 + m] - rm);
        S[q*257 + m] = e;
        lsum += e;
    }
    red[q*4 + mg] = lsum;
    __syncthreads();
    if (tid < 64)
        rowv[tid] = 1.0f / (red[tid*4]+red[tid*4+1]+red[tid*4+2]+red[tid*4+3]);
    __syncthreads();

    const int dg = mg;
    unsigned long long o2[8];
    #pragma unroll
    for (int t = 0; t < 8; t++) o2[t] = 0ull;
    for (int m = 0; m < 256; m++) {
        float p = S[q*257 + m];
        unsigned long long pd = pk2(p, p);
        const float4* vr = (const float4*)&Vs[m*64 + dg*16];
        #pragma unroll
        for (int t = 0; t < 4; t++) {
            float4 v4 = vr[t];
            o2[2*t]   = ffma2(pk2(v4.x,v4.y), pd, o2[2*t]);
            o2[2*t+1] = ffma2(pk2(v4.z,v4.w), pd, o2[2*t+1]);
        }
    }
    float inv = rowv[q];
    float ov[16];
    #pragma unroll
    for (int t = 0; t < 8; t++) upk2(o2[t], ov[2*t], ov[2*t+1]);
    __half* op = O + ((long)b_*NTOK + q0 + q)*C + h*DH + dg*16;
    #pragma unroll
    for (int dd = 0; dd < 16; dd += 2)
        *(__half2*)(op + dd) = __floats2half2_rn(ov[dd]*inv, ov[dd+1]*inv);
}

// ------------------------- judger row softmax -----------------------------
__global__ void rowsoftmax_kernel(float* __restrict__ S)
{
    const int row  = blockIdx.x * 8 + (threadIdx.x >> 5);
    const int lane = threadIdx.x & 31;
    float* p = S + (long)row*C + lane*4;
    float4 v = *(const float4*)p;
    float m = fmaxf(fmaxf(v.x,v.y), fmaxf(v.z,v.w));
    #pragma unroll
    for (int o = 16; o > 0; o >>= 1) m = fmaxf(m, __shfl_xor_sync(0xffffffffu, m, o));
    float4 e = make_float4(expf(v.x-m), expf(v.y-m), expf(v.z-m), expf(v.w-m));
    float s = e.x+e.y+e.z+e.w;
    s = warp_sum(s);
    float inv = 1.0f/s;
    e.x*=inv; e.y*=inv; e.z*=inv; e.w*=inv;
    *(float4*)p = e;
}

// ------------------------- elementwise a*s (half out) ---------------------
__global__ void amul_kernel(const __half* __restrict__ a,
                            const float* __restrict__ s,
                            __half* __restrict__ d)
{
    long i = (long)blockIdx.x * 256 + threadIdx.x;
    uint2 av = ((const uint2*)a)[i];
    float4 vs = ((const float4*)s)[i];
    __half2 a0 = *(__half2*)&av.x, a1 = *(__half2*)&av.y;
    float2 f0 = __half22float2(a0), f1 = __half22float2(a1);
    ((uint2*)d)[i] = make_uint2(h2pack(f0.x*vs.x, f0.y*vs.y),
                                h2pack(f1.x*vs.z, f1.y*vs.w));
}

// ------------------------- fused proj weight build (half out) -------------
__global__ void wfuse_kernel(const float* __restrict__ projw,
                             const float* __restrict__ outw,
                             const float* __restrict__ outb,
                             const float* __restrict__ projb,
                             __half* __restrict__ wfh, float* __restrict__ bc)
{
    const int o = blockIdx.x, t = threadIdx.x;
    float s = 0.f;
    #pragma unroll 4
    for (int j = 0; j < C; j++) s += projw[o*C + j] * outw[j*C + t];
    wfh[o*2*C + t]     = __float2half(s);
    wfh[o*2*C + C + t] = __float2half(projw[o*C + t]);
    __shared__ float red[C];
    red[t] = projw[o*C + t] * outb[t];
    __syncthreads();
    for (int st = 64; st > 0; st >>= 1){
        if (t < st) red[t] += red[t + st];
        __syncthreads();
    }
    if (t == 0) bc[o] = projb[o] + red[0];
}

// ------------------------- constant noise projections ---------------------
__global__ void cknoise_kernel(const float* __restrict__ inw,
                               const float* __restrict__ kn,
                               const float* __restrict__ vn,
                               float* __restrict__ ck, float* __restrict__ cv)
{
    int t = threadIdx.x;
    if (t < 128) {
        const float* w = inw + (long)(C + t)*C;
        float s = 0.f;
        #pragma unroll 4
        for (int j = 0; j < C; j++) s += kn[j]*w[j];
        ck[t] = s;
    } else {
        int c = t - 128;
        const float* w = inw + (long)(2*C + c)*C;
        float s = 0.f;
        #pragma unroll 4
        for (int j = 0; j < C; j++) s += vn[j]*w[j];
        cv[c] = s;
    }
}

// ------------------------- 2-key attention combine (half out) -------------
__global__ void combine_kernel(const float* __restrict__ qkv,
                               const float* __restrict__ kp1,
                               const float* __restrict__ vp1,
                               const float* __restrict__ ck,
                               const float* __restrict__ cv,
                               __half* __restrict__ O)
{
    long idx = (long)blockIdx.x * 256 + threadIdx.x;
    long r = idx >> 3;
    int  h = (int)(idx & 7);
    const float* qp = qkv + r*384 + h*16;
    const float* k0 = qkv + r*384 + 128 + h*16;
    const float* v0 = qkv + r*384 + 256 + h*16;
    const float* k1 = kp1 + r*128 + h*16;
    const float* v1 = vp1 + r*128 + h*16;
    const float* ckh = ck + h*16;
    const float* cvh = cv + h*16;
    float s0 = 0.f, s1 = 0.f;
    #pragma unroll
    for (int i = 0; i < 16; i++) {
        float qv = qp[i];
        s0 += qv * (k0[i] + ckh[i]);
        s1 += qv * k1[i];
    }
    s0 *= 0.25f; s1 *= 0.25f;
    float mx = fmaxf(s0, s1);
    float e0 = expf(s0-mx), e1 = expf(s1-mx);
    float inv = 1.0f/(e0+e1);
    float a0 = e0*inv, a1 = e1*inv;
    __half* op = O + r*128 + h*16;
    #pragma unroll
    for (int i = 0; i < 16; i += 2)
        *(__half2*)(op + i) = __floats2half2_rn(a0*(v0[i] + cvh[i]) + a1*v1[i],
                                                a0*(v0[i+1] + cvh[i+1]) + a1*v1[i+1]);
}

// ------------------------- host driver ------------------------------------
static void run_mma(const __half* A, const __half* A2,
                    const __half* W, int ldw,
                    const float* bias, float* D, __half* Dh,
                    int Ncols, int Ktot, int flags)
{
    dim3 g(NT/256, Ncols/128);
    mma_gemm<<<g, 512, MMA_SMEM_BYTES>>>(A, A2, W, ldw, bias, D, Dh, Ncols, Ktot, flags);
}

extern "C" void kernel_launch(void* const* d_in, const int* in_sizes, int n_in,
                              void* d_out, int out_size)
{
    const float* x0       = (const float*)d_in[0];
    const float* x1       = (const float*)d_in[1];
    const float* Wq       = (const float*)d_in[2];
    const float* bq       = (const float*)d_in[3];
    const float* Wkv      = (const float*)d_in[4];
    const float* bkv      = (const float*)d_in[5];
    const float* sr_w     = (const float*)d_in[6];
    const float* sr_b     = (const float*)d_in[7];
    const float* ln_g[2]  = {(const float*)d_in[8],  (const float*)d_in[10]};
    const float* ln_b[2]  = {(const float*)d_in[9],  (const float*)d_in[11]};
    const float* in_w[2]  = {(const float*)d_in[12], (const float*)d_in[16]};
    const float* in_b[2]  = {(const float*)d_in[13], (const float*)d_in[17]};
    const float* out_w[2] = {(const float*)d_in[14], (const float*)d_in[18]};
    const float* out_b[2] = {(const float*)d_in[15], (const float*)d_in[19]};
    const float* rj_w1    = (const float*)d_in[20];
    const float* rj_b1    = (const float*)d_in[21];
    const float* rj_w2    = (const float*)d_in[22];
    const float* rj_b2    = (const float*)d_in[23];
    const float* k_noise  = (const float*)d_in[24];
    const float* v_noise  = (const float*)d_in[25];
    const float* proj_w   = (const float*)d_in[26];
    const float* proj_b   = (const float*)d_in[27];

    __half *xh, *xim, *xah0, *xah1, *hh, *oh, *wqh, *rj1h, *rj2h, *inwh0, *inwh1, *wfh, *wim;
    float *q, *s, *qkv, *kp1, *vp1, *cpart, *xi, *kv, *ck, *cv, *bc;
    cudaGetSymbolAddress((void**)&xh,    g_xh);
    cudaGetSymbolAddress((void**)&xim,   g_xim);
    cudaGetSymbolAddress((void**)&xah0,  g_xah0);
    cudaGetSymbolAddress((void**)&xah1,  g_xah1);
    cudaGetSymbolAddress((void**)&hh,    g_hh);
    cudaGetSymbolAddress((void**)&oh,    g_oh);
    cudaGetSymbolAddress((void**)&wqh,   g_wqh);
    cudaGetSymbolAddress((void**)&rj1h,  g_rj1h);
    cudaGetSymbolAddress((void**)&rj2h,  g_rj2h);
    cudaGetSymbolAddress((void**)&inwh0, g_inwh0);
    cudaGetSymbolAddress((void**)&inwh1, g_inwh1);
    cudaGetSymbolAddress((void**)&wfh,   g_wfh);
    cudaGetSymbolAddress((void**)&wim,   g_wim);
    cudaGetSymbolAddress((void**)&q,     g_q);
    cudaGetSymbolAddress((void**)&s,     g_s);
    cudaGetSymbolAddress((void**)&qkv,   g_qkv);
    cudaGetSymbolAddress((void**)&kp1,   g_kp1);
    cudaGetSymbolAddress((void**)&vp1,   g_vp1);
    cudaGetSymbolAddress((void**)&cpart, g_cpart);
    cudaGetSymbolAddress((void**)&xi,    g_xi);
    cudaGetSymbolAddress((void**)&kv,    g_kv);
    cudaGetSymbolAddress((void**)&ck,    g_ck);
    cudaGetSymbolAddress((void**)&cv,    g_cv);
    cudaGetSymbolAddress((void**)&bc,    g_bc);

    const int attn_smem = ATTN_SMEM_FLOATS * 4;
    cudaFuncSetAttribute(attn_kernel, cudaFuncAttributeMaxDynamicSharedMemorySize, attn_smem);
    cudaFuncSetAttribute(mma_gemm, cudaFuncAttributeMaxDynamicSharedMemorySize, MMA_SMEM_BYTES);

    __half* xah[2] = {xah0, xah1};
    __half* inwh[2] = {inwh0, inwh1};
    const float* xin[2] = {x0, x1};

    // ---- weight conversions (once) ----
    convh_kernel<<<(C*C/4+255)/256, 256>>>(Wq, wqh, C*C/4);
    convh_kernel<<<(2*C*C/4+255)/256, 256>>>(rj_w1, rj1h, 2*C*C/4);
    convh_kernel<<<(C*C/4+255)/256, 256>>>(rj_w2, rj2h, C*C/4);
    convh_kernel<<<(3*C*C/4+255)/256, 256>>>(in_w[0], inwh0, 3*C*C/4);
    convh_kernel<<<(3*C*C/4+255)/256, 256>>>(in_w[1], inwh1, 3*C*C/4);
    wim_kernel<<<(C*KCONV)/256, 256>>>(sr_w, wim);

    // ---- stage A ----
    for (int im = 0; im < 2; im++) {
        convh_kernel<<<(NT*C/4)/256, 256>>>(xin[im], xh, NT*C/4);
        im2col_kernel<<<(BM*KCONV/4)/256, 256>>>(xin[im], xim);
        run_mma(xh, nullptr, wqh, C, bq, q, nullptr, C, C, 0);
        conv_mma<<<dim3(16, 1, KSPLIT), 256>>>(xim, wim, cpart);
        conv_reduce_kernel<<<(BM*C + 255)/256, 256>>>(cpart, sr_b, xi);
        ln_kernel<<<BM, 128>>>(xi, ln_g[im], ln_b[im]);
        gemm_kernel<<<dim3(BM/64, (2*C)/64), 256>>>(xi, Wkv, C, bkv, kv, 2*C, C);
        attn_kernel<<<dim3(NTOK/64, HEADS, BB), 256, attn_smem>>>(q, kv, xah[im]);
    }

    // ---- stage B ----
    for (int d = 0; d < 2; d++) {
        const __half* a  = xah[d];
        const __half* bb = xah[1-d];
        float* dst = (float*)d_out + (size_t)d * NT * C;

        run_mma(a, bb, rj1h, 2*C, rj_b1, nullptr, hh, C, 2*C, F_GELU);
        run_mma(hh, nullptr, rj2h, C, rj_b2, s, nullptr, C, C, 0);
        rowsoftmax_kernel<<<NT/8, 256>>>(s);

        cknoise_kernel<<<1, 256>>>(in_w[d], k_noise + d*C, v_noise + d*C, ck, cv);
        amul_kernel<<<NT*C/4/256, 256>>>(a, s, hh);   // hh := a*s

        run_mma(a,  nullptr, inwh[d],         C, in_b[d],       qkv, nullptr, 3*C, C, 0);
        run_mma(hh, nullptr, inwh[d] + C*C,   C, in_b[d] + C,   kp1, nullptr, C,   C, 0);
        run_mma(bb, nullptr, inwh[d] + 2*C*C, C, in_b[d] + 2*C, vp1, nullptr, C,   C, 0);

        combine_kernel<<<(long)NT*XH/256, 256>>>(qkv, kp1, vp1, ck, cv, oh);

        wfuse_kernel<<<C, C>>>(proj_w, out_w[d], out_b[d], proj_b, wfh, bc);
        run_mma(oh, a, wfh, 2*C, bc, dst, nullptr, C, 2*C, 0);
    }
}

// round 9
// speedup vs baseline: 3.6476x; 1.6325x over previous
#include <cuda_runtime.h>
#include <cuda_fp16.h>
#include <math.h>
#include <cstdint>

#define BB 4
#define NTOK 16384
#define C 128
#define NT (BB*NTOK)
#define M 256
#define BM (BB*M)
#define HEADS 2
#define DH 64
#define XH 8
#define KCONV 8192
#define KSPLIT 8

#define F_GELU  2

// ------------------------- scratch ---------------------------------------
__device__ __align__(256) __half g_xh  [NT*C];
__device__ __align__(256) __half g_xim [(size_t)BM*KCONV];
__device__ __align__(256) __half g_xah0[NT*C];
__device__ __align__(256) __half g_xah1[NT*C];
__device__ __align__(256) __half g_hh  [NT*C];
__device__ __align__(256) __half g_oh  [NT*C];
__device__ __align__(256) __half g_qh  [NT*C];
__device__ __align__(256) __half g_qkvh[(size_t)NT*3*C];
__device__ __align__(256) __half g_kp1h[NT*C];
__device__ __align__(256) __half g_vp1h[NT*C];
__device__ __align__(256) __half g_wqh [C*C];
__device__ __align__(256) __half g_rj1h[2*C*C];
__device__ __align__(256) __half g_rj2h[C*C];
__device__ __align__(256) __half g_inwh0[3*C*C];
__device__ __align__(256) __half g_inwh1[3*C*C];
__device__ __align__(256) __half g_wfh [2*C*C];
__device__ __align__(256) __half g_wim [(size_t)C*KCONV];
__device__ __align__(256) __half g_Kh  [BB*HEADS*M*DH];
__device__ __align__(256) __half g_VtG [BB*HEADS*DH*M];

__device__ __align__(256) float g_s  [NT*C];
__device__ __align__(256) float g_cpart[KSPLIT*BM*C];
__device__ __align__(256) float g_xi [BM*C];
__device__ __align__(256) float g_kv [BM*2*C];
__device__ __align__(256) float g_ck [C];
__device__ __align__(256) float g_cv [C];
__device__ __align__(256) float g_bc [C];

// ------------------------- helpers ---------------------------------------
__device__ __forceinline__ float gelu_exact(float v){
    return 0.5f * v * (1.0f + erff(v * 0.70710678118654752f));
}
__device__ __forceinline__ float warp_sum(float v){
    #pragma unroll
    for (int o = 16; o > 0; o >>= 1) v += __shfl_xor_sync(0xffffffffu, v, o);
    return v;
}
__device__ __forceinline__ void mma16(float* c, const unsigned* a, const unsigned* b){
    asm("mma.sync.aligned.m16n8k16.row.col.f32.f16.f16.f32 "
        "{%0,%1,%2,%3}, {%4,%5,%6,%7}, {%8,%9}, {%0,%1,%2,%3};"
        : "+f"(c[0]),"+f"(c[1]),"+f"(c[2]),"+f"(c[3])
        : "r"(a[0]),"r"(a[1]),"r"(a[2]),"r"(a[3]), "r"(b[0]),"r"(b[1]));
}
__device__ __forceinline__ unsigned h2pack(float lo, float hi){
    __half2 h = __floats2half2_rn(lo, hi);
    return *(unsigned*)&h;
}
__device__ __forceinline__ void cpa16(const __half* g, __half* s){
    unsigned sa = (unsigned)__cvta_generic_to_shared(s);
    asm volatile("cp.async.ca.shared.global [%0],[%1],16;\n" :: "r"(sa), "l"(g));
}

// ===================== fp16 cp.async tensor-core GEMM =====================
#define AST 40
#define BST 40
#define MMA_SMEM_BYTES ((2*256*AST + 2*128*BST)*2)

__global__ void __launch_bounds__(512, 1) mma_gemm(
    const __half* __restrict__ A, const __half* __restrict__ A2,
    const __half* __restrict__ W, int ldw,
    const float* __restrict__ bias,
    float* __restrict__ D, __half* __restrict__ Dh,
    int Ncols, int Ktot, int flags)
{
    extern __shared__ __half smh[];
    __half* smA = smh;
    __half* smB = smh + 2*256*AST;

    const int tid = threadIdx.x;
    const int lane = tid & 31, wid = tid >> 5;
    const int wm = wid >> 2, wn = wid & 3;
    const long row0 = (long)blockIdx.x * 256;
    const int  col0 = blockIdx.y * 128;

    float acc[4][4][4];
    #pragma unroll
    for (int i=0;i<4;i++)
        #pragma unroll
        for (int j=0;j<4;j++)
            #pragma unroll
            for (int t=0;t<4;t++) acc[i][j][t]=0.f;

    const int nch = Ktot >> 5;

    auto issue = [&](int ch){
        const int kk = ch*32;
        const __half* Asrc = (kk < 128) ? A : A2;
        const int kc = kk & 127;
        __half* Ab = smA + (ch&1)*(256*AST);
        __half* Bb = smB + (ch&1)*(128*BST);
        #pragma unroll
        for (int t=0;t<2;t++){
            int s = tid + t*512;
            int row = s >> 2, q8 = (s & 3) << 3;
            cpa16(Asrc + (row0+row)*128 + kc + q8, Ab + row*AST + q8);
        }
        {
            int row = tid >> 2, q8 = (tid & 3) << 3;
            cpa16(W + (long)(col0+row)*ldw + kk + q8, Bb + row*BST + q8);
        }
        asm volatile("cp.async.commit_group;\n");
    };

    issue(0);
    if (nch > 1) issue(1);

    for (int ch = 0; ch < nch; ch++){
        if (ch+1 < nch) asm volatile("cp.async.wait_group 1;\n" ::: "memory");
        else            asm volatile("cp.async.wait_group 0;\n" ::: "memory");
        __syncthreads();
        const __half* Ab = smA + (ch&1)*(256*AST);
        const __half* Bb = smB + (ch&1)*(128*BST);
        #pragma unroll
        for (int kb=0;kb<2;kb++){
            unsigned af[4][4], bf[4][2];
            #pragma unroll
            for (int i=0;i<4;i++){
                const __half* p = Ab + (wm*64 + i*16 + (lane>>2))*AST
                                + kb*16 + ((lane&3)<<1);
                af[i][0] = *(const unsigned*)p;
                af[i][1] = *(const unsigned*)(p + 8*AST);
                af[i][2] = *(const unsigned*)(p + 8);
                af[i][3] = *(const unsigned*)(p + 8*AST + 8);
            }
            #pragma unroll
            for (int j=0;j<4;j++){
                const __half* p = Bb + (wn*32 + j*8 + (lane>>2))*BST
                                + kb*16 + ((lane&3)<<1);
                bf[j][0] = *(const unsigned*)p;
                bf[j][1] = *(const unsigned*)(p + 8);
            }
            #pragma unroll
            for (int i=0;i<4;i++)
                #pragma unroll
                for (int j=0;j<4;j++)
                    mma16(acc[i][j], af[i], bf[j]);
        }
        __syncthreads();
        if (ch+2 < nch) issue(ch+2);
    }

    #pragma unroll
    for (int i=0;i<4;i++){
        long r = row0 + wm*64 + i*16 + (lane>>2);
        #pragma unroll
        for (int j=0;j<4;j++){
            int cc = col0 + wn*32 + j*8 + ((lane&3)<<1);
            float2 v0 = make_float2(acc[i][j][0], acc[i][j][1]);
            float2 v1 = make_float2(acc[i][j][2], acc[i][j][3]);
            if (bias){
                float2 b2 = *(const float2*)(bias + cc);
                v0.x+=b2.x; v0.y+=b2.y; v1.x+=b2.x; v1.y+=b2.y;
            }
            if (flags & F_GELU){
                v0.x=gelu_exact(v0.x); v0.y=gelu_exact(v0.y);
                v1.x=gelu_exact(v1.x); v1.y=gelu_exact(v1.y);
            }
            if (D){
                *(float2*)(D + r*(long)Ncols + cc) = v0;
                *(float2*)(D + (r+8)*(long)Ncols + cc) = v1;
            }
            if (Dh){
                *(__half2*)(Dh + r*(long)Ncols + cc) = __floats2half2_rn(v0.x, v0.y);
                *(__half2*)(Dh + (r+8)*(long)Ncols + cc) = __floats2half2_rn(v1.x, v1.y);
            }
        }
    }
}

// ===================== conv as split-K fp16 MMA ===========================
__global__ void __launch_bounds__(256) conv_mma(
    const __half* __restrict__ Aim, const __half* __restrict__ Wim,
    float* __restrict__ part)
{
    __shared__ __half sA[2][64*AST];
    __shared__ __half sB[2][128*BST];
    const int tid = threadIdx.x, lane = tid & 31, wid = tid >> 5;
    const int wm = wid >> 2, wn = wid & 3;
    const int row0 = blockIdx.x * 64;
    const int kz = blockIdx.z;
    const long Kb = (long)kz * 1024;

    float acc[2][4][4];
    #pragma unroll
    for (int i=0;i<2;i++)
        #pragma unroll
        for (int j=0;j<4;j++)
            #pragma unroll
            for (int t=0;t<4;t++) acc[i][j][t]=0.f;

    auto issue = [&](int ch){
        int kk = ch*32;
        {
            int row = tid >> 2, q8 = (tid & 3) << 3;
            if (row < 64)
                cpa16(Aim + (long)(row0+row)*KCONV + Kb + kk + q8,
                      &sA[ch&1][row*AST + q8]);
        }
        #pragma unroll
        for (int t=0;t<2;t++){
            int s = tid + t*256;
            int row = s >> 2, q8 = (s & 3) << 3;
            cpa16(Wim + (long)row*KCONV + Kb + kk + q8,
                  &sB[ch&1][row*BST + q8]);
        }
        asm volatile("cp.async.commit_group;\n");
    };

    issue(0); issue(1);
    for (int ch = 0; ch < 32; ch++){
        if (ch < 31) asm volatile("cp.async.wait_group 1;\n" ::: "memory");
        else         asm volatile("cp.async.wait_group 0;\n" ::: "memory");
        __syncthreads();
        const __half* Ab = sA[ch&1];
        const __half* Bb = sB[ch&1];
        #pragma unroll
        for (int kb=0;kb<2;kb++){
            unsigned af[2][4], bf[4][2];
            #pragma unroll
            for (int i=0;i<2;i++){
                const __half* p = Ab + (wm*32 + i*16 + (lane>>2))*AST
                                + kb*16 + ((lane&3)<<1);
                af[i][0] = *(const unsigned*)p;
                af[i][1] = *(const unsigned*)(p + 8*AST);
                af[i][2] = *(const unsigned*)(p + 8);
                af[i][3] = *(const unsigned*)(p + 8*AST + 8);
            }
            #pragma unroll
            for (int j=0;j<4;j++){
                const __half* p = Bb + (wn*32 + j*8 + (lane>>2))*BST
                                + kb*16 + ((lane&3)<<1);
                bf[j][0] = *(const unsigned*)p;
                bf[j][1] = *(const unsigned*)(p + 8);
            }
            #pragma unroll
            for (int i=0;i<2;i++)
                #pragma unroll
                for (int j=0;j<4;j++)
                    mma16(acc[i][j], af[i], bf[j]);
        }
        __syncthreads();
        if (ch+2 < 32) issue(ch+2);
    }

    #pragma unroll
    for (int i=0;i<2;i++){
        int r = row0 + wm*32 + i*16 + (lane>>2);
        #pragma unroll
        for (int j=0;j<4;j++){
            int cc = wn*32 + j*8 + ((lane&3)<<1);
            *(float2*)(part + ((long)kz*BM + r)*C + cc)
                = make_float2(acc[i][j][0], acc[i][j][1]);
            *(float2*)(part + ((long)kz*BM + r + 8)*C + cc)
                = make_float2(acc[i][j][2], acc[i][j][3]);
        }
    }
}

// ------------------------- conversions / gathers --------------------------
__global__ void convh_kernel(const float* __restrict__ s,
                             __half* __restrict__ d, int n4)
{
    int i = blockIdx.x * 256 + threadIdx.x;
    if (i < n4){
        float4 v = ((const float4*)s)[i];
        ((uint2*)d)[i] = make_uint2(h2pack(v.x,v.y), h2pack(v.z,v.w));
    }
}

__global__ void im2col_kernel(const float* __restrict__ x,
                              __half* __restrict__ xim)
{
    int idx = blockIdx.x * 256 + threadIdx.x;
    int r = idx >> 11, rem = idx & 2047;
    int k4 = rem << 2;
    int khkw = k4 >> 7, i = k4 & 127;
    int b = r >> 8, p = r & 255, ph = p >> 4, pw = p & 15;
    int kh = khkw >> 3, kw = khkw & 7;
    const float* src = x + ((long)(b*NTOK + (ph*8+kh)*128 + pw*8+kw))*C + i;
    float4 v = *(const float4*)src;
    ((uint2*)(xim + (long)r*KCONV + k4))[0] =
        make_uint2(h2pack(v.x,v.y), h2pack(v.z,v.w));
}

__global__ void wim_kernel(const float* __restrict__ srw,
                           __half* __restrict__ wim)
{
    int idx = blockIdx.x * 256 + threadIdx.x;
    int o = idx >> 13, k = idx & 8191;
    int khkw = k >> 7, i = k & 127;
    int kh = khkw >> 3, kw = khkw & 7;
    wim[idx] = __float2half(srw[(long)o*KCONV + i*64 + kh*8 + kw]);
}

__global__ void conv_reduce_kernel(const float* __restrict__ part,
                                   const float* __restrict__ srb,
                                   float* __restrict__ xi)
{
    int idx = blockIdx.x * 256 + threadIdx.x;
    if (idx < BM*C) {
        float s = srb[idx & (C-1)];
        #pragma unroll
        for (int z = 0; z < KSPLIT; z++) s += part[(long)z*BM*C + idx];
        xi[idx] = s;
    }
}

// kvprep: Kh[bh][m][d] = kv[b*M+m][h*64+d]; Vt[bh][d][m] = kv[b*M+m][128+h*64+d]
__global__ void kvprep_kernel(const float* __restrict__ kv,
                              __half* __restrict__ Kh, __half* __restrict__ Vt)
{
    int idx = blockIdx.x * 256 + threadIdx.x;   // BB*HEADS*M*DH = 131072
    int d = idx & 63, m = (idx >> 6) & 255, bh = idx >> 14;
    int b = bh >> 1, h = bh & 1;
    const float* base = kv + ((long)(b*M + m))*(2*C) + h*DH + d;
    Kh[(long)bh*M*DH + m*DH + d] = __float2half(base[0]);
    Vt[(long)bh*DH*M + d*M + m]  = __float2half(base[C]);
}

// ------------------------- scalar GEMM (tiny kv proj only) ----------------
__global__ void __launch_bounds__(256) gemm_kernel(
    const float* __restrict__ A,
    const float* __restrict__ W, int ldw,
    const float* __restrict__ bias,
    float* __restrict__ D, int Ncols, int K)
{
    __shared__ float As[16][64];
    __shared__ float Ws[16][64];
    const int tid = threadIdx.x;
    const int tx = tid & 15, ty = tid >> 4;
    const long row0 = (long)blockIdx.x * 64;
    const int  col0 = blockIdx.y * 64;
    const int lr = tid >> 2;
    const int lk = (tid & 3) << 2;

    const float* Arow  = A + (row0 + lr) * (long)K + lk;
    const float* Wrow  = W + (long)(col0 + lr) * ldw + lk;

    float acc[4][4] = {};
    for (int kk = 0; kk < K; kk += 16) {
        float4 av = *(const float4*)(Arow + kk);
        float4 wv = *(const float4*)(Wrow + kk);
        As[lk+0][lr]=av.x; As[lk+1][lr]=av.y; As[lk+2][lr]=av.z; As[lk+3][lr]=av.w;
        Ws[lk+0][lr]=wv.x; Ws[lk+1][lr]=wv.y; Ws[lk+2][lr]=wv.z; Ws[lk+3][lr]=wv.w;
        __syncthreads();
        #pragma unroll
        for (int k = 0; k < 16; k++) {
            float ar[4], br[4];
            *(float4*)ar = *(const float4*)&As[k][ty<<2];
            *(float4*)br = *(const float4*)&Ws[k][tx<<2];
            #pragma unroll
            for (int i = 0; i < 4; i++)
                #pragma unroll
                for (int j = 0; j < 4; j++)
                    acc[i][j] += ar[i] * br[j];
        }
        __syncthreads();
    }
    #pragma unroll
    for (int i = 0; i < 4; i++) {
        long r = row0 + (ty<<2) + i;
        int  c = col0 + (tx<<2);
        float4 v = make_float4(acc[i][0],acc[i][1],acc[i][2],acc[i][3]);
        v.x+=bias[c]; v.y+=bias[c+1]; v.z+=bias[c+2]; v.w+=bias[c+3];
        *(float4*)(D + r * (long)Ncols + c) = v;
    }
}

// ------------------------- layernorm --------------------------------------
__global__ void ln_kernel(float* __restrict__ xi, const float* __restrict__ g,
                          const float* __restrict__ b)
{
    const int row = blockIdx.x, t = threadIdx.x;
    __shared__ float red[4];
    __shared__ float mv[2];
    float v = xi[(long)row*C + t];
    float s = warp_sum(v);
    if ((t & 31) == 0) red[t >> 5] = s;
    __syncthreads();
    if (t == 0) mv[0] = (red[0]+red[1]+red[2]+red[3]) * (1.0f/C);
    __syncthreads();
    float d = v - mv[0];
    float s2 = warp_sum(d*d);
    if ((t & 31) == 0) red[t >> 5] = s2;
    __syncthreads();
    if (t == 0) mv[1] = (red[0]+red[1]+red[2]+red[3]) * (1.0f/C);
    __syncthreads();
    xi[(long)row*C + t] = d * rsqrtf(mv[1] + 1e-5f) * g[t] + b[t];
}

// ===================== SR attention via fp16 MMA ==========================
// block: (64 queries, head, batch). 256 threads / 8 warps.
// smem: S fp32[64][257], red/rowv, Qs[64][72]h, Ks[256][72]h,
//       Ps[64][264]h, Vt[64][264]h
#define ATTN2_SMEM (64*257*4 + 256*4 + 64*4 + (64*72 + 256*72 + 64*264 + 64*264)*2)

__global__ void __launch_bounds__(256, 1) attn_mma(
    const __half* __restrict__ Qh, const __half* __restrict__ KhG,
    const __half* __restrict__ VtG, __half* __restrict__ O)
{
    extern __shared__ char sm2[];
    float* S    = (float*)sm2;
    float* red  = S + 64*257;
    float* rowv = red + 256;
    __half* Qs  = (__half*)(rowv + 64);
    __half* Ks  = Qs + 64*72;
    __half* Ps  = Ks + 256*72;
    __half* Vt  = Ps + 64*264;

    const int tid = threadIdx.x, lane = tid & 31, wid = tid >> 5;
    const int h = blockIdx.y, b_ = blockIdx.z;
    const int q0 = blockIdx.x * 64;
    const int bh = b_*HEADS + h;

    // stage Q, K, Vt
    #pragma unroll
    for (int t = 0; t < 2; t++){
        int e = tid + t*256;               // 64*8 segs
        int row = e >> 3, c8 = (e & 7) << 3;
        *(uint4*)&Qs[row*72 + c8] =
            *(const uint4*)(Qh + ((long)b_*NTOK + q0 + row)*C + h*DH + c8);
    }
    #pragma unroll
    for (int t = 0; t < 8; t++){
        int e = tid + t*256;               // 256*8 segs
        int row = e >> 3, c8 = (e & 7) << 3;
        *(uint4*)&Ks[row*72 + c8] =
            *(const uint4*)(KhG + (long)bh*M*DH + row*DH + c8);
    }
    #pragma unroll
    for (int t = 0; t < 8; t++){
        int e = tid + t*256;               // 64*32 segs
        int row = e >> 5, c8 = (e & 31) << 3;
        *(uint4*)&Vt[row*264 + c8] =
            *(const uint4*)(VtG + (long)bh*DH*M + row*M + c8);
    }
    __syncthreads();

    // ---- scores: S = Q @ K^T * 0.125 ----
    {
        const int qr0 = (wid & 3) * 16;
        const int n0  = (wid >> 2) * 128;
        float sacc[16][4];
        #pragma unroll
        for (int j=0;j<16;j++){ sacc[j][0]=0;sacc[j][1]=0;sacc[j][2]=0;sacc[j][3]=0; }
        #pragma unroll
        for (int kb=0;kb<4;kb++){
            unsigned af[4];
            const __half* pa = Qs + (qr0 + (lane>>2))*72 + kb*16 + ((lane&3)<<1);
            af[0]=*(const unsigned*)pa;       af[1]=*(const unsigned*)(pa+8*72);
            af[2]=*(const unsigned*)(pa+8);   af[3]=*(const unsigned*)(pa+8*72+8);
            #pragma unroll
            for (int j=0;j<16;j++){
                unsigned bf[2];
                const __half* pb = Ks + (n0 + j*8 + (lane>>2))*72 + kb*16 + ((lane&3)<<1);
                bf[0]=*(const unsigned*)pb; bf[1]=*(const unsigned*)(pb+8);
                mma16(sacc[j], af, bf);
            }
        }
        #pragma unroll
        for (int j=0;j<16;j++){
            int r = qr0 + (lane>>2);
            int c = n0 + j*8 + ((lane&3)<<1);
            S[r*257 + c]     = sacc[j][0]*0.125f;
            S[r*257 + c + 1] = sacc[j][1]*0.125f;
            S[(r+8)*257 + c]     = sacc[j][2]*0.125f;
            S[(r+8)*257 + c + 1] = sacc[j][3]*0.125f;
        }
    }
    __syncthreads();

    // ---- softmax: max/sum over 256, probs -> Ps (fp16) ----
    {
        const int q = tid & 63, mg = tid >> 6;
        float lmax = -1e30f;
        for (int mi = 0; mi < 64; mi++)
            lmax = fmaxf(lmax, S[q*257 + mg*64 + mi]);
        red[q*4 + mg] = lmax;
        __syncthreads();
        if (tid < 64)
            rowv[tid] = fmaxf(fmaxf(red[tid*4],red[tid*4+1]),
                              fmaxf(red[tid*4+2],red[tid*4+3]));
        __syncthreads();
        float rm = rowv[q];
        float lsum = 0.f;
        for (int mi = 0; mi < 64; mi++){
            int m = mg*64 + mi;
            float e = expf(S[q*257 + m] - rm);
            Ps[q*264 + m] = __float2half(e);
            lsum += e;
        }
        red[q*4 + mg] = lsum;
        __syncthreads();
        if (tid < 64)
            rowv[tid] = 1.0f / (red[tid*4]+red[tid*4+1]+red[tid*4+2]+red[tid*4+3]);
    }
    __syncthreads();

    // ---- output: O = (P @ V) * inv ----
    {
        const int qr0 = (wid & 3) * 16;
        const int d0  = (wid >> 2) * 32;
        float oacc[4][4];
        #pragma unroll
        for (int j=0;j<4;j++){ oacc[j][0]=0;oacc[j][1]=0;oacc[j][2]=0;oacc[j][3]=0; }
        #pragma unroll
        for (int kb=0;kb<16;kb++){
            unsigned af[4];
            const __half* pa = Ps + (qr0 + (lane>>2))*264 + kb*16 + ((lane&3)<<1);
            af[0]=*(const unsigned*)pa;       af[1]=*(const unsigned*)(pa+8*264);
            af[2]=*(const unsigned*)(pa+8);   af[3]=*(const unsigned*)(pa+8*264+8);
            #pragma unroll
            for (int j=0;j<4;j++){
                unsigned bf[2];
                const __half* pb = Vt + (d0 + j*8 + (lane>>2))*264 + kb*16 + ((lane&3)<<1);
                bf[0]=*(const unsigned*)pb; bf[1]=*(const unsigned*)(pb+8);
                mma16(oacc[j], af, bf);
            }
        }
        int r0 = qr0 + (lane>>2);
        float inv0 = rowv[r0], inv1 = rowv[r0+8];
        #pragma unroll
        for (int j=0;j<4;j++){
            int c = d0 + j*8 + ((lane&3)<<1);
            __half* op0 = O + ((long)b_*NTOK + q0 + r0)*C + h*DH + c;
            __half* op1 = O + ((long)b_*NTOK + q0 + r0 + 8)*C + h*DH + c;
            *(__half2*)op0 = __floats2half2_rn(oacc[j][0]*inv0, oacc[j][1]*inv0);
            *(__half2*)op1 = __floats2half2_rn(oacc[j][2]*inv1, oacc[j][3]*inv1);
        }
    }
}

// ------------------------- judger row softmax -----------------------------
__global__ void rowsoftmax_kernel(float* __restrict__ S)
{
    const int row  = blockIdx.x * 8 + (threadIdx.x >> 5);
    const int lane = threadIdx.x & 31;
    float* p = S + (long)row*C + lane*4;
    float4 v = *(const float4*)p;
    float m = fmaxf(fmaxf(v.x,v.y), fmaxf(v.z,v.w));
    #pragma unroll
    for (int o = 16; o > 0; o >>= 1) m = fmaxf(m, __shfl_xor_sync(0xffffffffu, m, o));
    float4 e = make_float4(expf(v.x-m), expf(v.y-m), expf(v.z-m), expf(v.w-m));
    float s = e.x+e.y+e.z+e.w;
    s = warp_sum(s);
    float inv = 1.0f/s;
    e.x*=inv; e.y*=inv; e.z*=inv; e.w*=inv;
    *(float4*)p = e;
}

// ------------------------- elementwise a*s (half out) ---------------------
__global__ void amul_kernel(const __half* __restrict__ a,
                            const float* __restrict__ s,
                            __half* __restrict__ d)
{
    long i = (long)blockIdx.x * 256 + threadIdx.x;
    uint2 av = ((const uint2*)a)[i];
    float4 vs = ((const float4*)s)[i];
    __half2 a0 = *(__half2*)&av.x, a1 = *(__half2*)&av.y;
    float2 f0 = __half22float2(a0), f1 = __half22float2(a1);
    ((uint2*)d)[i] = make_uint2(h2pack(f0.x*vs.x, f0.y*vs.y),
                                h2pack(f1.x*vs.z, f1.y*vs.w));
}

// ------------------------- fused proj weight build ------------------------
__global__ void wfuse_kernel(const float* __restrict__ projw,
                             const float* __restrict__ outw,
                             const float* __restrict__ outb,
                             const float* __restrict__ projb,
                             __half* __restrict__ wfh, float* __restrict__ bc)
{
    const int o = blockIdx.x, t = threadIdx.x;
    float s = 0.f;
    #pragma unroll 4
    for (int j = 0; j < C; j++) s += projw[o*C + j] * outw[j*C + t];
    wfh[o*2*C + t]     = __float2half(s);
    wfh[o*2*C + C + t] = __float2half(projw[o*C + t]);
    __shared__ float red[C];
    red[t] = projw[o*C + t] * outb[t];
    __syncthreads();
    for (int st = 64; st > 0; st >>= 1){
        if (t < st) red[t] += red[t + st];
        __syncthreads();
    }
    if (t == 0) bc[o] = projb[o] + red[0];
}

// ------------------------- constant noise projections ---------------------
__global__ void cknoise_kernel(const float* __restrict__ inw,
                               const float* __restrict__ kn,
                               const float* __restrict__ vn,
                               float* __restrict__ ck, float* __restrict__ cv)
{
    int t = threadIdx.x;
    if (t < 128) {
        const float* w = inw + (long)(C + t)*C;
        float s = 0.f;
        #pragma unroll 4
        for (int j = 0; j < C; j++) s += kn[j]*w[j];
        ck[t] = s;
    } else {
        int c = t - 128;
        const float* w = inw + (long)(2*C + c)*C;
        float s = 0.f;
        #pragma unroll 4
        for (int j = 0; j < C; j++) s += vn[j]*w[j];
        cv[c] = s;
    }
}

// ------------------------- 2-key attention combine (half in/out) ----------
__global__ void combine_kernel(const __half* __restrict__ qkv,
                               const __half* __restrict__ kp1,
                               const __half* __restrict__ vp1,
                               const float* __restrict__ ck,
                               const float* __restrict__ cv,
                               __half* __restrict__ O)
{
    long idx = (long)blockIdx.x * 256 + threadIdx.x;
    long r = idx >> 3;
    int  h = (int)(idx & 7);
    const __half* qp = qkv + r*384 + h*16;
    const __half* k0 = qkv + r*384 + 128 + h*16;
    const __half* v0 = qkv + r*384 + 256 + h*16;
    const __half* k1 = kp1 + r*128 + h*16;
    const __half* v1 = vp1 + r*128 + h*16;
    const float* ckh = ck + h*16;
    const float* cvh = cv + h*16;
    float s0 = 0.f, s1 = 0.f;
    #pragma unroll
    for (int i = 0; i < 16; i++) {
        float qv = __half2float(qp[i]);
        s0 += qv * (__half2float(k0[i]) + ckh[i]);
        s1 += qv * __half2float(k1[i]);
    }
    s0 *= 0.25f; s1 *= 0.25f;
    float mx = fmaxf(s0, s1);
    float e0 = expf(s0-mx), e1 = expf(s1-mx);
    float inv = 1.0f/(e0+e1);
    float a0 = e0*inv, a1 = e1*inv;
    __half* op = O + r*128 + h*16;
    #pragma unroll
    for (int i = 0; i < 16; i += 2)
        *(__half2*)(op + i) = __floats2half2_rn(
            a0*(__half2float(v0[i]) + cvh[i]) + a1*__half2float(v1[i]),
            a0*(__half2float(v0[i+1]) + cvh[i+1]) + a1*__half2float(v1[i+1]));
}

// ------------------------- host driver ------------------------------------
static void run_mma(const __half* A, const __half* A2,
                    const __half* W, int ldw,
                    const float* bias, float* D, __half* Dh,
                    int Ncols, int Ktot, int flags)
{
    dim3 g(NT/256, Ncols/128);
    mma_gemm<<<g, 512, MMA_SMEM_BYTES>>>(A, A2, W, ldw, bias, D, Dh, Ncols, Ktot, flags);
}

extern "C" void kernel_launch(void* const* d_in, const int* in_sizes, int n_in,
                              void* d_out, int out_size)
{
    const float* x0       = (const float*)d_in[0];
    const float* x1       = (const float*)d_in[1];
    const float* Wq       = (const float*)d_in[2];
    const float* bq       = (const float*)d_in[3];
    const float* Wkv      = (const float*)d_in[4];
    const float* bkv      = (const float*)d_in[5];
    const float* sr_w     = (const float*)d_in[6];
    const float* sr_b     = (const float*)d_in[7];
    const float* ln_g[2]  = {(const float*)d_in[8],  (const float*)d_in[10]};
    const float* ln_b[2]  = {(const float*)d_in[9],  (const float*)d_in[11]};
    const float* in_w[2]  = {(const float*)d_in[12], (const float*)d_in[16]};
    const float* in_b[2]  = {(const float*)d_in[13], (const float*)d_in[17]};
    const float* out_w[2] = {(const float*)d_in[14], (const float*)d_in[18]};
    const float* out_b[2] = {(const float*)d_in[15], (const float*)d_in[19]};
    const float* rj_w1    = (const float*)d_in[20];
    const float* rj_b1    = (const float*)d_in[21];
    const float* rj_w2    = (const float*)d_in[22];
    const float* rj_b2    = (const float*)d_in[23];
    const float* k_noise  = (const float*)d_in[24];
    const float* v_noise  = (const float*)d_in[25];
    const float* proj_w   = (const float*)d_in[26];
    const float* proj_b   = (const float*)d_in[27];

    __half *xh, *xim, *xah0, *xah1, *hh, *oh, *qh, *qkvh, *kp1h, *vp1h;
    __half *wqh, *rj1h, *rj2h, *inwh0, *inwh1, *wfh, *wim, *Kh, *VtG;
    float *s, *cpart, *xi, *kv, *ck, *cv, *bc;
    cudaGetSymbolAddress((void**)&xh,    g_xh);
    cudaGetSymbolAddress((void**)&xim,   g_xim);
    cudaGetSymbolAddress((void**)&xah0,  g_xah0);
    cudaGetSymbolAddress((void**)&xah1,  g_xah1);
    cudaGetSymbolAddress((void**)&hh,    g_hh);
    cudaGetSymbolAddress((void**)&oh,    g_oh);
    cudaGetSymbolAddress((void**)&qh,    g_qh);
    cudaGetSymbolAddress((void**)&qkvh,  g_qkvh);
    cudaGetSymbolAddress((void**)&kp1h,  g_kp1h);
    cudaGetSymbolAddress((void**)&vp1h,  g_vp1h);
    cudaGetSymbolAddress((void**)&wqh,   g_wqh);
    cudaGetSymbolAddress((void**)&rj1h,  g_rj1h);
    cudaGetSymbolAddress((void**)&rj2h,  g_rj2h);
    cudaGetSymbolAddress((void**)&inwh0, g_inwh0);
    cudaGetSymbolAddress((void**)&inwh1, g_inwh1);
    cudaGetSymbolAddress((void**)&wfh,   g_wfh);
    cudaGetSymbolAddress((void**)&wim,   g_wim);
    cudaGetSymbolAddress((void**)&Kh,    g_Kh);
    cudaGetSymbolAddress((void**)&VtG,   g_VtG);
    cudaGetSymbolAddress((void**)&s,     g_s);
    cudaGetSymbolAddress((void**)&cpart, g_cpart);
    cudaGetSymbolAddress((void**)&xi,    g_xi);
    cudaGetSymbolAddress((void**)&kv,    g_kv);
    cudaGetSymbolAddress((void**)&ck,    g_ck);
    cudaGetSymbolAddress((void**)&cv,    g_cv);
    cudaGetSymbolAddress((void**)&bc,    g_bc);

    cudaFuncSetAttribute(attn_mma, cudaFuncAttributeMaxDynamicSharedMemorySize, ATTN2_SMEM);
    cudaFuncSetAttribute(mma_gemm, cudaFuncAttributeMaxDynamicSharedMemorySize, MMA_SMEM_BYTES);

    __half* xah[2] = {xah0, xah1};
    __half* inwh[2] = {inwh0, inwh1};
    const float* xin[2] = {x0, x1};

    // ---- weight conversions (once) ----
    convh_kernel<<<(C*C/4+255)/256, 256>>>(Wq, wqh, C*C/4);
    convh_kernel<<<(2*C*C/4+255)/256, 256>>>(rj_w1, rj1h, 2*C*C/4);
    convh_kernel<<<(C*C/4+255)/256, 256>>>(rj_w2, rj2h, C*C/4);
    convh_kernel<<<(3*C*C/4+255)/256, 256>>>(in_w[0], inwh0, 3*C*C/4);
    convh_kernel<<<(3*C*C/4+255)/256, 256>>>(in_w[1], inwh1, 3*C*C/4);
    wim_kernel<<<(C*KCONV)/256, 256>>>(sr_w, wim);

    // ---- stage A ----
    for (int im = 0; im < 2; im++) {
        convh_kernel<<<(NT*C/4)/256, 256>>>(xin[im], xh, NT*C/4);
        im2col_kernel<<<(BM*KCONV/4)/256, 256>>>(xin[im], xim);
        run_mma(xh, nullptr, wqh, C, bq, nullptr, qh, C, C, 0);
        conv_mma<<<dim3(16, 1, KSPLIT), 256>>>(xim, wim, cpart);
        conv_reduce_kernel<<<(BM*C + 255)/256, 256>>>(cpart, sr_b, xi);
        ln_kernel<<<BM, 128>>>(xi, ln_g[im], ln_b[im]);
        gemm_kernel<<<dim3(BM/64, (2*C)/64), 256>>>(xi, Wkv, C, bkv, kv, 2*C, C);
        kvprep_kernel<<<BB*HEADS*M*DH/256, 256>>>(kv, Kh, VtG);
        attn_mma<<<dim3(NTOK/64, HEADS, BB), 256, ATTN2_SMEM>>>(qh, Kh, VtG, xah[im]);
    }

    // ---- stage B ----
    for (int d = 0; d < 2; d++) {
        const __half* a  = xah[d];
        const __half* bb = xah[1-d];
        float* dst = (float*)d_out + (size_t)d * NT * C;

        run_mma(a, bb, rj1h, 2*C, rj_b1, nullptr, hh, C, 2*C, F_GELU);
        run_mma(hh, nullptr, rj2h, C, rj_b2, s, nullptr, C, C, 0);
        rowsoftmax_kernel<<<NT/8, 256>>>(s);

        cknoise_kernel<<<1, 256>>>(in_w[d], k_noise + d*C, v_noise + d*C, ck, cv);
        amul_kernel<<<NT*C/4/256, 256>>>(a, s, hh);   // hh := a*s

        run_mma(a,  nullptr, inwh[d],         C, in_b[d],       nullptr, qkvh, 3*C, C, 0);
        run_mma(hh, nullptr, inwh[d] + C*C,   C, in_b[d] + C,   nullptr, kp1h, C,   C, 0);
        run_mma(bb, nullptr, inwh[d] + 2*C*C, C, in_b[d] + 2*C, nullptr, vp1h, C,   C, 0);

        combine_kernel<<<(long)NT*XH/256, 256>>>(qkvh, kp1h, vp1h, ck, cv, oh);

        wfuse_kernel<<<C, C>>>(proj_w, out_w[d], out_b[d], proj_b, wfh, bc);
        run_mma(oh, a, wfh, 2*C, bc, dst, nullptr, C, 2*C, 0);
    }
}

// round 10
// speedup vs baseline: 4.0326x; 1.1056x over previous
#include <cuda_runtime.h>
#include <cuda_fp16.h>
#include <math.h>
#include <cstdint>

#define BB 4
#define NTOK 16384
#define C 128
#define NT (BB*NTOK)
#define NTC (NT*C)
#define M 256
#define BM (BB*M)
#define HEADS 2
#define DH 64
#define XH 8
#define KCONV 8192
#define KSPLIT 8

#define F_GELU  2

// ------------------------- scratch (x2 for image/direction batching) -----
__device__ __align__(256) __half g_xh  [2*NTC];
__device__ __align__(256) __half g_xim [(size_t)2*BM*KCONV];
__device__ __align__(256) __half g_xah [2*NTC];
__device__ __align__(256) __half g_hh  [2*NTC];
__device__ __align__(256) __half g_oh  [2*NTC];
__device__ __align__(256) __half g_qh  [2*NTC];
__device__ __align__(256) __half g_qkvh[(size_t)2*NT*3*C];
__device__ __align__(256) __half g_kp1h[2*NTC];
__device__ __align__(256) __half g_vp1h[2*NTC];
__device__ __align__(256) __half g_wqh [C*C];
__device__ __align__(256) __half g_rj1h[2*C*C];
__device__ __align__(256) __half g_rj2h[C*C];
__device__ __align__(256) __half g_inwh[2*3*C*C];
__device__ __align__(256) __half g_wfh [2*2*C*C];
__device__ __align__(256) __half g_wim [(size_t)C*KCONV];
__device__ __align__(256) __half g_Kh  [2*BB*HEADS*M*DH];
__device__ __align__(256) __half g_VtG [2*BB*HEADS*DH*M];

__device__ __align__(256) float g_s  [2*NTC];
__device__ __align__(256) float g_cpart[(size_t)2*KSPLIT*BM*C];
__device__ __align__(256) float g_xi [2*BM*C];
__device__ __align__(256) float g_kv [2*BM*2*C];
__device__ __align__(256) float g_ck [2*C];
__device__ __align__(256) float g_cv [2*C];
__device__ __align__(256) float g_bc [2*C];

// ------------------------- helpers ---------------------------------------
__device__ __forceinline__ float gelu_exact(float v){
    return 0.5f * v * (1.0f + erff(v * 0.70710678118654752f));
}
__device__ __forceinline__ float warp_sum(float v){
    #pragma unroll
    for (int o = 16; o > 0; o >>= 1) v += __shfl_xor_sync(0xffffffffu, v, o);
    return v;
}
__device__ __forceinline__ void mma16(float* c, const unsigned* a, const unsigned* b){
    asm("mma.sync.aligned.m16n8k16.row.col.f32.f16.f16.f32 "
        "{%0,%1,%2,%3}, {%4,%5,%6,%7}, {%8,%9}, {%0,%1,%2,%3};"
        : "+f"(c[0]),"+f"(c[1]),"+f"(c[2]),"+f"(c[3])
        : "r"(a[0]),"r"(a[1]),"r"(a[2]),"r"(a[3]), "r"(b[0]),"r"(b[1]));
}
__device__ __forceinline__ unsigned h2pack(float lo, float hi){
    __half2 h = __floats2half2_rn(lo, hi);
    return *(unsigned*)&h;
}
__device__ __forceinline__ void cpa16(const __half* g, __half* s){
    unsigned sa = (unsigned)__cvta_generic_to_shared(s);
    asm volatile("cp.async.ca.shared.global [%0],[%1],16;\n" :: "r"(sa), "l"(g));
}

// ===================== batched fp16 tensor-core GEMM ======================
struct Ent {
    const __half* A; const __half* A2; const __half* W;
    const float* bias; float* D; __half* Dh;
    int ldw; int ldd;
};
struct Batch10 { Ent e[10]; };

#define AST 40
#define BST 40
#define MMA_SMEM_BYTES ((2*256*AST + 2*128*BST)*2)

__global__ void __launch_bounds__(512, 1) mma_gemmB(
    Batch10 bt, int Ktot, int flags)
{
    extern __shared__ __half smh[];
    __half* smA = smh;
    __half* smB = smh + 2*256*AST;

    const Ent E = bt.e[blockIdx.z];
    const int tid = threadIdx.x;
    const int lane = tid & 31, wid = tid >> 5;
    const int wm = wid >> 2, wn = wid & 3;
    const long row0 = (long)blockIdx.x * 256;

    float acc[4][4][4];
    #pragma unroll
    for (int i=0;i<4;i++)
        #pragma unroll
        for (int j=0;j<4;j++)
            #pragma unroll
            for (int t=0;t<4;t++) acc[i][j][t]=0.f;

    const int nch = Ktot >> 5;

    auto issue = [&](int ch){
        const int kk = ch*32;
        const __half* Asrc = (kk < 128) ? E.A : E.A2;
        const int kc = kk & 127;
        __half* Ab = smA + (ch&1)*(256*AST);
        __half* Bb = smB + (ch&1)*(128*BST);
        #pragma unroll
        for (int t=0;t<2;t++){
            int s = tid + t*512;
            int row = s >> 2, q8 = (s & 3) << 3;
            cpa16(Asrc + (row0+row)*128 + kc + q8, Ab + row*AST + q8);
        }
        {
            int row = tid >> 2, q8 = (tid & 3) << 3;
            cpa16(E.W + (long)row*E.ldw + kk + q8, Bb + row*BST + q8);
        }
        asm volatile("cp.async.commit_group;\n");
    };

    issue(0);
    if (nch > 1) issue(1);

    for (int ch = 0; ch < nch; ch++){
        if (ch+1 < nch) asm volatile("cp.async.wait_group 1;\n" ::: "memory");
        else            asm volatile("cp.async.wait_group 0;\n" ::: "memory");
        __syncthreads();
        const __half* Ab = smA + (ch&1)*(256*AST);
        const __half* Bb = smB + (ch&1)*(128*BST);
        #pragma unroll
        for (int kb=0;kb<2;kb++){
            unsigned af[4][4], bf[4][2];
            #pragma unroll
            for (int i=0;i<4;i++){
                const __half* p = Ab + (wm*64 + i*16 + (lane>>2))*AST
                                + kb*16 + ((lane&3)<<1);
                af[i][0] = *(const unsigned*)p;
                af[i][1] = *(const unsigned*)(p + 8*AST);
                af[i][2] = *(const unsigned*)(p + 8);
                af[i][3] = *(const unsigned*)(p + 8*AST + 8);
            }
            #pragma unroll
            for (int j=0;j<4;j++){
                const __half* p = Bb + (wn*32 + j*8 + (lane>>2))*BST
                                + kb*16 + ((lane&3)<<1);
                bf[j][0] = *(const unsigned*)p;
                bf[j][1] = *(const unsigned*)(p + 8);
            }
            #pragma unroll
            for (int i=0;i<4;i++)
                #pragma unroll
                for (int j=0;j<4;j++)
                    mma16(acc[i][j], af[i], bf[j]);
        }
        __syncthreads();
        if (ch+2 < nch) issue(ch+2);
    }

    #pragma unroll
    for (int i=0;i<4;i++){
        long r = row0 + wm*64 + i*16 + (lane>>2);
        #pragma unroll
        for (int j=0;j<4;j++){
            int cc = wn*32 + j*8 + ((lane&3)<<1);
            float2 v0 = make_float2(acc[i][j][0], acc[i][j][1]);
            float2 v1 = make_float2(acc[i][j][2], acc[i][j][3]);
            if (E.bias){
                float2 b2 = *(const float2*)(E.bias + cc);
                v0.x+=b2.x; v0.y+=b2.y; v1.x+=b2.x; v1.y+=b2.y;
            }
            if (flags & F_GELU){
                v0.x=gelu_exact(v0.x); v0.y=gelu_exact(v0.y);
                v1.x=gelu_exact(v1.x); v1.y=gelu_exact(v1.y);
            }
            if (E.D){
                *(float2*)(E.D + r*(long)E.ldd + cc) = v0;
                *(float2*)(E.D + (r+8)*(long)E.ldd + cc) = v1;
            }
            if (E.Dh){
                *(__half2*)(E.Dh + r*(long)E.ldd + cc) = __floats2half2_rn(v0.x, v0.y);
                *(__half2*)(E.Dh + (r+8)*(long)E.ldd + cc) = __floats2half2_rn(v1.x, v1.y);
            }
        }
    }
}

// ===================== conv as split-K fp16 MMA (2 images) ================
__global__ void __launch_bounds__(256) conv_mma(
    const __half* __restrict__ AimG, const __half* __restrict__ Wim,
    float* __restrict__ partG)
{
    __shared__ __half sA[2][64*AST];
    __shared__ __half sB[2][128*BST];
    const int tid = threadIdx.x, lane = tid & 31, wid = tid >> 5;
    const int wm = wid >> 2, wn = wid & 3;
    const int row0 = blockIdx.x * 64;
    const int kz  = blockIdx.z & 7;
    const int img = blockIdx.z >> 3;
    const __half* Aim = AimG + (size_t)img*BM*KCONV;
    float* part = partG + (size_t)img*KSPLIT*BM*C;
    const long Kb = (long)kz * 1024;

    float acc[2][4][4];
    #pragma unroll
    for (int i=0;i<2;i++)
        #pragma unroll
        for (int j=0;j<4;j++)
            #pragma unroll
            for (int t=0;t<4;t++) acc[i][j][t]=0.f;

    auto issue = [&](int ch){
        int kk = ch*32;
        {
            int row = tid >> 2, q8 = (tid & 3) << 3;
            if (row < 64)
                cpa16(Aim + (long)(row0+row)*KCONV + Kb + kk + q8,
                      &sA[ch&1][row*AST + q8]);
        }
        #pragma unroll
        for (int t=0;t<2;t++){
            int s = tid + t*256;
            int row = s >> 2, q8 = (s & 3) << 3;
            cpa16(Wim + (long)row*KCONV + Kb + kk + q8,
                  &sB[ch&1][row*BST + q8]);
        }
        asm volatile("cp.async.commit_group;\n");
    };

    issue(0); issue(1);
    for (int ch = 0; ch < 32; ch++){
        if (ch < 31) asm volatile("cp.async.wait_group 1;\n" ::: "memory");
        else         asm volatile("cp.async.wait_group 0;\n" ::: "memory");
        __syncthreads();
        const __half* Ab = sA[ch&1];
        const __half* Bb = sB[ch&1];
        #pragma unroll
        for (int kb=0;kb<2;kb++){
            unsigned af[2][4], bf[4][2];
            #pragma unroll
            for (int i=0;i<2;i++){
                const __half* p = Ab + (wm*32 + i*16 + (lane>>2))*AST
                                + kb*16 + ((lane&3)<<1);
                af[i][0] = *(const unsigned*)p;
                af[i][1] = *(const unsigned*)(p + 8*AST);
                af[i][2] = *(const unsigned*)(p + 8);
                af[i][3] = *(const unsigned*)(p + 8*AST + 8);
            }
            #pragma unroll
            for (int j=0;j<4;j++){
                const __half* p = Bb + (wn*32 + j*8 + (lane>>2))*BST
                                + kb*16 + ((lane&3)<<1);
                bf[j][0] = *(const unsigned*)p;
                bf[j][1] = *(const unsigned*)(p + 8);
            }
            #pragma unroll
            for (int i=0;i<2;i++)
                #pragma unroll
                for (int j=0;j<4;j++)
                    mma16(acc[i][j], af[i], bf[j]);
        }
        __syncthreads();
        if (ch+2 < 32) issue(ch+2);
    }

    #pragma unroll
    for (int i=0;i<2;i++){
        int r = row0 + wm*32 + i*16 + (lane>>2);
        #pragma unroll
        for (int j=0;j<4;j++){
            int cc = wn*32 + j*8 + ((lane&3)<<1);
            *(float2*)(part + ((long)kz*BM + r)*C + cc)
                = make_float2(acc[i][j][0], acc[i][j][1]);
            *(float2*)(part + ((long)kz*BM + r + 8)*C + cc)
                = make_float2(acc[i][j][2], acc[i][j][3]);
        }
    }
}

// ------------------------- conversions / gathers (2 images) ---------------
__global__ void convh2_kernel(const float* __restrict__ x0,
                              const float* __restrict__ x1,
                              __half* __restrict__ d)
{
    int i = blockIdx.x * 256 + threadIdx.x;
    int img = blockIdx.y;
    const float* src = img ? x1 : x0;
    float4 v = ((const float4*)src)[i];
    ((uint2*)(d + (size_t)img*NTC))[i] =
        make_uint2(h2pack(v.x,v.y), h2pack(v.z,v.w));
}

__global__ void im2col_kernel(const float* __restrict__ x0,
                              const float* __restrict__ x1,
                              __half* __restrict__ ximG)
{
    int idx = blockIdx.x * 256 + threadIdx.x;
    int img = blockIdx.y;
    const float* x = img ? x1 : x0;
    __half* xim = ximG + (size_t)img*BM*KCONV;
    int r = idx >> 11, rem = idx & 2047;
    int k4 = rem << 2;
    int khkw = k4 >> 7, i = k4 & 127;
    int b = r >> 8, p = r & 255, ph = p >> 4, pw = p & 15;
    int kh = khkw >> 3, kw = khkw & 7;
    const float* src = x + ((long)(b*NTOK + (ph*8+kh)*128 + pw*8+kw))*C + i;
    float4 v = *(const float4*)src;
    ((uint2*)(xim + (long)r*KCONV + k4))[0] =
        make_uint2(h2pack(v.x,v.y), h2pack(v.z,v.w));
}

__global__ void wim_kernel(const float* __restrict__ srw,
                           __half* __restrict__ wim)
{
    int idx = blockIdx.x * 256 + threadIdx.x;
    int o = idx >> 13, k = idx & 8191;
    int khkw = k >> 7, i = k & 127;
    int kh = khkw >> 3, kw = khkw & 7;
    wim[idx] = __float2half(srw[(long)o*KCONV + i*64 + kh*8 + kw]);
}

// fused conv-reduce + bias + layernorm (both images)
__global__ void redln_kernel(const float* __restrict__ partG,
                             const float* __restrict__ srb,
                             const float* __restrict__ g0, const float* __restrict__ b0,
                             const float* __restrict__ g1, const float* __restrict__ b1,
                             float* __restrict__ xiG)
{
    const int row = blockIdx.x;          // 0 .. 2*BM-1
    const int img = row >> 10, r = row & 1023;
    const int t = threadIdx.x;
    const float* part = partG + (size_t)img*KSPLIT*BM*C;
    const float* g = img ? g1 : g0;
    const float* b = img ? b1 : b0;

    float v = srb[t];
    #pragma unroll
    for (int z = 0; z < KSPLIT; z++) v += part[(long)z*BM*C + r*C + t];

    __shared__ float red[4];
    __shared__ float mv[2];
    float s = warp_sum(v);
    if ((t & 31) == 0) red[t >> 5] = s;
    __syncthreads();
    if (t == 0) mv[0] = (red[0]+red[1]+red[2]+red[3]) * (1.0f/C);
    __syncthreads();
    float d = v - mv[0];
    float s2 = warp_sum(d*d);
    if ((t & 31) == 0) red[t >> 5] = s2;
    __syncthreads();
    if (t == 0) mv[1] = (red[0]+red[1]+red[2]+red[3]) * (1.0f/C);
    __syncthreads();
    xiG[(size_t)img*BM*C + r*C + t] = d * rsqrtf(mv[1] + 1e-5f) * g[t] + b[t];
}

// kvprep both images
__global__ void kvprep_kernel(const float* __restrict__ kvG,
                              __half* __restrict__ KhG, __half* __restrict__ VtGG)
{
    int idx = blockIdx.x * 256 + threadIdx.x;   // 2*131072
    int img = idx >> 17;
    int l = idx & 131071;
    int d = l & 63, m = (l >> 6) & 255, bh = l >> 14;
    int b = bh >> 1, h = bh & 1;
    const float* base = kvG + (size_t)img*BM*2*C + ((long)(b*M + m))*(2*C) + h*DH + d;
    KhG[(size_t)img*BB*HEADS*M*DH + (long)bh*M*DH + m*DH + d] = __float2half(base[0]);
    VtGG[(size_t)img*BB*HEADS*DH*M + (long)bh*DH*M + d*M + m]  = __float2half(base[C]);
}

// ------------------------- scalar GEMM (kv proj, both images) -------------
__global__ void __launch_bounds__(256) gemm_kernel(
    const float* __restrict__ AG,
    const float* __restrict__ W,
    const float* __restrict__ bias,
    float* __restrict__ DG)
{
    __shared__ float As[16][64];
    __shared__ float Ws[16][64];
    const int tid = threadIdx.x;
    const int tx = tid & 15, ty = tid >> 4;
    const int img = blockIdx.z;
    const float* A = AG + (size_t)img*BM*C;
    float* D = DG + (size_t)img*BM*2*C;
    const long row0 = (long)blockIdx.x * 64;
    const int  col0 = blockIdx.y * 64;
    const int lr = tid >> 2;
    const int lk = (tid & 3) << 2;

    const float* Arow  = A + (row0 + lr) * (long)C + lk;
    const float* Wrow  = W + (long)(col0 + lr) * C + lk;

    float acc[4][4] = {};
    for (int kk = 0; kk < C; kk += 16) {
        float4 av = *(const float4*)(Arow + kk);
        float4 wv = *(const float4*)(Wrow + kk);
        As[lk+0][lr]=av.x; As[lk+1][lr]=av.y; As[lk+2][lr]=av.z; As[lk+3][lr]=av.w;
        Ws[lk+0][lr]=wv.x; Ws[lk+1][lr]=wv.y; Ws[lk+2][lr]=wv.z; Ws[lk+3][lr]=wv.w;
        __syncthreads();
        #pragma unroll
        for (int k = 0; k < 16; k++) {
            float ar[4], br[4];
            *(float4*)ar = *(const float4*)&As[k][ty<<2];
            *(float4*)br = *(const float4*)&Ws[k][tx<<2];
            #pragma unroll
            for (int i = 0; i < 4; i++)
                #pragma unroll
                for (int j = 0; j < 4; j++)
                    acc[i][j] += ar[i] * br[j];
        }
        __syncthreads();
    }
    #pragma unroll
    for (int i = 0; i < 4; i++) {
        long r = row0 + (ty<<2) + i;
        int  c = col0 + (tx<<2);
        float4 v = make_float4(acc[i][0],acc[i][1],acc[i][2],acc[i][3]);
        v.x+=bias[c]; v.y+=bias[c+1]; v.z+=bias[c+2]; v.w+=bias[c+3];
        *(float4*)(D + r * (long)(2*C) + c) = v;
    }
}

// ===================== SR attention via fp16 MMA (2 images) ===============
#define ATTN2_SMEM (64*257*4 + 256*4 + 64*4 + (64*72 + 256*72 + 64*264 + 64*264)*2)

__global__ void __launch_bounds__(256, 1) attn_mma(
    const __half* __restrict__ QhG, const __half* __restrict__ KhG,
    const __half* __restrict__ VtGG, __half* __restrict__ OG)
{
    extern __shared__ char sm2[];
    float* S    = (float*)sm2;
    float* red  = S + 64*257;
    float* rowv = red + 256;
    __half* Qs  = (__half*)(rowv + 64);
    __half* Ks  = Qs + 64*72;
    __half* Ps  = Ks + 256*72;
    __half* Vt  = Ps + 64*264;

    const int tid = threadIdx.x, lane = tid & 31, wid = tid >> 5;
    const int h = blockIdx.y;
    const int z = blockIdx.z;
    const int b_ = z & 3, img = z >> 2;
    const int q0 = blockIdx.x * 64;
    const int bh = b_*HEADS + h;

    const __half* Qh = QhG + (size_t)img*NTC;
    const __half* KhB = KhG + (size_t)img*BB*HEADS*M*DH;
    const __half* VtB = VtGG + (size_t)img*BB*HEADS*DH*M;
    __half* O = OG + (size_t)img*NTC;

    #pragma unroll
    for (int t = 0; t < 2; t++){
        int e = tid + t*256;
        int row = e >> 3, c8 = (e & 7) << 3;
        *(uint4*)&Qs[row*72 + c8] =
            *(const uint4*)(Qh + ((long)b_*NTOK + q0 + row)*C + h*DH + c8);
    }
    #pragma unroll
    for (int t = 0; t < 8; t++){
        int e = tid + t*256;
        int row = e >> 3, c8 = (e & 7) << 3;
        *(uint4*)&Ks[row*72 + c8] =
            *(const uint4*)(KhB + (long)bh*M*DH + row*DH + c8);
    }
    #pragma unroll
    for (int t = 0; t < 8; t++){
        int e = tid + t*256;
        int row = e >> 5, c8 = (e & 31) << 3;
        *(uint4*)&Vt[row*264 + c8] =
            *(const uint4*)(VtB + (long)bh*DH*M + row*M + c8);
    }
    __syncthreads();

    {
        const int qr0 = (wid & 3) * 16;
        const int n0  = (wid >> 2) * 128;
        float sacc[16][4];
        #pragma unroll
        for (int j=0;j<16;j++){ sacc[j][0]=0;sacc[j][1]=0;sacc[j][2]=0;sacc[j][3]=0; }
        #pragma unroll
        for (int kb=0;kb<4;kb++){
            unsigned af[4];
            const __half* pa = Qs + (qr0 + (lane>>2))*72 + kb*16 + ((lane&3)<<1);
            af[0]=*(const unsigned*)pa;       af[1]=*(const unsigned*)(pa+8*72);
            af[2]=*(const unsigned*)(pa+8);   af[3]=*(const unsigned*)(pa+8*72+8);
            #pragma unroll
            for (int j=0;j<16;j++){
                unsigned bf[2];
                const __half* pb = Ks + (n0 + j*8 + (lane>>2))*72 + kb*16 + ((lane&3)<<1);
                bf[0]=*(const unsigned*)pb; bf[1]=*(const unsigned*)(pb+8);
                mma16(sacc[j], af, bf);
            }
        }
        #pragma unroll
        for (int j=0;j<16;j++){
            int r = qr0 + (lane>>2);
            int c = n0 + j*8 + ((lane&3)<<1);
            S[r*257 + c]     = sacc[j][0]*0.125f;
            S[r*257 + c + 1] = sacc[j][1]*0.125f;
            S[(r+8)*257 + c]     = sacc[j][2]*0.125f;
            S[(r+8)*257 + c + 1] = sacc[j][3]*0.125f;
        }
    }
    __syncthreads();

    {
        const int q = tid & 63, mg = tid >> 6;
        float lmax = -1e30f;
        for (int mi = 0; mi < 64; mi++)
            lmax = fmaxf(lmax, S[q*257 + mg*64 + mi]);
        red[q*4 + mg] = lmax;
        __syncthreads();
        if (tid < 64)
            rowv[tid] = fmaxf(fmaxf(red[tid*4],red[tid*4+1]),
                              fmaxf(red[tid*4+2],red[tid*4+3]));
        __syncthreads();
        float rm = rowv[q];
        float lsum = 0.f;
        for (int mi = 0; mi < 64; mi++){
            int m = mg*64 + mi;
            float e = expf(S[q*257 + m] - rm);
            Ps[q*264 + m] = __float2half(e);
            lsum += e;
        }
        red[q*4 + mg] = lsum;
        __syncthreads();
        if (tid < 64)
            rowv[tid] = 1.0f / (red[tid*4]+red[tid*4+1]+red[tid*4+2]+red[tid*4+3]);
    }
    __syncthreads();

    {
        const int qr0 = (wid & 3) * 16;
        const int d0  = (wid >> 2) * 32;
        float oacc[4][4];
        #pragma unroll
        for (int j=0;j<4;j++){ oacc[j][0]=0;oacc[j][1]=0;oacc[j][2]=0;oacc[j][3]=0; }
        #pragma unroll
        for (int kb=0;kb<16;kb++){
            unsigned af[4];
            const __half* pa = Ps + (qr0 + (lane>>2))*264 + kb*16 + ((lane&3)<<1);
            af[0]=*(const unsigned*)pa;       af[1]=*(const unsigned*)(pa+8*264);
            af[2]=*(const unsigned*)(pa+8);   af[3]=*(const unsigned*)(pa+8*264+8);
            #pragma unroll
            for (int j=0;j<4;j++){
                unsigned bf[2];
                const __half* pb = Vt + (d0 + j*8 + (lane>>2))*264 + kb*16 + ((lane&3)<<1);
                bf[0]=*(const unsigned*)pb; bf[1]=*(const unsigned*)(pb+8);
                mma16(oacc[j], af, bf);
            }
        }
        int r0 = qr0 + (lane>>2);
        float inv0 = rowv[r0], inv1 = rowv[r0+8];
        #pragma unroll
        for (int j=0;j<4;j++){
            int c = d0 + j*8 + ((lane&3)<<1);
            __half* op0 = O + ((long)b_*NTOK + q0 + r0)*C + h*DH + c;
            __half* op1 = O + ((long)b_*NTOK + q0 + r0 + 8)*C + h*DH + c;
            *(__half2*)op0 = __floats2half2_rn(oacc[j][0]*inv0, oacc[j][1]*inv0);
            *(__half2*)op1 = __floats2half2_rn(oacc[j][2]*inv1, oacc[j][3]*inv1);
        }
    }
}

// ---------------- fused judger softmax + a*s (both directions) ------------
__global__ void smax_amul_kernel(const float* __restrict__ sG,
                                 const __half* __restrict__ xahG,
                                 __half* __restrict__ hhG)
{
    const int d = blockIdx.y;
    const long row = (long)blockIdx.x * 8 + (threadIdx.x >> 5);
    const int lane = threadIdx.x & 31;
    const float* p = sG + (size_t)d*NTC + row*C + lane*4;
    float4 v = *(const float4*)p;
    float m = fmaxf(fmaxf(v.x,v.y), fmaxf(v.z,v.w));
    #pragma unroll
    for (int o = 16; o > 0; o >>= 1) m = fmaxf(m, __shfl_xor_sync(0xffffffffu, m, o));
    float4 e = make_float4(expf(v.x-m), expf(v.y-m), expf(v.z-m), expf(v.w-m));
    float s = e.x+e.y+e.z+e.w;
    s = warp_sum(s);
    float inv = 1.0f/s;
    const __half* a = xahG + (size_t)d*NTC + row*C + lane*4;
    uint2 av = *(const uint2*)a;
    float2 f0 = __half22float2(*(__half2*)&av.x);
    float2 f1 = __half22float2(*(__half2*)&av.y);
    uint2 out = make_uint2(h2pack(f0.x*e.x*inv, f0.y*e.y*inv),
                           h2pack(f1.x*e.z*inv, f1.y*e.w*inv));
    *(uint2*)(hhG + (size_t)d*NTC + row*C + lane*4) = out;
}

// ------------------------- weight-prep kernels ----------------------------
__global__ void convh_kernel(const float* __restrict__ s,
                             __half* __restrict__ d, int n4)
{
    int i = blockIdx.x * 256 + threadIdx.x;
    if (i < n4){
        float4 v = ((const float4*)s)[i];
        ((uint2*)d)[i] = make_uint2(h2pack(v.x,v.y), h2pack(v.z,v.w));
    }
}

__global__ void wfuse_kernel(const float* __restrict__ projw,
                             const float* __restrict__ outw0,
                             const float* __restrict__ outb0,
                             const float* __restrict__ outw1,
                             const float* __restrict__ outb1,
                             const float* __restrict__ projb,
                             __half* __restrict__ wfhG, float* __restrict__ bcG)
{
    const int o = blockIdx.x, t = threadIdx.x, d = blockIdx.y;
    const float* outw = d ? outw1 : outw0;
    const float* outb = d ? outb1 : outb0;
    __half* wfh = wfhG + (size_t)d*2*C*C;
    float* bc = bcG + d*C;
    float s = 0.f;
    #pragma unroll 4
    for (int j = 0; j < C; j++) s += projw[o*C + j] * outw[j*C + t];
    wfh[o*2*C + t]     = __float2half(s);
    wfh[o*2*C + C + t] = __float2half(projw[o*C + t]);
    __shared__ float red[C];
    red[t] = projw[o*C + t] * outb[t];
    __syncthreads();
    for (int st = 64; st > 0; st >>= 1){
        if (t < st) red[t] += red[t + st];
        __syncthreads();
    }
    if (t == 0) bc[o] = projb[o] + red[0];
}

__global__ void cknoise_kernel(const float* __restrict__ inw0,
                               const float* __restrict__ inw1,
                               const float* __restrict__ kn,
                               const float* __restrict__ vn,
                               float* __restrict__ ckG, float* __restrict__ cvG)
{
    int t = threadIdx.x, d = blockIdx.x;
    const float* inw = d ? inw1 : inw0;
    if (t < 128) {
        const float* w = inw + (long)(C + t)*C;
        float s = 0.f;
        #pragma unroll 4
        for (int j = 0; j < C; j++) s += kn[d*C + j]*w[j];
        ckG[d*C + t] = s;
    } else {
        int c = t - 128;
        const float* w = inw + (long)(2*C + c)*C;
        float s = 0.f;
        #pragma unroll 4
        for (int j = 0; j < C; j++) s += vn[d*C + j]*w[j];
        cvG[d*C + c] = s;
    }
}

// ------------------------- 2-key combine (both directions) ----------------
__global__ void combine_kernel(const __half* __restrict__ qkvG,
                               const __half* __restrict__ kp1G,
                               const __half* __restrict__ vp1G,
                               const float* __restrict__ ckG,
                               const float* __restrict__ cvG,
                               __half* __restrict__ OG)
{
    const int d = blockIdx.y;
    long idx = (long)blockIdx.x * 256 + threadIdx.x;
    long r = idx >> 3;
    int  h = (int)(idx & 7);
    const __half* qp = qkvG + (size_t)d*NT*3*C + r*384 + h*16;
    const __half* k0 = qp + 128;
    const __half* v0 = qp + 256;
    const __half* k1 = kp1G + (size_t)d*NTC + r*128 + h*16;
    const __half* v1 = vp1G + (size_t)d*NTC + r*128 + h*16;
    const float* ckh = ckG + d*C + h*16;
    const float* cvh = cvG + d*C + h*16;
    float s0 = 0.f, s1 = 0.f;
    #pragma unroll
    for (int i = 0; i < 16; i++) {
        float qv = __half2float(qp[i]);
        s0 += qv * (__half2float(k0[i]) + ckh[i]);
        s1 += qv * __half2float(k1[i]);
    }
    s0 *= 0.25f; s1 *= 0.25f;
    float mx = fmaxf(s0, s1);
    float e0 = expf(s0-mx), e1 = expf(s1-mx);
    float inv = 1.0f/(e0+e1);
    float a0 = e0*inv, a1 = e1*inv;
    __half* op = OG + (size_t)d*NTC + r*128 + h*16;
    #pragma unroll
    for (int i = 0; i < 16; i += 2)
        *(__half2*)(op + i) = __floats2half2_rn(
            a0*(__half2float(v0[i]) + cvh[i]) + a1*__half2float(v1[i]),
            a0*(__half2float(v0[i+1]) + cvh[i+1]) + a1*__half2float(v1[i+1]));
}

// ------------------------- host driver ------------------------------------
extern "C" void kernel_launch(void* const* d_in, const int* in_sizes, int n_in,
                              void* d_out, int out_size)
{
    const float* x0       = (const float*)d_in[0];
    const float* x1       = (const float*)d_in[1];
    const float* Wq       = (const float*)d_in[2];
    const float* bq       = (const float*)d_in[3];
    const float* Wkv      = (const float*)d_in[4];
    const float* bkv      = (const float*)d_in[5];
    const float* sr_w     = (const float*)d_in[6];
    const float* sr_b     = (const float*)d_in[7];
    const float* ln_g[2]  = {(const float*)d_in[8],  (const float*)d_in[10]};
    const float* ln_b[2]  = {(const float*)d_in[9],  (const float*)d_in[11]};
    const float* in_w[2]  = {(const float*)d_in[12], (const float*)d_in[16]};
    const float* in_b[2]  = {(const float*)d_in[13], (const float*)d_in[17]};
    const float* out_w[2] = {(const float*)d_in[14], (const float*)d_in[18]};
    const float* out_b[2] = {(const float*)d_in[15], (const float*)d_in[19]};
    const float* rj_w1    = (const float*)d_in[20];
    const float* rj_b1    = (const float*)d_in[21];
    const float* rj_w2    = (const float*)d_in[22];
    const float* rj_b2    = (const float*)d_in[23];
    const float* k_noise  = (const float*)d_in[24];
    const float* v_noise  = (const float*)d_in[25];
    const float* proj_w   = (const float*)d_in[26];
    const float* proj_b   = (const float*)d_in[27];

    __half *xh, *xim, *xah, *hh, *oh, *qh, *qkvh, *kp1h, *vp1h;
    __half *wqh, *rj1h, *rj2h, *inwh, *wfh, *wim, *Kh, *VtG;
    float *s, *cpart, *xi, *kv, *ck, *cv, *bc;
    cudaGetSymbolAddress((void**)&xh,    g_xh);
    cudaGetSymbolAddress((void**)&xim,   g_xim);
    cudaGetSymbolAddress((void**)&xah,   g_xah);
    cudaGetSymbolAddress((void**)&hh,    g_hh);
    cudaGetSymbolAddress((void**)&oh,    g_oh);
    cudaGetSymbolAddress((void**)&qh,    g_qh);
    cudaGetSymbolAddress((void**)&qkvh,  g_qkvh);
    cudaGetSymbolAddress((void**)&kp1h,  g_kp1h);
    cudaGetSymbolAddress((void**)&vp1h,  g_vp1h);
    cudaGetSymbolAddress((void**)&wqh,   g_wqh);
    cudaGetSymbolAddress((void**)&rj1h,  g_rj1h);
    cudaGetSymbolAddress((void**)&rj2h,  g_rj2h);
    cudaGetSymbolAddress((void**)&inwh,  g_inwh);
    cudaGetSymbolAddress((void**)&wfh,   g_wfh);
    cudaGetSymbolAddress((void**)&wim,   g_wim);
    cudaGetSymbolAddress((void**)&Kh,    g_Kh);
    cudaGetSymbolAddress((void**)&VtG,   g_VtG);
    cudaGetSymbolAddress((void**)&s,     g_s);
    cudaGetSymbolAddress((void**)&cpart, g_cpart);
    cudaGetSymbolAddress((void**)&xi,    g_xi);
    cudaGetSymbolAddress((void**)&kv,    g_kv);
    cudaGetSymbolAddress((void**)&ck,    g_ck);
    cudaGetSymbolAddress((void**)&cv,    g_cv);
    cudaGetSymbolAddress((void**)&bc,    g_bc);

    cudaFuncSetAttribute(attn_mma, cudaFuncAttributeMaxDynamicSharedMemorySize, ATTN2_SMEM);
    cudaFuncSetAttribute(mma_gemmB, cudaFuncAttributeMaxDynamicSharedMemorySize, MMA_SMEM_BYTES);

    // ---- weight prep (independent of data path) ----
    convh_kernel<<<(C*C/4+255)/256, 256>>>(Wq, wqh, C*C/4);
    convh_kernel<<<(2*C*C/4+255)/256, 256>>>(rj_w1, rj1h, 2*C*C/4);
    convh_kernel<<<(C*C/4+255)/256, 256>>>(rj_w2, rj2h, C*C/4);
    convh_kernel<<<(3*C*C/4+255)/256, 256>>>(in_w[0], inwh, 3*C*C/4);
    convh_kernel<<<(3*C*C/4+255)/256, 256>>>(in_w[1], inwh + 3*C*C, 3*C*C/4);
    wim_kernel<<<(C*KCONV)/256, 256>>>(sr_w, wim);
    wfuse_kernel<<<dim3(C,2), C>>>(proj_w, out_w[0], out_b[0], out_w[1], out_b[1],
                                   proj_b, wfh, bc);
    cknoise_kernel<<<2, 256>>>(in_w[0], in_w[1], k_noise, v_noise, ck, cv);

    Batch10 B;

    // ---- stage A (both images batched) ----
    convh2_kernel<<<dim3((NTC/4)/256, 2), 256>>>(x0, x1, xh);
    im2col_kernel<<<dim3((BM*KCONV/4)/256, 2), 256>>>(x0, x1, xim);
    for (int im = 0; im < 2; im++)
        B.e[im] = { xh + (size_t)im*NTC, nullptr, wqh, bq, nullptr,
                    qh + (size_t)im*NTC, C, C };
    mma_gemmB<<<dim3(NT/256,1,2), 512, MMA_SMEM_BYTES>>>(B, C, 0);
    conv_mma<<<dim3(16, 1, 16), 256>>>(xim, wim, cpart);
    redln_kernel<<<2*BM, 128>>>(cpart, sr_b, ln_g[0], ln_b[0], ln_g[1], ln_b[1], xi);
    gemm_kernel<<<dim3(BM/64, 4, 2), 256>>>(xi, Wkv, bkv, kv);
    kvprep_kernel<<<2*BB*HEADS*M*DH/256, 256>>>(kv, Kh, VtG);
    attn_mma<<<dim3(NTOK/64, HEADS, 2*BB), 256, ATTN2_SMEM>>>(qh, Kh, VtG, xah);

    // ---- stage B (both directions batched) ----
    // judger1: hh_d = gelu([xa_d | xa_{1-d}] @ rj1^T + b1)
    for (int d = 0; d < 2; d++)
        B.e[d] = { xah + (size_t)d*NTC, xah + (size_t)(1-d)*NTC, rj1h, rj_b1,
                   nullptr, hh + (size_t)d*NTC, 2*C, C };
    mma_gemmB<<<dim3(NT/256,1,2), 512, MMA_SMEM_BYTES>>>(B, 2*C, F_GELU);

    // judger2: s_d = hh_d @ rj2^T + b2
    for (int d = 0; d < 2; d++)
        B.e[d] = { hh + (size_t)d*NTC, nullptr, rj2h, rj_b2,
                   s + (size_t)d*NTC, nullptr, C, C };
    mma_gemmB<<<dim3(NT/256,1,2), 512, MMA_SMEM_BYTES>>>(B, C, 0);

    // fused rowsoftmax + a*s -> hh_d
    smax_amul_kernel<<<dim3(NT/8, 2), 256>>>(s, xah, hh);

    // proj batch (10 entries, all N=128, K=128)
    for (int d = 0; d < 2; d++){
        const __half* a  = xah + (size_t)d*NTC;
        const __half* bb = xah + (size_t)(1-d)*NTC;
        const __half* w  = inwh + (size_t)d*3*C*C;
        __half* qk = qkvh + (size_t)d*NT*3*C;
        B.e[d*5+0] = { a, nullptr, w,         in_b[d],       nullptr, qk,       C, 3*C };
        B.e[d*5+1] = { a, nullptr, w + C*C,   in_b[d] + C,   nullptr, qk + C,   C, 3*C };
        B.e[d*5+2] = { a, nullptr, w + 2*C*C, in_b[d] + 2*C, nullptr, qk + 2*C, C, 3*C };
        B.e[d*5+3] = { hh + (size_t)d*NTC, nullptr, w + C*C,   in_b[d] + C,
                       nullptr, kp1h + (size_t)d*NTC, C, C };
        B.e[d*5+4] = { bb, nullptr, w + 2*C*C, in_b[d] + 2*C,
                       nullptr, vp1h + (size_t)d*NTC, C, C };
    }
    mma_gemmB<<<dim3(NT/256,1,10), 512, MMA_SMEM_BYTES>>>(B, C, 0);

    combine_kernel<<<dim3((NT*XH)/256, 2), 256>>>(qkvh, kp1h, vp1h, ck, cv, oh);

    // final: dst_d = [oh_d | xa_d] @ wfh_d^T + bc_d
    for (int d = 0; d < 2; d++)
        B.e[d] = { oh + (size_t)d*NTC, xah + (size_t)d*NTC, wfh + (size_t)d*2*C*C,
                   bc + d*C, (float*)d_out + (size_t)d*NTC, nullptr, 2*C, C };
    mma_gemmB<<<dim3(NT/256,1,2), 512, MMA_SMEM_BYTES>>>(B, 2*C, 0);
}